// round 11
// baseline (speedup 1.0000x reference)
#include <cuda_runtime.h>
#include <cuda_bf16.h>
#include <stdint.h>
#include <math.h>

#define BATCH 8
#define DIM   256
#define NSLOT 64
#define LTOK  4096

// ---------------- scratch ----------------
__device__ float g_templates[BATCH*NSLOT*DIM];
__device__ float g_attn[BATCH*LTOK*NSLOT];
__device__ float g_colsum_part[BATCH*64*NSLOT];
__device__ float g_colsum[BATCH*NSLOT];
__device__ float g_accpart[8*BATCH*NSLOT*DIM];
// bf16 split operands
__device__ __nv_bfloat16 g_xh[36799488];
__device__ __nv_bfloat16 g_xl[36799488];
__device__ __nv_bfloat16 g_cwh[27*32768];
__device__ __nv_bfloat16 g_cwl[27*32768];
__device__ __nv_bfloat16 g_kvh[256*512];
__device__ __nv_bfloat16 g_kvl[256*512];
__device__ __nv_bfloat16 g_toksh[32768*256];
__device__ __nv_bfloat16 g_toksl[32768*256];
__device__ __nv_bfloat16 g_kh[32768*256];
__device__ __nv_bfloat16 g_kl[32768*256];
__device__ __nv_bfloat16 g_vh[32768*256];
__device__ __nv_bfloat16 g_vl[32768*256];
__device__ __nv_bfloat16 g_qh[512*256];
__device__ __nv_bfloat16 g_ql[512*256];
__device__ __nv_bfloat16 g_ath[BATCH*LTOK*NSLOT];
__device__ __nv_bfloat16 g_atl[BATCH*LTOK*NSLOT];
__device__ __nv_bfloat16 g_tlnh[512*256];   // LN_t(templates) split
__device__ __nv_bfloat16 g_tlnl[512*256];
__device__ __nv_bfloat16 g_tbh[512*256];    // LN_m(templates) split
__device__ __nv_bfloat16 g_tbl[512*256];
__device__ __nv_bfloat16 g_hidh[512*512];   // hidden split
__device__ __nv_bfloat16 g_hidl[512*512];
__device__ __nv_bfloat16 g_wqh[65536],  g_wql[65536];
__device__ __nv_bfloat16 g_w1h[131072], g_w1l[131072];
__device__ __nv_bfloat16 g_w2h[131072], g_w2l[131072];

__device__ __forceinline__ float gelu_exact(float v) {
    return 0.5f * v * (1.0f + erff(v * 0.70710678118654752f));
}

// ========== mma.sync helpers ==========
__device__ __forceinline__ uint32_t smem_u32(const void* p) {
    uint32_t a;
    asm("{ .reg .u64 t; cvta.to.shared.u64 t, %1; cvt.u32.u64 %0, t; }" : "=r"(a) : "l"(p));
    return a;
}
__device__ __forceinline__ void ldsm_x4(uint32_t* r, uint32_t addr) {
    asm volatile("ldmatrix.sync.aligned.m8n8.x4.shared.b16 {%0,%1,%2,%3}, [%4];"
        : "=r"(r[0]), "=r"(r[1]), "=r"(r[2]), "=r"(r[3]) : "r"(addr));
}
__device__ __forceinline__ void ldsm_x4_t(uint32_t* r, uint32_t addr) {
    asm volatile("ldmatrix.sync.aligned.m8n8.x4.trans.shared.b16 {%0,%1,%2,%3}, [%4];"
        : "=r"(r[0]), "=r"(r[1]), "=r"(r[2]), "=r"(r[3]) : "r"(addr));
}
__device__ __forceinline__ void mma_bf16(float* d, const uint32_t* a, const uint32_t* b) {
    asm volatile("mma.sync.aligned.m16n8k16.row.col.f32.bf16.bf16.f32 "
        "{%0,%1,%2,%3}, {%4,%5,%6,%7}, {%8,%9}, {%0,%1,%2,%3};"
        : "+f"(d[0]), "+f"(d[1]), "+f"(d[2]), "+f"(d[3])
        : "r"(a[0]), "r"(a[1]), "r"(a[2]), "r"(a[3]), "r"(b[0]), "r"(b[1]));
}
__device__ __forceinline__ void bsplit(float v0, float v1, __nv_bfloat162& hh, __nv_bfloat162& ll) {
    __nv_bfloat16 h0 = __float2bfloat16(v0), h1 = __float2bfloat16(v1);
    hh.x = h0; hh.y = h1;
    ll.x = __float2bfloat16(v0 - __bfloat162float(h0));
    ll.y = __float2bfloat16(v1 - __bfloat162float(h1));
}

// 128x256 += A(128x128, pitch 272B) x B(128k x 256n, pitch 528B); 3-term bf16 split.
__device__ __forceinline__ void mma_chunk(
    uint32_t sAh, uint32_t sAl, uint32_t sBh, uint32_t sBl,
    float d[2][8][4], int wm, int wn, int lane)
{
    uint32_t aoff0 = (uint32_t)((wm*32 + (lane & 15))*272 + (lane >> 4)*16);
    uint32_t boff0 = (uint32_t)((lane & 15)*528 + (wn*64 + (lane >> 4)*8)*2);
    #pragma unroll
    for (int kk = 0; kk < 8; kk++) {
        uint32_t ah[8], al[8], bb[16];
        uint32_t ao = aoff0 + kk*32;
        ldsm_x4(ah,     sAh + ao);
        ldsm_x4(ah + 4, sAh + ao + 4352);
        ldsm_x4(al,     sAl + ao);
        ldsm_x4(al + 4, sAl + ao + 4352);
        uint32_t bo = boff0 + kk*8448;
        #pragma unroll
        for (int jj = 0; jj < 4; jj++) ldsm_x4_t(bb + jj*4, sBh + bo + jj*32);
        #pragma unroll
        for (int mi = 0; mi < 2; mi++) {
            #pragma unroll
            for (int j = 0; j < 8; j++) {
                const uint32_t* bf = bb + (j >> 1)*4 + (j & 1)*2;
                mma_bf16(d[mi][j], mi ? ah + 4 : ah, bf);
                mma_bf16(d[mi][j], mi ? al + 4 : al, bf);
            }
        }
        #pragma unroll
        for (int jj = 0; jj < 4; jj++) ldsm_x4_t(bb + jj*4, sBl + bo + jj*32);
        #pragma unroll
        for (int mi = 0; mi < 2; mi++) {
            #pragma unroll
            for (int j = 0; j < 8; j++) {
                const uint32_t* bf = bb + (j >> 1)*4 + (j & 1)*2;
                mma_bf16(d[mi][j], mi ? ah + 4 : ah, bf);
            }
        }
    }
}

// ---------------- prep kernels ----------------
__global__ void templates_init_kernel(const float* __restrict__ tinit) {
    int b = blockIdx.x, t = threadIdx.x;
    for (int n = 0; n < NSLOT; n++)
        g_templates[(b*NSLOT + n)*DIM + t] = tinit[n*DIM + t];
}

__global__ __launch_bounds__(256) void xsplit_kernel(const float* __restrict__ x) {
    __shared__ float st[128*33];
    int bid = blockIdx.x; int b = bid / 1089; int rem = bid % 1089; int d = rem / 33, h = rem % 33;
    int t = threadIdx.x, warp = t >> 5, lane = t & 31;
    const float* xb = x + ((((size_t)b*128)*33 + d)*33 + h)*33;
    for (int c = warp; c < 128; c += 8) {
        const float* src = xb + (size_t)c*35937;
        st[c*33 + lane] = src[lane];
        if (lane == 0) st[c*33 + 32] = src[32];
    }
    __syncthreads();
    size_t ob = ((((size_t)b*33 + d)*33 + h)*33)*128;
    for (int i = t; i < 33*128; i += 256) {
        int w = i >> 7, c = i & 127;
        float v = st[c*33 + w];
        __nv_bfloat16 hi = __float2bfloat16(v);
        g_xh[ob + (size_t)w*128 + c] = hi;
        g_xl[ob + (size_t)w*128 + c] = __float2bfloat16(v - __bfloat162float(hi));
    }
}

__global__ void cwsplit_kernel(const float* __restrict__ cw) {
    int idx = blockIdx.x*256 + threadIdx.x;
    int tap = idx >> 15, r = idx & 32767;
    int k = r >> 8, n = r & 255;
    float v = cw[(size_t)n*3456 + k*27 + tap];
    __nv_bfloat16 hi = __float2bfloat16(v);
    g_cwh[idx] = hi;
    g_cwl[idx] = __float2bfloat16(v - __bfloat162float(hi));
}

__global__ void kvsplit_kernel(const float* __restrict__ Wk, const float* __restrict__ Wv) {
    int idx = blockIdx.x*256 + threadIdx.x;
    int k = idx >> 9, c512 = idx & 511;
    int mat = c512 >> 8, col = c512 & 255;
    const float* W = mat ? Wv : Wk;
    float v = W[(size_t)k*256 + col];
    __nv_bfloat16 hi = __float2bfloat16(v);
    g_kvh[idx] = hi;
    g_kvl[idx] = __float2bfloat16(v - __bfloat162float(hi));
}

// FIXED: selector-based split so device globals are referenced from DEVICE code.
// (Passing __device__ array symbols as kernel args from host passes the host
//  shadow address; on GB300 ATS that silently writes host memory and leaves
//  the real arrays zero.)
__global__ void wsplit_kernel(const float* __restrict__ W, int which) {
    int idx = blockIdx.x*256 + threadIdx.x;
    float v = W[idx];
    __nv_bfloat16 hi = __float2bfloat16(v);
    __nv_bfloat16 lo = __float2bfloat16(v - __bfloat162float(hi));
    if (which == 0)      { g_wqh[idx] = hi; g_wql[idx] = lo; }
    else if (which == 1) { g_w1h[idx] = hi; g_w1l[idx] = lo; }
    else                 { g_w2h[idx] = hi; g_w2l[idx] = lo; }
}

// LN_t of templates -> bf16 split (primes iteration 0)
__global__ __launch_bounds__(256) void ln_t_split_kernel(
    const float* __restrict__ g, const float* __restrict__ bb) {
    int b = blockIdx.x, t = threadIdx.x;
    int r = t >> 2, part = t & 3;
    const float* row = g_templates + ((size_t)(b*NSLOT) + r)*DIM + part*64;
    float s = 0.f, sq = 0.f;
    #pragma unroll
    for (int i = 0; i < 64; i += 4) {
        float4 v = *(const float4*)(row + i);
        s += v.x+v.y+v.z+v.w;
        sq += v.x*v.x + v.y*v.y + v.z*v.z + v.w*v.w;
    }
    s  += __shfl_xor_sync(0xffffffffu, s, 1);  s  += __shfl_xor_sync(0xffffffffu, s, 2);
    sq += __shfl_xor_sync(0xffffffffu, sq, 1); sq += __shfl_xor_sync(0xffffffffu, sq, 2);
    float mu = s * (1.0f/256.0f);
    float rs = rsqrtf(sq * (1.0f/256.0f) - mu*mu + 1e-5f);
    size_t o = ((size_t)(b*NSLOT) + r)*DIM + part*64;
    #pragma unroll
    for (int i = 0; i < 64; i += 2) {
        int ch = part*64 + i;
        float v0 = (row[i]   - mu)*rs*g[ch]   + bb[ch];
        float v1 = (row[i+1] - mu)*rs*g[ch+1] + bb[ch+1];
        __nv_bfloat162 hh, ll;
        bsplit(v0, v1, hh, ll);
        *(__nv_bfloat162*)(g_tlnh + o + i) = hh;
        *(__nv_bfloat162*)(g_tlnl + o + i) = ll;
    }
}

// ---------------- conv (implicit GEMM via mma.sync) + bias + ReLU + LN ----------------
#define CMM_SMEM 204800
__global__ __launch_bounds__(512, 1) void conv_mma_kernel(
    const float* __restrict__ convb, const float* __restrict__ lng, const float* __restrict__ lnb)
{
    extern __shared__ char sm[];
    uint32_t sb = smem_u32(sm);
    const uint32_t oAh = 0, oAl = 34816, oBh = 69632, oBl = 137216;
    int t = threadIdx.x, lane = t & 31, wid = t >> 5;
    int wm = wid >> 2, wn = wid & 3;
    int bx = blockIdx.x; int b = bx >> 5, xd = (bx >> 1) & 15, half = bx & 1;

    float d[2][8][4];
    #pragma unroll
    for (int i = 0; i < 2; i++)
        #pragma unroll
        for (int j = 0; j < 8; j++)
            #pragma unroll
            for (int c = 0; c < 4; c++) d[i][j][c] = 0.f;

    int m = t >> 2, q = t & 3;
    int xhl = m >> 4, xw = m & 15;

    for (int tap = 0; tap < 27; tap++) {
        int kd = tap/9, r9 = tap%9, kh = r9/3, kw = r9%3;
        {
            size_t xi = ((((size_t)(b*33) + 2*xd + kd)*33 + 2*(half*8 + xhl) + kh)*33 + 2*xw + kw)*128 + q*32;
            const uint4* shi = (const uint4*)(g_xh + xi);
            const uint4* slo = (const uint4*)(g_xl + xi);
            char* dh = sm + oAh + m*272 + q*64;
            char* dl = sm + oAl + m*272 + q*64;
            #pragma unroll
            for (int j = 0; j < 4; j++) {
                *(uint4*)(dh + j*16) = shi[j];
                *(uint4*)(dl + j*16) = slo[j];
            }
        }
        {
            const uint4* s1 = (const uint4*)(g_cwh + tap*32768);
            const uint4* s2 = (const uint4*)(g_cwl + tap*32768);
            #pragma unroll
            for (int it = 0; it < 8; it++) {
                int i = t + it*512;
                int row = i >> 5, seg = i & 31;
                *(uint4*)(sm + oBh + row*528 + seg*16) = s1[i];
                *(uint4*)(sm + oBl + row*528 + seg*16) = s2[i];
            }
        }
        __syncthreads();
        mma_chunk(sb + oAh, sb + oAl, sb + oBh, sb + oBl, d, wm, wn, lane);
        __syncthreads();
    }

    float* stg = (float*)sm;
    {
        int r0 = wm*32 + (lane >> 2);
        int c0 = wn*64 + (lane & 3)*2;
        #pragma unroll
        for (int mi = 0; mi < 2; mi++)
            #pragma unroll
            for (int j = 0; j < 8; j++) {
                int rr = r0 + mi*16, cc = c0 + j*8;
                *(float2*)(stg + (size_t)rr*264 + cc)     = make_float2(d[mi][j][0], d[mi][j][1]);
                *(float2*)(stg + (size_t)(rr+8)*264 + cc) = make_float2(d[mi][j][2], d[mi][j][3]);
            }
    }
    __syncthreads();

    {
        int tok = t >> 2, q2 = t & 3;
        const float* src = stg + (size_t)tok*264 + q2*64;
        float z[64];
        float s = 0.f, sq = 0.f;
        #pragma unroll
        for (int i = 0; i < 64; i++) {
            float v = fmaxf(src[i] + convb[q2*64 + i], 0.f);
            z[i] = v; s += v; sq += v*v;
        }
        s  += __shfl_xor_sync(0xffffffffu, s, 1);  s  += __shfl_xor_sync(0xffffffffu, s, 2);
        sq += __shfl_xor_sync(0xffffffffu, sq, 1); sq += __shfl_xor_sync(0xffffffffu, sq, 2);
        float mu = s * (1.f/256.f);
        float rs = rsqrtf(sq * (1.f/256.f) - mu*mu + 1e-5f);
        int l = (xd*16 + half*8 + (tok >> 4))*16 + (tok & 15);
        size_t tg = ((size_t)b*4096 + l)*256 + q2*64;
        #pragma unroll
        for (int i = 0; i < 64; i += 2) {
            int ch = q2*64 + i;
            float v0 = (z[i]   - mu)*rs*lng[ch]   + lnb[ch];
            float v1 = (z[i+1] - mu)*rs*lng[ch+1] + lnb[ch+1];
            __nv_bfloat162 hh, ll;
            bsplit(v0, v1, hh, ll);
            *(__nv_bfloat162*)(g_toksh + tg + i) = hh;
            *(__nv_bfloat162*)(g_toksl + tg + i) = ll;
        }
    }
}

// ---------------- K/V projection via mma.sync -> bf16 split outputs ----------------
__global__ __launch_bounds__(512, 1) void kv_mma_kernel() {
    extern __shared__ char sm[];
    uint32_t sb = smem_u32(sm);
    const uint32_t oAh = 0, oAl = 34816, oBh = 69632, oBl = 137216;
    int t = threadIdx.x, lane = t & 31, wid = t >> 5;
    int wm = wid >> 2, wn = wid & 3;
    int nhalf = blockIdx.x & 1, chunk = blockIdx.x >> 1;

    float d[2][8][4];
    #pragma unroll
    for (int i = 0; i < 2; i++)
        #pragma unroll
        for (int j = 0; j < 8; j++)
            #pragma unroll
            for (int c = 0; c < 4; c++) d[i][j][c] = 0.f;

    int m = t >> 2, q = t & 3;
    for (int kc = 0; kc < 2; kc++) {
        {
            size_t ti = ((size_t)(chunk*128 + m))*256 + kc*128 + q*32;
            const uint4* shi = (const uint4*)(g_toksh + ti);
            const uint4* slo = (const uint4*)(g_toksl + ti);
            char* dh = sm + oAh + m*272 + q*64;
            char* dl = sm + oAl + m*272 + q*64;
            #pragma unroll
            for (int j = 0; j < 4; j++) {
                *(uint4*)(dh + j*16) = shi[j];
                *(uint4*)(dl + j*16) = slo[j];
            }
        }
        {
            #pragma unroll
            for (int it = 0; it < 8; it++) {
                int i = t + it*512;
                int row = i >> 5, seg = i & 31;
                size_t off = (size_t)(kc*128 + row)*512 + nhalf*256 + seg*8;
                *(uint4*)(sm + oBh + row*528 + seg*16) = *(const uint4*)(g_kvh + off);
                *(uint4*)(sm + oBl + row*528 + seg*16) = *(const uint4*)(g_kvl + off);
            }
        }
        __syncthreads();
        mma_chunk(sb + oAh, sb + oAl, sb + oBh, sb + oBl, d, wm, wn, lane);
        __syncthreads();
    }

    __nv_bfloat16* dh = nhalf ? g_vh : g_kh;
    __nv_bfloat16* dl = nhalf ? g_vl : g_kl;
    int r0 = wm*32 + (lane >> 2);
    int c0 = wn*64 + (lane & 3)*2;
    #pragma unroll
    for (int mi = 0; mi < 2; mi++)
        #pragma unroll
        for (int j = 0; j < 8; j++) {
            int rr = r0 + mi*16, cc = c0 + j*8;
            size_t tok = (size_t)chunk*128 + rr;
            __nv_bfloat162 hh, ll;
            bsplit(d[mi][j][0], d[mi][j][1], hh, ll);
            *(__nv_bfloat162*)(dh + tok*256 + cc) = hh;
            *(__nv_bfloat162*)(dl + tok*256 + cc) = ll;
            bsplit(d[mi][j][2], d[mi][j][3], hh, ll);
            *(__nv_bfloat162*)(dh + (tok+8)*256 + cc) = hh;
            *(__nv_bfloat162*)(dl + (tok+8)*256 + cc) = ll;
        }
}

// ---------------- q = LN_t(templates) @ Wq * scale via mma. grid 4 ----------------
__global__ __launch_bounds__(512, 1) void gemm_q_mma_kernel() {
    extern __shared__ char sm[];
    uint32_t sb = smem_u32(sm);
    const uint32_t oAh = 0, oAl = 34816, oBh = 69632, oBl = 137216;
    int t = threadIdx.x, lane = t & 31, wid = t >> 5;
    int wm = wid >> 2, wn = wid & 3;
    int mb = blockIdx.x;

    float d[2][8][4];
    #pragma unroll
    for (int i = 0; i < 2; i++)
        #pragma unroll
        for (int j = 0; j < 8; j++)
            #pragma unroll
            for (int c = 0; c < 4; c++) d[i][j][c] = 0.f;

    int m = t >> 2, q = t & 3;
    for (int kc = 0; kc < 2; kc++) {
        {
            size_t ti = ((size_t)(mb*128 + m))*256 + kc*128 + q*32;
            const uint4* shi = (const uint4*)(g_tlnh + ti);
            const uint4* slo = (const uint4*)(g_tlnl + ti);
            char* dh = sm + oAh + m*272 + q*64;
            char* dl = sm + oAl + m*272 + q*64;
            #pragma unroll
            for (int j = 0; j < 4; j++) {
                *(uint4*)(dh + j*16) = shi[j];
                *(uint4*)(dl + j*16) = slo[j];
            }
        }
        {
            #pragma unroll
            for (int it = 0; it < 8; it++) {
                int i = t + it*512;
                int row = i >> 5, seg = i & 31;
                size_t off = (size_t)(kc*128 + row)*256 + seg*8;
                *(uint4*)(sm + oBh + row*528 + seg*16) = *(const uint4*)(g_wqh + off);
                *(uint4*)(sm + oBl + row*528 + seg*16) = *(const uint4*)(g_wql + off);
            }
        }
        __syncthreads();
        mma_chunk(sb + oAh, sb + oAl, sb + oBh, sb + oBl, d, wm, wn, lane);
        __syncthreads();
    }

    const float sc = 0.0625f;
    int r0 = wm*32 + (lane >> 2);
    int c0 = wn*64 + (lane & 3)*2;
    #pragma unroll
    for (int mi = 0; mi < 2; mi++)
        #pragma unroll
        for (int j = 0; j < 8; j++) {
            int rr = r0 + mi*16, cc = c0 + j*8;
            size_t row = (size_t)mb*128 + rr;
            __nv_bfloat162 hh, ll;
            bsplit(d[mi][j][0]*sc, d[mi][j][1]*sc, hh, ll);
            *(__nv_bfloat162*)(g_qh + row*256 + cc) = hh;
            *(__nv_bfloat162*)(g_ql + row*256 + cc) = ll;
            bsplit(d[mi][j][2]*sc, d[mi][j][3]*sc, hh, ll);
            *(__nv_bfloat162*)(g_qh + (row+8)*256 + cc) = hh;
            *(__nv_bfloat162*)(g_ql + (row+8)*256 + cc) = ll;
        }
}

// ---------------- hidden = GELU(LN_m @ W1 + b1) via mma. grid (2, 4) ----------------
__global__ __launch_bounds__(512, 1) void gemm_h_mma_kernel(const float* __restrict__ b1) {
    extern __shared__ char sm[];
    uint32_t sb = smem_u32(sm);
    const uint32_t oAh = 0, oAl = 34816, oBh = 69632, oBl = 137216;
    int t = threadIdx.x, lane = t & 31, wid = t >> 5;
    int wm = wid >> 2, wn = wid & 3;
    int nc = blockIdx.x, mb = blockIdx.y;

    float d[2][8][4];
    #pragma unroll
    for (int i = 0; i < 2; i++)
        #pragma unroll
        for (int j = 0; j < 8; j++)
            #pragma unroll
            for (int c = 0; c < 4; c++) d[i][j][c] = 0.f;

    int m = t >> 2, q = t & 3;
    for (int kc = 0; kc < 2; kc++) {
        {
            size_t ti = ((size_t)(mb*128 + m))*256 + kc*128 + q*32;
            const uint4* shi = (const uint4*)(g_tbh + ti);
            const uint4* slo = (const uint4*)(g_tbl + ti);
            char* dh = sm + oAh + m*272 + q*64;
            char* dl = sm + oAl + m*272 + q*64;
            #pragma unroll
            for (int j = 0; j < 4; j++) {
                *(uint4*)(dh + j*16) = shi[j];
                *(uint4*)(dl + j*16) = slo[j];
            }
        }
        {
            #pragma unroll
            for (int it = 0; it < 8; it++) {
                int i = t + it*512;
                int row = i >> 5, seg = i & 31;
                size_t off = (size_t)(kc*128 + row)*512 + nc*256 + seg*8;
                *(uint4*)(sm + oBh + row*528 + seg*16) = *(const uint4*)(g_w1h + off);
                *(uint4*)(sm + oBl + row*528 + seg*16) = *(const uint4*)(g_w1l + off);
            }
        }
        __syncthreads();
        mma_chunk(sb + oAh, sb + oAl, sb + oBh, sb + oBl, d, wm, wn, lane);
        __syncthreads();
    }

    int r0 = wm*32 + (lane >> 2);
    int c0 = wn*64 + (lane & 3)*2;
    #pragma unroll
    for (int mi = 0; mi < 2; mi++)
        #pragma unroll
        for (int j = 0; j < 8; j++) {
            int rr = r0 + mi*16, cc = c0 + j*8;
            size_t row = (size_t)mb*128 + rr;
            int ch = nc*256 + cc;
            float v0 = gelu_exact(d[mi][j][0] + b1[ch]);
            float v1 = gelu_exact(d[mi][j][1] + b1[ch+1]);
            float v2 = gelu_exact(d[mi][j][2] + b1[ch]);
            float v3 = gelu_exact(d[mi][j][3] + b1[ch+1]);
            __nv_bfloat162 hh, ll;
            bsplit(v0, v1, hh, ll);
            *(__nv_bfloat162*)(g_hidh + row*512 + ch) = hh;
            *(__nv_bfloat162*)(g_hidl + row*512 + ch) = ll;
            bsplit(v2, v3, hh, ll);
            *(__nv_bfloat162*)(g_hidh + (row+8)*512 + ch) = hh;
            *(__nv_bfloat162*)(g_hidl + (row+8)*512 + ch) = ll;
        }
}

// ---------------- templates += hidden @ W2 + b2, then LN_t split. grid 4 ----------------
__global__ __launch_bounds__(512, 1) void gemm_o_mma_kernel(
    const float* __restrict__ b2, const float* __restrict__ lng, const float* __restrict__ lnb) {
    extern __shared__ char sm[];
    uint32_t sb = smem_u32(sm);
    const uint32_t oAh = 0, oAl = 34816, oBh = 69632, oBl = 137216;
    int t = threadIdx.x, lane = t & 31, wid = t >> 5;
    int wm = wid >> 2, wn = wid & 3;
    int mb = blockIdx.x;

    float d[2][8][4];
    #pragma unroll
    for (int i = 0; i < 2; i++)
        #pragma unroll
        for (int j = 0; j < 8; j++)
            #pragma unroll
            for (int c = 0; c < 4; c++) d[i][j][c] = 0.f;

    int m = t >> 2, q = t & 3;
    for (int kc = 0; kc < 4; kc++) {
        {
            size_t ti = ((size_t)(mb*128 + m))*512 + kc*128 + q*32;
            const uint4* shi = (const uint4*)(g_hidh + ti);
            const uint4* slo = (const uint4*)(g_hidl + ti);
            char* dh = sm + oAh + m*272 + q*64;
            char* dl = sm + oAl + m*272 + q*64;
            #pragma unroll
            for (int j = 0; j < 4; j++) {
                *(uint4*)(dh + j*16) = shi[j];
                *(uint4*)(dl + j*16) = slo[j];
            }
        }
        {
            #pragma unroll
            for (int it = 0; it < 8; it++) {
                int i = t + it*512;
                int row = i >> 5, seg = i & 31;
                size_t off = (size_t)(kc*128 + row)*256 + seg*8;
                *(uint4*)(sm + oBh + row*528 + seg*16) = *(const uint4*)(g_w2h + off);
                *(uint4*)(sm + oBl + row*528 + seg*16) = *(const uint4*)(g_w2l + off);
            }
        }
        __syncthreads();
        mma_chunk(sb + oAh, sb + oAl, sb + oBh, sb + oBl, d, wm, wn, lane);
        __syncthreads();
    }

    float* stg = (float*)sm;
    {
        int r0 = wm*32 + (lane >> 2);
        int c0 = wn*64 + (lane & 3)*2;
        #pragma unroll
        for (int mi = 0; mi < 2; mi++)
            #pragma unroll
            for (int j = 0; j < 8; j++) {
                int rr = r0 + mi*16, cc = c0 + j*8;
                *(float2*)(stg + (size_t)rr*264 + cc)     = make_float2(d[mi][j][0], d[mi][j][1]);
                *(float2*)(stg + (size_t)(rr+8)*264 + cc) = make_float2(d[mi][j][2], d[mi][j][3]);
            }
    }
    __syncthreads();

    {
        int rr = t >> 2, q2 = t & 3;
        size_t row = (size_t)mb*128 + rr;
        const float* src = stg + (size_t)rr*264 + q2*64;
        float* trow = g_templates + row*256 + q2*64;
        float z[64];
        float s = 0.f, sq = 0.f;
        #pragma unroll
        for (int i = 0; i < 64; i++) {
            float v = trow[i] + src[i] + b2[q2*64 + i];
            z[i] = v; s += v; sq += v*v;
        }
        s  += __shfl_xor_sync(0xffffffffu, s, 1);  s  += __shfl_xor_sync(0xffffffffu, s, 2);
        sq += __shfl_xor_sync(0xffffffffu, sq, 1); sq += __shfl_xor_sync(0xffffffffu, sq, 2);
        float mu = s * (1.f/256.f);
        float rs = rsqrtf(sq * (1.f/256.f) - mu*mu + 1e-5f);
        size_t o = row*256 + q2*64;
        #pragma unroll
        for (int i = 0; i < 64; i += 2) {
            int ch = q2*64 + i;
            trow[i] = z[i]; trow[i+1] = z[i+1];
            float v0 = (z[i]   - mu)*rs*lng[ch]   + lnb[ch];
            float v1 = (z[i+1] - mu)*rs*lng[ch+1] + lnb[ch+1];
            __nv_bfloat162 hh, ll;
            bsplit(v0, v1, hh, ll);
            *(__nv_bfloat162*)(g_tlnh + o + i) = hh;
            *(__nv_bfloat162*)(g_tlnl + o + i) = ll;
        }
    }
}

// ---------------- attn logits via mma + softmax + colsum partials ----------------
#define ATT_SMEM 104448
__global__ __launch_bounds__(256) void attn_mma_kernel() {
    extern __shared__ char sm[];
    uint32_t sb = smem_u32(sm);
    const uint32_t oAh = 0, oAl = 34816, oQh = 69632, oQl = 87040;
    int t = threadIdx.x, lane = t & 31, wid = t >> 5;
    int wm = wid >> 1, wn = wid & 1;
    int lb = blockIdx.x, b = blockIdx.y;

    float d[2][4][4];
    #pragma unroll
    for (int i = 0; i < 2; i++)
        #pragma unroll
        for (int j = 0; j < 4; j++)
            #pragma unroll
            for (int c = 0; c < 4; c++) d[i][j][c] = 0.f;

    for (int kc = 0; kc < 2; kc++) {
        {
            int row = t >> 1, half = t & 1;
            size_t ti = ((size_t)(b*4096) + lb*128 + row)*256 + kc*128 + half*64;
            const uint4* shi = (const uint4*)(g_kh + ti);
            const uint4* slo = (const uint4*)(g_kl + ti);
            char* dh = sm + oAh + row*272 + half*128;
            char* dl = sm + oAl + row*272 + half*128;
            #pragma unroll
            for (int j = 0; j < 8; j++) {
                *(uint4*)(dh + j*16) = shi[j];
                *(uint4*)(dl + j*16) = slo[j];
            }
        }
        {
            int row = t >> 2, q4 = t & 3;
            size_t ti = ((size_t)(b*NSLOT) + row)*256 + kc*128 + q4*32;
            const uint4* shi = (const uint4*)(g_qh + ti);
            const uint4* slo = (const uint4*)(g_ql + ti);
            char* dh = sm + oQh + row*272 + q4*64;
            char* dl = sm + oQl + row*272 + q4*64;
            #pragma unroll
            for (int j = 0; j < 4; j++) {
                *(uint4*)(dh + j*16) = shi[j];
                *(uint4*)(dl + j*16) = slo[j];
            }
        }
        __syncthreads();
        uint32_t aoff0 = (uint32_t)((wm*32 + (lane & 15))*272 + (lane >> 4)*16);
        uint32_t qoff0 = (uint32_t)(((lane >> 4)*8 + (lane & 7) + wn*32)*272 + ((lane >> 3) & 1)*16);
        #pragma unroll
        for (int kk = 0; kk < 8; kk++) {
            uint32_t ah[8], al[8], qh8[8], ql8[8];
            uint32_t ao = aoff0 + kk*32;
            ldsm_x4(ah,     sb + oAh + ao);
            ldsm_x4(ah + 4, sb + oAh + ao + 16*272);
            ldsm_x4(al,     sb + oAl + ao);
            ldsm_x4(al + 4, sb + oAl + ao + 16*272);
            uint32_t qo = qoff0 + kk*32;
            ldsm_x4(qh8,     sb + oQh + qo);
            ldsm_x4(qh8 + 4, sb + oQh + qo + 16*272);
            ldsm_x4(ql8,     sb + oQl + qo);
            ldsm_x4(ql8 + 4, sb + oQl + qo + 16*272);
            #pragma unroll
            for (int mi = 0; mi < 2; mi++) {
                #pragma unroll
                for (int j = 0; j < 4; j++) {
                    const uint32_t* bh = qh8 + (j >> 1)*4 + (j & 1)*2;
                    const uint32_t* bl = ql8 + (j >> 1)*4 + (j & 1)*2;
                    const uint32_t* am = mi ? ah + 4 : ah;
                    const uint32_t* aml = mi ? al + 4 : al;
                    mma_bf16(d[mi][j], am, bh);
                    mma_bf16(d[mi][j], am, bl);
                    mma_bf16(d[mi][j], aml, bh);
                }
            }
        }
        __syncthreads();
    }

    float* stg = (float*)sm;
    {
        int r0 = wm*32 + (lane >> 2);
        int c0 = wn*32 + (lane & 3)*2;
        #pragma unroll
        for (int mi = 0; mi < 2; mi++)
            #pragma unroll
            for (int j = 0; j < 4; j++) {
                int rr = r0 + mi*16, cc = c0 + j*8;
                *(float2*)(stg + rr*68 + cc)     = make_float2(d[mi][j][0], d[mi][j][1]);
                *(float2*)(stg + (rr+8)*68 + cc) = make_float2(d[mi][j][2], d[mi][j][3]);
            }
    }
    __syncthreads();

    {
        int row = t >> 1, half = t & 1;
        float* sr = stg + row*68 + half*32;
        float a[32];
        float mx = -3.4e38f;
        #pragma unroll
        for (int i = 0; i < 32; i++) { a[i] = sr[i]; mx = fmaxf(mx, a[i]); }
        mx = fmaxf(mx, __shfl_xor_sync(0xffffffffu, mx, 1));
        float s = 0.f;
        #pragma unroll
        for (int i = 0; i < 32; i++) { a[i] = expf(a[i] - mx); s += a[i]; }
        s += __shfl_xor_sync(0xffffffffu, s, 1);
        float inv = 1.0f / s;
        size_t gi = ((size_t)(b*4096) + lb*128 + row)*64 + half*32;
        #pragma unroll
        for (int i = 0; i < 32; i++) { a[i] = a[i]*inv + 1e-8f; sr[i] = a[i]; }
        #pragma unroll
        for (int i = 0; i < 32; i += 4)
            *(float4*)(g_attn + gi + i) = make_float4(a[i], a[i+1], a[i+2], a[i+3]);
        #pragma unroll
        for (int i = 0; i < 32; i += 2) {
            __nv_bfloat162 hh, ll;
            bsplit(a[i], a[i+1], hh, ll);
            *(__nv_bfloat162*)(g_ath + gi + i) = hh;
            *(__nv_bfloat162*)(g_atl + gi + i) = ll;
        }
    }
    __syncthreads();
    if (t < 64) {
        float s = 0.f;
        for (int r = 0; r < 128; r++) s += stg[r*68 + t];
        g_colsum_part[((size_t)b*64 + lb)*NSLOT + t] = s;
    }
}

// ---------------- attn^T @ v via mma. grid (2, 8, 8) ----------------
#define GC_SMEM 106496
__global__ __launch_bounds__(256) void gemm_c_mma_kernel() {
    extern __shared__ char sm[];
    uint32_t sb = smem_u32(sm);
    const uint32_t oAth = 0, oAtl = 18432, oVh = 36864, oVl = 71680;
    int t = threadIdx.x, lane = t & 31, wid = t >> 5;
    int wm = wid & 1, wn = wid >> 1;
    int dh = blockIdx.x, ps = blockIdx.y, b = blockIdx.z;

    float d[2][4][4];
    #pragma unroll
    for (int i = 0; i < 2; i++)
        #pragma unroll
        for (int j = 0; j < 4; j++)
            #pragma unroll
            for (int c = 0; c < 4; c++) d[i][j][c] = 0.f;

    for (int lc = 0; lc < 4; lc++) {
        int l0 = ps*512 + lc*128;
        {
            int row = t >> 1, half = t & 1;
            size_t ti = ((size_t)(b*4096) + l0 + row)*64 + half*32;
            const uint4* shi = (const uint4*)(g_ath + ti);
            const uint4* slo = (const uint4*)(g_atl + ti);
            char* dst_h = sm + oAth + row*144 + half*64;
            char* dst_l = sm + oAtl + row*144 + half*64;
            #pragma unroll
            for (int j = 0; j < 4; j++) {
                *(uint4*)(dst_h + j*16) = shi[j];
                *(uint4*)(dst_l + j*16) = slo[j];
            }
        }
        {
            int row = t >> 1, half = t & 1;
            size_t ti = ((size_t)(b*4096) + l0 + row)*256 + dh*128 + half*64;
            const uint4* shi = (const uint4*)(g_vh + ti);
            const uint4* slo = (const uint4*)(g_vl + ti);
            char* dst_h = sm + oVh + row*272 + half*128;
            char* dst_l = sm + oVl + row*272 + half*128;
            #pragma unroll
            for (int j = 0; j < 8; j++) {
                *(uint4*)(dst_h + j*16) = shi[j];
                *(uint4*)(dst_l + j*16) = slo[j];
            }
        }
        __syncthreads();
        uint32_t aoff0 = (uint32_t)((((lane >> 4)*8 + (lane & 7)))*144 + ((lane >> 3) & 1)*16 + wm*64);
        uint32_t boff0 = (uint32_t)((lane & 15)*272 + (wn*32 + (lane >> 4)*8)*2);
        #pragma unroll
        for (int kk = 0; kk < 8; kk++) {
            uint32_t ah[8], al[8], bh8[8], bl8[8];
            uint32_t ao = aoff0 + kk*16*144;
            ldsm_x4_t(ah,     sb + oAth + ao);
            ldsm_x4_t(ah + 4, sb + oAth + ao + 32);
            ldsm_x4_t(al,     sb + oAtl + ao);
            ldsm_x4_t(al + 4, sb + oAtl + ao + 32);
            uint32_t bo = boff0 + kk*16*272;
            ldsm_x4_t(bh8,     sb + oVh + bo);
            ldsm_x4_t(bh8 + 4, sb + oVh + bo + 32);
            ldsm_x4_t(bl8,     sb + oVl + bo);
            ldsm_x4_t(bl8 + 4, sb + oVl + bo + 32);
            #pragma unroll
            for (int mi = 0; mi < 2; mi++) {
                #pragma unroll
                for (int j = 0; j < 4; j++) {
                    const uint32_t* bfh = bh8 + (j >> 1)*4 + (j & 1)*2;
                    const uint32_t* bfl = bl8 + (j >> 1)*4 + (j & 1)*2;
                    const uint32_t* am = mi ? ah + 4 : ah;
                    const uint32_t* aml = mi ? al + 4 : al;
                    mma_bf16(d[mi][j], am, bfh);
                    mma_bf16(d[mi][j], am, bfl);
                    mma_bf16(d[mi][j], aml, bfh);
                }
            }
        }
        __syncthreads();
    }

    int r0 = wm*32 + (lane >> 2);
    int c0 = dh*128 + wn*32 + (lane & 3)*2;
    float* C = g_accpart + ((size_t)((ps*BATCH + b)*NSLOT))*DIM;
    #pragma unroll
    for (int mi = 0; mi < 2; mi++)
        #pragma unroll
        for (int j = 0; j < 4; j++) {
            int slot = r0 + mi*16, cc = c0 + j*8;
            *(float2*)(C + (size_t)slot*DIM + cc)     = make_float2(d[mi][j][0], d[mi][j][1]);
            *(float2*)(C + (size_t)(slot+8)*DIM + cc) = make_float2(d[mi][j][2], d[mi][j][3]);
        }
}

// ---------------- fused colsum + template update + LN_m split. grid 8 ----------------
#define FIN_SMEM_FLOATS (16384 + 256 + 64)
__global__ __launch_bounds__(256) void finalize_kernel(const float* __restrict__ g,
                                                       const float* __restrict__ bb) {
    extern __shared__ float smf[];
    float* tv   = smf;
    float* csp  = smf + 16384;
    float* csin = smf + 16640;
    int b = blockIdx.x, t = threadIdx.x;
    {
        int part4 = t >> 6, n = t & 63;
        float s = 0.f;
        #pragma unroll
        for (int lb = 0; lb < 8; lb++)
            s += g_colsum_part[((size_t)b*64 + part4*8 + lb)*NSLOT + n];
        csp[part4*64 + n] = s;
    }
    __syncthreads();
    if (t < 64) {
        float tot = csp[t] + csp[64+t] + csp[128+t] + csp[192+t];
        g_colsum[b*NSLOT + t] = tot;
        csin[t] = 1.0f / tot;
    }
    __syncthreads();
    for (int n = 0; n < NSLOT; n++) {
        float s = 0.f;
        #pragma unroll
        for (int p = 0; p < 8; p++)
            s += g_accpart[((size_t)((p*BATCH + b)*NSLOT) + n)*DIM + t];
        size_t idx = ((size_t)(b*NSLOT) + n)*DIM + t;
        float val = g_templates[idx] + s * csin[n];
        g_templates[idx] = val;
        tv[n*256 + t] = val;
    }
    __syncthreads();
    {
        int r = t >> 2, part = t & 3;
        const float* row = tv + r*256 + part*64;
        float s = 0.f, sq = 0.f;
        #pragma unroll
        for (int i = 0; i < 64; i += 4) {
            float4 v = *(const float4*)(row + i);
            s += v.x+v.y+v.z+v.w;
            sq += v.x*v.x + v.y*v.y + v.z*v.z + v.w*v.w;
        }
        s  += __shfl_xor_sync(0xffffffffu, s, 1);  s  += __shfl_xor_sync(0xffffffffu, s, 2);
        sq += __shfl_xor_sync(0xffffffffu, sq, 1); sq += __shfl_xor_sync(0xffffffffu, sq, 2);
        float mu = s * (1.0f/256.0f);
        float rs = rsqrtf(sq * (1.0f/256.0f) - mu*mu + 1e-5f);
        size_t o = ((size_t)(b*NSLOT) + r)*DIM + part*64;
        #pragma unroll
        for (int i = 0; i < 64; i += 2) {
            int ch = part*64 + i;
            float v0 = (row[i]   - mu)*rs*g[ch]   + bb[ch];
            float v1 = (row[i+1] - mu)*rs*g[ch+1] + bb[ch+1];
            __nv_bfloat162 hh, ll;
            bsplit(v0, v1, hh, ll);
            *(__nv_bfloat162*)(g_tbh + o + i) = hh;
            *(__nv_bfloat162*)(g_tbl + o + i) = ll;
        }
    }
}

// ---------------- outputs ----------------
__global__ void out_templates_kernel(float* __restrict__ out) {
    int b = blockIdx.x, d = threadIdx.x;
    for (int n = 0; n < NSLOT; n++)
        out[((size_t)(b*DIM) + d)*NSLOT + n] = g_templates[((size_t)(b*NSLOT) + n)*DIM + d];
}

__global__ void out_attn_kernel(float* __restrict__ out) {
    int n = blockIdx.x, b = blockIdx.y, t = threadIdx.x;
    float inv = 1.0f / g_colsum[b*NSLOT + n];
    size_t base = (size_t)BATCH*DIM*NSLOT + ((size_t)(b*NSLOT + n))*LTOK;
    for (int k = 0; k < 16; k++) {
        int l = k*256 + t;
        out[base + l] = g_attn[((size_t)b*LTOK + l)*NSLOT + n] * inv;
    }
}

// ---------------- launch ----------------
extern "C" void kernel_launch(void* const* d_in, const int* in_sizes, int n_in,
                              void* d_out, int out_size) {
    const float* x       = (const float*)d_in[0];
    const float* tinit   = (const float*)d_in[1];
    const float* conv_w  = (const float*)d_in[2];
    const float* conv_b  = (const float*)d_in[3];
    const float* Wq      = (const float*)d_in[4];
    const float* Wk      = (const float*)d_in[5];
    const float* Wv      = (const float*)d_in[6];
    const float* ln_in_g = (const float*)d_in[7];
    const float* ln_in_b = (const float*)d_in[8];
    const float* ln_t_g  = (const float*)d_in[9];
    const float* ln_t_b  = (const float*)d_in[10];
    const float* ln_m_g  = (const float*)d_in[11];
    const float* ln_m_b  = (const float*)d_in[12];
    const float* W1      = (const float*)d_in[13];
    const float* b1      = (const float*)d_in[14];
    const float* W2      = (const float*)d_in[15];
    const float* b2      = (const float*)d_in[16];
    float* out = (float*)d_out;

    cudaFuncSetAttribute(conv_mma_kernel, cudaFuncAttributeMaxDynamicSharedMemorySize, CMM_SMEM);
    cudaFuncSetAttribute(kv_mma_kernel, cudaFuncAttributeMaxDynamicSharedMemorySize, CMM_SMEM);
    cudaFuncSetAttribute(gemm_q_mma_kernel, cudaFuncAttributeMaxDynamicSharedMemorySize, CMM_SMEM);
    cudaFuncSetAttribute(gemm_h_mma_kernel, cudaFuncAttributeMaxDynamicSharedMemorySize, CMM_SMEM);
    cudaFuncSetAttribute(gemm_o_mma_kernel, cudaFuncAttributeMaxDynamicSharedMemorySize, CMM_SMEM);
    cudaFuncSetAttribute(attn_mma_kernel, cudaFuncAttributeMaxDynamicSharedMemorySize, ATT_SMEM);
    cudaFuncSetAttribute(gemm_c_mma_kernel, cudaFuncAttributeMaxDynamicSharedMemorySize, GC_SMEM);
    cudaFuncSetAttribute(finalize_kernel, cudaFuncAttributeMaxDynamicSharedMemorySize, FIN_SMEM_FLOATS*4);

    templates_init_kernel<<<8, 256>>>(tinit);
    xsplit_kernel<<<8*33*33, 256>>>(x);
    cwsplit_kernel<<<3456, 256>>>(conv_w);
    kvsplit_kernel<<<512, 256>>>(Wk, Wv);
    wsplit_kernel<<<256, 256>>>(Wq, 0);
    wsplit_kernel<<<512, 256>>>(W1, 1);
    wsplit_kernel<<<512, 256>>>(W2, 2);
    conv_mma_kernel<<<256, 512, CMM_SMEM>>>(conv_b, ln_in_g, ln_in_b);
    kv_mma_kernel<<<512, 512, CMM_SMEM>>>();
    ln_t_split_kernel<<<8, 256>>>(ln_t_g, ln_t_b);

    for (int it = 0; it < 6; it++) {
        gemm_q_mma_kernel<<<4, 512, CMM_SMEM>>>();
        attn_mma_kernel<<<dim3(32, 8), 256, ATT_SMEM>>>();
        gemm_c_mma_kernel<<<dim3(2, 8, 8), 256, GC_SMEM>>>();
        finalize_kernel<<<8, 256, FIN_SMEM_FLOATS*4>>>(ln_m_g, ln_m_b);
        gemm_h_mma_kernel<<<dim3(2, 4), 512, CMM_SMEM>>>(b1);
        gemm_o_mma_kernel<<<4, 512, CMM_SMEM>>>(b2, ln_t_g, ln_t_b);
    }

    out_templates_kernel<<<8, 256>>>(out);
    out_attn_kernel<<<dim3(64, 8), 256>>>(out);
}

// round 12
// speedup vs baseline: 1.4033x; 1.4033x over previous
#include <cuda_runtime.h>
#include <cuda_bf16.h>
#include <stdint.h>
#include <math.h>

#define BATCH 8
#define DIM   256
#define NSLOT 64
#define LTOK  4096

typedef unsigned long long u64;

__device__ __forceinline__ u64 PK1(float v) {
    u64 r; asm("mov.b64 %0, {%1,%1};" : "=l"(r) : "f"(v)); return r;
}
__device__ __forceinline__ void FMA2(u64& d, u64 a, u64 b) {
    asm("fma.rn.f32x2 %0, %1, %2, %0;" : "+l"(d) : "l"(a), "l"(b));
}
__device__ __forceinline__ float2 UPK(u64 v) {
    float2 f; asm("mov.b64 {%0,%1}, %2;" : "=f"(f.x), "=f"(f.y) : "l"(v)); return f;
}

// ---------------- scratch ----------------
__device__ float g_templates[BATCH*NSLOT*DIM];
__device__ float g_tbuf[BATCH*NSLOT*DIM];
__device__ float g_attn[BATCH*LTOK*NSLOT];
__device__ float g_colsum_part[BATCH*64*NSLOT];
__device__ float g_colsum[BATCH*NSLOT];
__device__ float g_accpart[8*BATCH*NSLOT*DIM];
__device__ float g_hidden[BATCH*NSLOT*512];
// bf16 split operands
__device__ __nv_bfloat16 g_xh[36799488];
__device__ __nv_bfloat16 g_xl[36799488];
__device__ __nv_bfloat16 g_cwh[27*32768];
__device__ __nv_bfloat16 g_cwl[27*32768];
__device__ __nv_bfloat16 g_kvh[256*512];
__device__ __nv_bfloat16 g_kvl[256*512];
__device__ __nv_bfloat16 g_toksh[32768*256];
__device__ __nv_bfloat16 g_toksl[32768*256];
__device__ __nv_bfloat16 g_kh[32768*256];
__device__ __nv_bfloat16 g_kl[32768*256];
__device__ __nv_bfloat16 g_vh[32768*256];
__device__ __nv_bfloat16 g_vl[32768*256];
__device__ __nv_bfloat16 g_qh[BATCH*NSLOT*DIM];
__device__ __nv_bfloat16 g_ql[BATCH*NSLOT*DIM];
__device__ __nv_bfloat16 g_ath[BATCH*LTOK*NSLOT];
__device__ __nv_bfloat16 g_atl[BATCH*LTOK*NSLOT];

__device__ __forceinline__ float gelu_exact(float v) {
    return 0.5f * v * (1.0f + erff(v * 0.70710678118654752f));
}

// ========== mma.sync helpers ==========
__device__ __forceinline__ uint32_t smem_u32(const void* p) {
    uint32_t a;
    asm("{ .reg .u64 t; cvta.to.shared.u64 t, %1; cvt.u32.u64 %0, t; }" : "=r"(a) : "l"(p));
    return a;
}
__device__ __forceinline__ void ldsm_x4(uint32_t* r, uint32_t addr) {
    asm volatile("ldmatrix.sync.aligned.m8n8.x4.shared.b16 {%0,%1,%2,%3}, [%4];"
        : "=r"(r[0]), "=r"(r[1]), "=r"(r[2]), "=r"(r[3]) : "r"(addr));
}
__device__ __forceinline__ void ldsm_x4_t(uint32_t* r, uint32_t addr) {
    asm volatile("ldmatrix.sync.aligned.m8n8.x4.trans.shared.b16 {%0,%1,%2,%3}, [%4];"
        : "=r"(r[0]), "=r"(r[1]), "=r"(r[2]), "=r"(r[3]) : "r"(addr));
}
__device__ __forceinline__ void mma_bf16(float* d, const uint32_t* a, const uint32_t* b) {
    asm volatile("mma.sync.aligned.m16n8k16.row.col.f32.bf16.bf16.f32 "
        "{%0,%1,%2,%3}, {%4,%5,%6,%7}, {%8,%9}, {%0,%1,%2,%3};"
        : "+f"(d[0]), "+f"(d[1]), "+f"(d[2]), "+f"(d[3])
        : "r"(a[0]), "r"(a[1]), "r"(a[2]), "r"(a[3]), "r"(b[0]), "r"(b[1]));
}
__device__ __forceinline__ void bsplit(float v0, float v1, __nv_bfloat162& hh, __nv_bfloat162& ll) {
    __nv_bfloat16 h0 = __float2bfloat16(v0), h1 = __float2bfloat16(v1);
    hh.x = h0; hh.y = h1;
    ll.x = __float2bfloat16(v0 - __bfloat162float(h0));
    ll.y = __float2bfloat16(v1 - __bfloat162float(h1));
}
__device__ __forceinline__ void cpa16(uint32_t dst, const void* src) {
    asm volatile("cp.async.cg.shared.global [%0], [%1], 16;" :: "r"(dst), "l"(src) : "memory");
}
#define CP_COMMIT asm volatile("cp.async.commit_group;" ::: "memory")
#define CP_WAIT0  asm volatile("cp.async.wait_group 0;" ::: "memory")

// 128x256 += A(128x128, pitch 272B) x B(128k x 256n, pitch 528B); 3-term bf16 split.
__device__ __forceinline__ void mma_chunk(
    uint32_t sAh, uint32_t sAl, uint32_t sBh, uint32_t sBl,
    float d[2][8][4], int wm, int wn, int lane)
{
    uint32_t aoff0 = (uint32_t)((wm*32 + (lane & 15))*272 + (lane >> 4)*16);
    uint32_t boff0 = (uint32_t)((lane & 15)*528 + (wn*64 + (lane >> 4)*8)*2);
    #pragma unroll
    for (int kk = 0; kk < 8; kk++) {
        uint32_t ah[8], al[8], bb[16];
        uint32_t ao = aoff0 + kk*32;
        ldsm_x4(ah,     sAh + ao);
        ldsm_x4(ah + 4, sAh + ao + 4352);
        ldsm_x4(al,     sAl + ao);
        ldsm_x4(al + 4, sAl + ao + 4352);
        uint32_t bo = boff0 + kk*8448;
        #pragma unroll
        for (int jj = 0; jj < 4; jj++) ldsm_x4_t(bb + jj*4, sBh + bo + jj*32);
        #pragma unroll
        for (int mi = 0; mi < 2; mi++) {
            #pragma unroll
            for (int j = 0; j < 8; j++) {
                const uint32_t* bf = bb + (j >> 1)*4 + (j & 1)*2;
                mma_bf16(d[mi][j], mi ? ah + 4 : ah, bf);
                mma_bf16(d[mi][j], mi ? al + 4 : al, bf);
            }
        }
        #pragma unroll
        for (int jj = 0; jj < 4; jj++) ldsm_x4_t(bb + jj*4, sBl + bo + jj*32);
        #pragma unroll
        for (int mi = 0; mi < 2; mi++) {
            #pragma unroll
            for (int j = 0; j < 8; j++) {
                const uint32_t* bf = bb + (j >> 1)*4 + (j & 1)*2;
                mma_bf16(d[mi][j], mi ? ah + 4 : ah, bf);
            }
        }
    }
}

// dual-term pass: d += Ah*B + Al*B  (first half of mma_chunk, verbatim)
__device__ __forceinline__ void mma_dual(
    uint32_t sAh, uint32_t sAl, uint32_t sB,
    float d[2][8][4], int wm, int wn, int lane)
{
    uint32_t aoff0 = (uint32_t)((wm*32 + (lane & 15))*272 + (lane >> 4)*16);
    uint32_t boff0 = (uint32_t)((lane & 15)*528 + (wn*64 + (lane >> 4)*8)*2);
    #pragma unroll
    for (int kk = 0; kk < 8; kk++) {
        uint32_t ah[8], al[8], bb[16];
        uint32_t ao = aoff0 + kk*32;
        ldsm_x4(ah,     sAh + ao);
        ldsm_x4(ah + 4, sAh + ao + 4352);
        ldsm_x4(al,     sAl + ao);
        ldsm_x4(al + 4, sAl + ao + 4352);
        uint32_t bo = boff0 + kk*8448;
        #pragma unroll
        for (int jj = 0; jj < 4; jj++) ldsm_x4_t(bb + jj*4, sB + bo + jj*32);
        #pragma unroll
        for (int mi = 0; mi < 2; mi++) {
            #pragma unroll
            for (int j = 0; j < 8; j++) {
                const uint32_t* bf = bb + (j >> 1)*4 + (j & 1)*2;
                mma_bf16(d[mi][j], mi ? ah + 4 : ah, bf);
                mma_bf16(d[mi][j], mi ? al + 4 : al, bf);
            }
        }
    }
}

// single-term pass: d += Ah*B  (second half of mma_chunk, verbatim)
__device__ __forceinline__ void mma_single(
    uint32_t sAh, uint32_t sB,
    float d[2][8][4], int wm, int wn, int lane)
{
    uint32_t aoff0 = (uint32_t)((wm*32 + (lane & 15))*272 + (lane >> 4)*16);
    uint32_t boff0 = (uint32_t)((lane & 15)*528 + (wn*64 + (lane >> 4)*8)*2);
    #pragma unroll
    for (int kk = 0; kk < 8; kk++) {
        uint32_t ah[8], bb[16];
        uint32_t ao = aoff0 + kk*32;
        ldsm_x4(ah,     sAh + ao);
        ldsm_x4(ah + 4, sAh + ao + 4352);
        uint32_t bo = boff0 + kk*8448;
        #pragma unroll
        for (int jj = 0; jj < 4; jj++) ldsm_x4_t(bb + jj*4, sB + bo + jj*32);
        #pragma unroll
        for (int mi = 0; mi < 2; mi++) {
            #pragma unroll
            for (int j = 0; j < 8; j++) {
                const uint32_t* bf = bb + (j >> 1)*4 + (j & 1)*2;
                mma_bf16(d[mi][j], mi ? ah + 4 : ah, bf);
            }
        }
    }
}

// ---------------- prep kernels ----------------
__global__ void templates_init_kernel(const float* __restrict__ tinit) {
    int b = blockIdx.x, t = threadIdx.x;
    for (int n = 0; n < NSLOT; n++)
        g_templates[(b*NSLOT + n)*DIM + t] = tinit[n*DIM + t];
}

__global__ __launch_bounds__(256) void xsplit_kernel(const float* __restrict__ x) {
    __shared__ float st[128*33];
    int bid = blockIdx.x; int b = bid / 1089; int rem = bid % 1089; int d = rem / 33, h = rem % 33;
    int t = threadIdx.x, warp = t >> 5, lane = t & 31;
    const float* xb = x + ((((size_t)b*128)*33 + d)*33 + h)*33;
    for (int c = warp; c < 128; c += 8) {
        const float* src = xb + (size_t)c*35937;
        st[c*33 + lane] = src[lane];
        if (lane == 0) st[c*33 + 32] = src[32];
    }
    __syncthreads();
    size_t ob = ((((size_t)b*33 + d)*33 + h)*33)*128;
    for (int i = t; i < 33*128; i += 256) {
        int w = i >> 7, c = i & 127;
        float v = st[c*33 + w];
        __nv_bfloat16 hi = __float2bfloat16(v);
        g_xh[ob + (size_t)w*128 + c] = hi;
        g_xl[ob + (size_t)w*128 + c] = __float2bfloat16(v - __bfloat162float(hi));
    }
}

__global__ void cwsplit_kernel(const float* __restrict__ cw) {
    int idx = blockIdx.x*256 + threadIdx.x;
    int tap = idx >> 15, r = idx & 32767;
    int k = r >> 8, n = r & 255;
    float v = cw[(size_t)n*3456 + k*27 + tap];
    __nv_bfloat16 hi = __float2bfloat16(v);
    g_cwh[idx] = hi;
    g_cwl[idx] = __float2bfloat16(v - __bfloat162float(hi));
}

__global__ void kvsplit_kernel(const float* __restrict__ Wk, const float* __restrict__ Wv) {
    int idx = blockIdx.x*256 + threadIdx.x;
    int k = idx >> 9, c512 = idx & 511;
    int mat = c512 >> 8, col = c512 & 255;
    const float* W = mat ? Wv : Wk;
    float v = W[(size_t)k*256 + col];
    __nv_bfloat16 hi = __float2bfloat16(v);
    g_kvh[idx] = hi;
    g_kvl[idx] = __float2bfloat16(v - __bfloat162float(hi));
}

// ---------------- conv (implicit GEMM, cp.async-pipelined B) + bias + ReLU + LN ----------------
// smem: Ah 0(34816), Al 34816, B0 69632(67584: Bh slot), B1 137216(Bl slot). total 204800.
#define CMM_SMEM 204800
__global__ __launch_bounds__(512, 1) void conv_mma_kernel(
    const float* __restrict__ convb, const float* __restrict__ lng, const float* __restrict__ lnb)
{
    extern __shared__ char sm[];
    uint32_t sb = smem_u32(sm);
    const uint32_t oAh = 0, oAl = 34816, oB0 = 69632, oB1 = 137216;
    int t = threadIdx.x, lane = t & 31, wid = t >> 5;
    int wm = wid >> 2, wn = wid & 3;
    int bx = blockIdx.x; int b = bx >> 5, xd = (bx >> 1) & 15, half = bx & 1;

    float d[2][8][4];
    #pragma unroll
    for (int i = 0; i < 2; i++)
        #pragma unroll
        for (int j = 0; j < 8; j++)
            #pragma unroll
            for (int c = 0; c < 4; c++) d[i][j][c] = 0.f;

    int m = t >> 2, q = t & 3;
    int xhl = m >> 4, xw = m & 15;

    // preload Bh(tap 0) into B0
    {
        const uint4* s1 = (const uint4*)(g_cwh);
        #pragma unroll
        for (int it = 0; it < 8; it++) {
            int i = t + it*512;
            cpa16(sb + oB0 + (uint32_t)((i >> 5)*528 + (i & 31)*16), s1 + i);
        }
        CP_COMMIT;
    }

    for (int tap = 0; tap < 27; tap++) {
        int kd = tap/9, r9 = tap%9, kh = r9/3, kw = r9%3;
        // A tiles (regular stores)
        {
            size_t xi = ((((size_t)(b*33) + 2*xd + kd)*33 + 2*(half*8 + xhl) + kh)*33 + 2*xw + kw)*128 + q*32;
            const uint4* shi = (const uint4*)(g_xh + xi);
            const uint4* slo = (const uint4*)(g_xl + xi);
            char* dh = sm + oAh + m*272 + q*64;
            char* dl = sm + oAl + m*272 + q*64;
            #pragma unroll
            for (int j = 0; j < 4; j++) {
                *(uint4*)(dh + j*16) = shi[j];
                *(uint4*)(dl + j*16) = slo[j];
            }
        }
        CP_WAIT0;              // Bh(tap) landed
        __syncthreads();       // + A visible, prior readers done
        // prefetch Bl(tap) into B1
        {
            const uint4* s2 = (const uint4*)(g_cwl + tap*32768);
            #pragma unroll
            for (int it = 0; it < 8; it++) {
                int i = t + it*512;
                cpa16(sb + oB1 + (uint32_t)((i >> 5)*528 + (i & 31)*16), s2 + i);
            }
            CP_COMMIT;
        }
        mma_dual(sb + oAh, sb + oAl, sb + oB0, d, wm, wn, lane);   // ah*Bh + al*Bh
        CP_WAIT0;              // Bl(tap) landed
        __syncthreads();       // everyone done reading B0
        if (tap < 26) {        // prefetch Bh(tap+1) into B0
            const uint4* s1 = (const uint4*)(g_cwh + (tap+1)*32768);
            #pragma unroll
            for (int it = 0; it < 8; it++) {
                int i = t + it*512;
                cpa16(sb + oB0 + (uint32_t)((i >> 5)*528 + (i & 31)*16), s1 + i);
            }
            CP_COMMIT;
        }
        mma_single(sb + oAh, sb + oB1, d, wm, wn, lane);           // ah*Bl
        __syncthreads();       // done with A and B1 before next tap overwrites
    }

    // stage fp32 accum to smem, pitch 264 floats
    float* stg = (float*)sm;
    {
        int r0 = wm*32 + (lane >> 2);
        int c0 = wn*64 + (lane & 3)*2;
        #pragma unroll
        for (int mi = 0; mi < 2; mi++)
            #pragma unroll
            for (int j = 0; j < 8; j++) {
                int rr = r0 + mi*16, cc = c0 + j*8;
                *(float2*)(stg + (size_t)rr*264 + cc)     = make_float2(d[mi][j][0], d[mi][j][1]);
                *(float2*)(stg + (size_t)(rr+8)*264 + cc) = make_float2(d[mi][j][2], d[mi][j][3]);
            }
    }
    __syncthreads();

    {
        int tok = t >> 2, q2 = t & 3;
        const float* src = stg + (size_t)tok*264 + q2*64;
        float z[64];
        float s = 0.f, sq = 0.f;
        #pragma unroll
        for (int i = 0; i < 64; i++) {
            float v = fmaxf(src[i] + convb[q2*64 + i], 0.f);
            z[i] = v; s += v; sq += v*v;
        }
        s  += __shfl_xor_sync(0xffffffffu, s, 1);  s  += __shfl_xor_sync(0xffffffffu, s, 2);
        sq += __shfl_xor_sync(0xffffffffu, sq, 1); sq += __shfl_xor_sync(0xffffffffu, sq, 2);
        float mu = s * (1.f/256.f);
        float rs = rsqrtf(sq * (1.f/256.f) - mu*mu + 1e-5f);
        int l = (xd*16 + half*8 + (tok >> 4))*16 + (tok & 15);
        size_t tg = ((size_t)b*4096 + l)*256 + q2*64;
        #pragma unroll
        for (int i = 0; i < 64; i += 2) {
            int ch = q2*64 + i;
            float v0 = (z[i]   - mu)*rs*lng[ch]   + lnb[ch];
            float v1 = (z[i+1] - mu)*rs*lng[ch+1] + lnb[ch+1];
            __nv_bfloat162 hh, ll;
            bsplit(v0, v1, hh, ll);
            *(__nv_bfloat162*)(g_toksh + tg + i) = hh;
            *(__nv_bfloat162*)(g_toksl + tg + i) = ll;
        }
    }
}

// ---------------- K/V projection via mma.sync -> bf16 split outputs ----------------
__global__ __launch_bounds__(512, 1) void kv_mma_kernel() {
    extern __shared__ char sm[];
    uint32_t sb = smem_u32(sm);
    const uint32_t oAh = 0, oAl = 34816, oBh = 69632, oBl = 137216;
    int t = threadIdx.x, lane = t & 31, wid = t >> 5;
    int wm = wid >> 2, wn = wid & 3;
    int nhalf = blockIdx.x & 1, chunk = blockIdx.x >> 1;

    float d[2][8][4];
    #pragma unroll
    for (int i = 0; i < 2; i++)
        #pragma unroll
        for (int j = 0; j < 8; j++)
            #pragma unroll
            for (int c = 0; c < 4; c++) d[i][j][c] = 0.f;

    int m = t >> 2, q = t & 3;
    for (int kc = 0; kc < 2; kc++) {
        {
            size_t ti = ((size_t)(chunk*128 + m))*256 + kc*128 + q*32;
            const uint4* shi = (const uint4*)(g_toksh + ti);
            const uint4* slo = (const uint4*)(g_toksl + ti);
            char* dh = sm + oAh + m*272 + q*64;
            char* dl = sm + oAl + m*272 + q*64;
            #pragma unroll
            for (int j = 0; j < 4; j++) {
                *(uint4*)(dh + j*16) = shi[j];
                *(uint4*)(dl + j*16) = slo[j];
            }
        }
        {
            #pragma unroll
            for (int it = 0; it < 8; it++) {
                int i = t + it*512;
                int row = i >> 5, seg = i & 31;
                size_t off = (size_t)(kc*128 + row)*512 + nhalf*256 + seg*8;
                *(uint4*)(sm + oBh + row*528 + seg*16) = *(const uint4*)(g_kvh + off);
                *(uint4*)(sm + oBl + row*528 + seg*16) = *(const uint4*)(g_kvl + off);
            }
        }
        __syncthreads();
        mma_chunk(sb + oAh, sb + oAl, sb + oBh, sb + oBl, d, wm, wn, lane);
        __syncthreads();
    }

    __nv_bfloat16* dh = nhalf ? g_vh : g_kh;
    __nv_bfloat16* dl = nhalf ? g_vl : g_kl;
    int r0 = wm*32 + (lane >> 2);
    int c0 = wn*64 + (lane & 3)*2;
    #pragma unroll
    for (int mi = 0; mi < 2; mi++)
        #pragma unroll
        for (int j = 0; j < 8; j++) {
            int rr = r0 + mi*16, cc = c0 + j*8;
            size_t tok = (size_t)chunk*128 + rr;
            __nv_bfloat162 hh, ll;
            bsplit(d[mi][j][0], d[mi][j][1], hh, ll);
            *(__nv_bfloat162*)(dh + tok*256 + cc) = hh;
            *(__nv_bfloat162*)(dl + tok*256 + cc) = ll;
            bsplit(d[mi][j][2], d[mi][j][3], hh, ll);
            *(__nv_bfloat162*)(dh + (tok+8)*256 + cc) = hh;
            *(__nv_bfloat162*)(dl + (tok+8)*256 + cc) = ll;
        }
}

// ---------------- fused LN_t + q-GEMM (scalar, proven) -> bf16 split q ----------------
__global__ __launch_bounds__(256) void gemm_q_kernel(
    const float* __restrict__ Wq, const float* __restrict__ lng, const float* __restrict__ lnb)
{
    extern __shared__ float smf[];
    float* Af = smf; float* Bs = smf + 16384;
    int b = blockIdx.y; int nc = blockIdx.x * 64;
    int t = threadIdx.x;
    {
        int r = t >> 2, part = t & 3;
        const float* row = g_templates + ((size_t)(b*NSLOT) + r)*DIM + part*64;
        float s = 0.f, sq = 0.f;
        #pragma unroll
        for (int i = 0; i < 64; i += 4) {
            float4 v = *(const float4*)(row + i);
            s += v.x+v.y+v.z+v.w;
            sq += v.x*v.x + v.y*v.y + v.z*v.z + v.w*v.w;
        }
        s  += __shfl_xor_sync(0xffffffffu, s, 1);  s  += __shfl_xor_sync(0xffffffffu, s, 2);
        sq += __shfl_xor_sync(0xffffffffu, sq, 1); sq += __shfl_xor_sync(0xffffffffu, sq, 2);
        float mu = s * (1.0f/256.0f);
        float rs = rsqrtf(sq * (1.0f/256.0f) - mu*mu + 1e-5f);
        #pragma unroll
        for (int i = 0; i < 64; i += 4) {
            float4 v = *(const float4*)(row + i);
            float4 gg = *(const float4*)(lng + part*64 + i);
            float4 bv = *(const float4*)(lnb + part*64 + i);
            Af[(part*64+i+0)*64 + r] = (v.x - mu)*rs*gg.x + bv.x;
            Af[(part*64+i+1)*64 + r] = (v.y - mu)*rs*gg.y + bv.y;
            Af[(part*64+i+2)*64 + r] = (v.z - mu)*rs*gg.z + bv.z;
            Af[(part*64+i+3)*64 + r] = (v.w - mu)*rs*gg.w + bv.w;
        }
    }
    __syncthreads();
    int tm = t >> 4, tn = t & 15;
    u64 acc[4][2] = {};
    int kk0 = t >> 4, n4 = (t & 15)*4;
    for (int k0 = 0; k0 < 256; k0 += 16) {
        *(float4*)(Bs + kk0*64 + n4) = *(const float4*)(Wq + (size_t)(k0+kk0)*256 + nc + n4);
        __syncthreads();
        #pragma unroll
        for (int kk = 0; kk < 16; kk++) {
            ulonglong2 a2 = *(ulonglong2*)(Af + (k0+kk)*64 + tm*4);
            float4 bb = *(float4*)(Bs + kk*64 + tn*4);
            u64 q0 = PK1(bb.x), q1 = PK1(bb.y), q2 = PK1(bb.z), q3 = PK1(bb.w);
            FMA2(acc[0][0], a2.x, q0); FMA2(acc[0][1], a2.y, q0);
            FMA2(acc[1][0], a2.x, q1); FMA2(acc[1][1], a2.y, q1);
            FMA2(acc[2][0], a2.x, q2); FMA2(acc[2][1], a2.y, q2);
            FMA2(acc[3][0], a2.x, q3); FMA2(acc[3][1], a2.y, q3);
        }
        __syncthreads();
    }
    const float scale = 0.0625f;
    #pragma unroll
    for (int p = 0; p < 2; p++) {
        float2 f0 = UPK(acc[0][p]), f1 = UPK(acc[1][p]), f2 = UPK(acc[2][p]), f3 = UPK(acc[3][p]);
        int mm = tm*4 + p*2;
        size_t o0 = ((size_t)(b*NSLOT) + mm)*DIM + nc + tn*4;
        __nv_bfloat162 hh, ll;
        bsplit(f0.x*scale, f1.x*scale, hh, ll);
        *(__nv_bfloat162*)(g_qh + o0) = hh; *(__nv_bfloat162*)(g_ql + o0) = ll;
        bsplit(f2.x*scale, f3.x*scale, hh, ll);
        *(__nv_bfloat162*)(g_qh + o0 + 2) = hh; *(__nv_bfloat162*)(g_ql + o0 + 2) = ll;
        bsplit(f0.y*scale, f1.y*scale, hh, ll);
        *(__nv_bfloat162*)(g_qh + o0 + DIM) = hh; *(__nv_bfloat162*)(g_ql + o0 + DIM) = ll;
        bsplit(f2.y*scale, f3.y*scale, hh, ll);
        *(__nv_bfloat162*)(g_qh + o0 + DIM + 2) = hh; *(__nv_bfloat162*)(g_ql + o0 + DIM + 2) = ll;
    }
}

// ---------------- attn logits via mma + softmax + colsum partials ----------------
#define ATT_SMEM 104448
__global__ __launch_bounds__(256) void attn_mma_kernel() {
    extern __shared__ char sm[];
    uint32_t sb = smem_u32(sm);
    const uint32_t oAh = 0, oAl = 34816, oQh = 69632, oQl = 87040;
    int t = threadIdx.x, lane = t & 31, wid = t >> 5;
    int wm = wid >> 1, wn = wid & 1;
    int lb = blockIdx.x, b = blockIdx.y;

    float d[2][4][4];
    #pragma unroll
    for (int i = 0; i < 2; i++)
        #pragma unroll
        for (int j = 0; j < 4; j++)
            #pragma unroll
            for (int c = 0; c < 4; c++) d[i][j][c] = 0.f;

    for (int kc = 0; kc < 2; kc++) {
        {
            int row = t >> 1, half = t & 1;
            size_t ti = ((size_t)(b*4096) + lb*128 + row)*256 + kc*128 + half*64;
            const uint4* shi = (const uint4*)(g_kh + ti);
            const uint4* slo = (const uint4*)(g_kl + ti);
            char* dh = sm + oAh + row*272 + half*128;
            char* dl = sm + oAl + row*272 + half*128;
            #pragma unroll
            for (int j = 0; j < 8; j++) {
                *(uint4*)(dh + j*16) = shi[j];
                *(uint4*)(dl + j*16) = slo[j];
            }
        }
        {
            int row = t >> 2, q4 = t & 3;
            size_t ti = ((size_t)(b*NSLOT) + row)*256 + kc*128 + q4*32;
            const uint4* shi = (const uint4*)(g_qh + ti);
            const uint4* slo = (const uint4*)(g_ql + ti);
            char* dh = sm + oQh + row*272 + q4*64;
            char* dl = sm + oQl + row*272 + q4*64;
            #pragma unroll
            for (int j = 0; j < 4; j++) {
                *(uint4*)(dh + j*16) = shi[j];
                *(uint4*)(dl + j*16) = slo[j];
            }
        }
        __syncthreads();
        uint32_t aoff0 = (uint32_t)((wm*32 + (lane & 15))*272 + (lane >> 4)*16);
        uint32_t qoff0 = (uint32_t)(((lane >> 4)*8 + (lane & 7) + wn*32)*272 + ((lane >> 3) & 1)*16);
        #pragma unroll
        for (int kk = 0; kk < 8; kk++) {
            uint32_t ah[8], al[8], qh8[8], ql8[8];
            uint32_t ao = aoff0 + kk*32;
            ldsm_x4(ah,     sb + oAh + ao);
            ldsm_x4(ah + 4, sb + oAh + ao + 16*272);
            ldsm_x4(al,     sb + oAl + ao);
            ldsm_x4(al + 4, sb + oAl + ao + 16*272);
            uint32_t qo = qoff0 + kk*32;
            ldsm_x4(qh8,     sb + oQh + qo);
            ldsm_x4(qh8 + 4, sb + oQh + qo + 16*272);
            ldsm_x4(ql8,     sb + oQl + qo);
            ldsm_x4(ql8 + 4, sb + oQl + qo + 16*272);
            #pragma unroll
            for (int mi = 0; mi < 2; mi++) {
                #pragma unroll
                for (int j = 0; j < 4; j++) {
                    const uint32_t* bh = qh8 + (j >> 1)*4 + (j & 1)*2;
                    const uint32_t* bl = ql8 + (j >> 1)*4 + (j & 1)*2;
                    const uint32_t* am = mi ? ah + 4 : ah;
                    const uint32_t* aml = mi ? al + 4 : al;
                    mma_bf16(d[mi][j], am, bh);
                    mma_bf16(d[mi][j], am, bl);
                    mma_bf16(d[mi][j], aml, bh);
                }
            }
        }
        __syncthreads();
    }

    float* stg = (float*)sm;
    {
        int r0 = wm*32 + (lane >> 2);
        int c0 = wn*32 + (lane & 3)*2;
        #pragma unroll
        for (int mi = 0; mi < 2; mi++)
            #pragma unroll
            for (int j = 0; j < 4; j++) {
                int rr = r0 + mi*16, cc = c0 + j*8;
                *(float2*)(stg + rr*68 + cc)     = make_float2(d[mi][j][0], d[mi][j][1]);
                *(float2*)(stg + (rr+8)*68 + cc) = make_float2(d[mi][j][2], d[mi][j][3]);
            }
    }
    __syncthreads();

    {
        int row = t >> 1, half = t & 1;
        float* sr = stg + row*68 + half*32;
        float a[32];
        float mx = -3.4e38f;
        #pragma unroll
        for (int i = 0; i < 32; i++) { a[i] = sr[i]; mx = fmaxf(mx, a[i]); }
        mx = fmaxf(mx, __shfl_xor_sync(0xffffffffu, mx, 1));
        float s = 0.f;
        #pragma unroll
        for (int i = 0; i < 32; i++) { a[i] = expf(a[i] - mx); s += a[i]; }
        s += __shfl_xor_sync(0xffffffffu, s, 1);
        float inv = 1.0f / s;
        size_t gi = ((size_t)(b*4096) + lb*128 + row)*64 + half*32;
        #pragma unroll
        for (int i = 0; i < 32; i++) { a[i] = a[i]*inv + 1e-8f; sr[i] = a[i]; }
        #pragma unroll
        for (int i = 0; i < 32; i += 4)
            *(float4*)(g_attn + gi + i) = make_float4(a[i], a[i+1], a[i+2], a[i+3]);
        #pragma unroll
        for (int i = 0; i < 32; i += 2) {
            __nv_bfloat162 hh, ll;
            bsplit(a[i], a[i+1], hh, ll);
            *(__nv_bfloat162*)(g_ath + gi + i) = hh;
            *(__nv_bfloat162*)(g_atl + gi + i) = ll;
        }
    }
    __syncthreads();
    if (t < 64) {
        float s = 0.f;
        for (int r = 0; r < 128; r++) s += stg[r*68 + t];
        g_colsum_part[((size_t)b*64 + lb)*NSLOT + t] = s;
    }
}

// ---------------- attn^T @ v via mma. grid (2, 8, 8) ----------------
#define GC_SMEM 106496
__global__ __launch_bounds__(256) void gemm_c_mma_kernel() {
    extern __shared__ char sm[];
    uint32_t sb = smem_u32(sm);
    const uint32_t oAth = 0, oAtl = 18432, oVh = 36864, oVl = 71680;
    int t = threadIdx.x, lane = t & 31, wid = t >> 5;
    int wm = wid & 1, wn = wid >> 1;
    int dh = blockIdx.x, ps = blockIdx.y, b = blockIdx.z;

    float d[2][4][4];
    #pragma unroll
    for (int i = 0; i < 2; i++)
        #pragma unroll
        for (int j = 0; j < 4; j++)
            #pragma unroll
            for (int c = 0; c < 4; c++) d[i][j][c] = 0.f;

    for (int lc = 0; lc < 4; lc++) {
        int l0 = ps*512 + lc*128;
        {
            int row = t >> 1, half = t & 1;
            size_t ti = ((size_t)(b*4096) + l0 + row)*64 + half*32;
            const uint4* shi = (const uint4*)(g_ath + ti);
            const uint4* slo = (const uint4*)(g_atl + ti);
            char* dst_h = sm + oAth + row*144 + half*64;
            char* dst_l = sm + oAtl + row*144 + half*64;
            #pragma unroll
            for (int j = 0; j < 4; j++) {
                *(uint4*)(dst_h + j*16) = shi[j];
                *(uint4*)(dst_l + j*16) = slo[j];
            }
        }
        {
            int row = t >> 1, half = t & 1;
            size_t ti = ((size_t)(b*4096) + l0 + row)*256 + dh*128 + half*64;
            const uint4* shi = (const uint4*)(g_vh + ti);
            const uint4* slo = (const uint4*)(g_vl + ti);
            char* dst_h = sm + oVh + row*272 + half*128;
            char* dst_l = sm + oVl + row*272 + half*128;
            #pragma unroll
            for (int j = 0; j < 8; j++) {
                *(uint4*)(dst_h + j*16) = shi[j];
                *(uint4*)(dst_l + j*16) = slo[j];
            }
        }
        __syncthreads();
        uint32_t aoff0 = (uint32_t)((((lane >> 4)*8 + (lane & 7)))*144 + ((lane >> 3) & 1)*16 + wm*64);
        uint32_t boff0 = (uint32_t)((lane & 15)*272 + (wn*32 + (lane >> 4)*8)*2);
        #pragma unroll
        for (int kk = 0; kk < 8; kk++) {
            uint32_t ah[8], al[8], bh8[8], bl8[8];
            uint32_t ao = aoff0 + kk*16*144;
            ldsm_x4_t(ah,     sb + oAth + ao);
            ldsm_x4_t(ah + 4, sb + oAth + ao + 32);
            ldsm_x4_t(al,     sb + oAtl + ao);
            ldsm_x4_t(al + 4, sb + oAtl + ao + 32);
            uint32_t bo = boff0 + kk*16*272;
            ldsm_x4_t(bh8,     sb + oVh + bo);
            ldsm_x4_t(bh8 + 4, sb + oVh + bo + 32);
            ldsm_x4_t(bl8,     sb + oVl + bo);
            ldsm_x4_t(bl8 + 4, sb + oVl + bo + 32);
            #pragma unroll
            for (int mi = 0; mi < 2; mi++) {
                #pragma unroll
                for (int j = 0; j < 4; j++) {
                    const uint32_t* bfh = bh8 + (j >> 1)*4 + (j & 1)*2;
                    const uint32_t* bfl = bl8 + (j >> 1)*4 + (j & 1)*2;
                    const uint32_t* am = mi ? ah + 4 : ah;
                    const uint32_t* aml = mi ? al + 4 : al;
                    mma_bf16(d[mi][j], am, bfh);
                    mma_bf16(d[mi][j], am, bfl);
                    mma_bf16(d[mi][j], aml, bfh);
                }
            }
        }
        __syncthreads();
    }

    int r0 = wm*32 + (lane >> 2);
    int c0 = dh*128 + wn*32 + (lane & 3)*2;
    float* C = g_accpart + ((size_t)((ps*BATCH + b)*NSLOT))*DIM;
    #pragma unroll
    for (int mi = 0; mi < 2; mi++)
        #pragma unroll
        for (int j = 0; j < 4; j++) {
            int slot = r0 + mi*16, cc = c0 + j*8;
            *(float2*)(C + (size_t)slot*DIM + cc)     = make_float2(d[mi][j][0], d[mi][j][1]);
            *(float2*)(C + (size_t)(slot+8)*DIM + cc) = make_float2(d[mi][j][2], d[mi][j][3]);
        }
}

// ---------------- MLP kernels (scalar, proven) ----------------
__global__ __launch_bounds__(256) void gemm_h_kernel(const float* __restrict__ W1,
                                                     const float* __restrict__ b1)
{
    extern __shared__ float smf[];
    float* Af = smf; float* Bs = smf + 16384;
    int b = blockIdx.y; int nc = blockIdx.x * 64;
    int t = threadIdx.x;
    {
        int r = t >> 2, part = t & 3;
        const float* row = g_tbuf + ((size_t)(b*NSLOT) + r)*DIM + part*64;
        #pragma unroll
        for (int i = 0; i < 64; i += 4) {
            float4 v = *(const float4*)(row + i);
            Af[(part*64+i+0)*64 + r] = v.x;
            Af[(part*64+i+1)*64 + r] = v.y;
            Af[(part*64+i+2)*64 + r] = v.z;
            Af[(part*64+i+3)*64 + r] = v.w;
        }
    }
    __syncthreads();
    int tm = t >> 4, tn = t & 15;
    u64 acc[4][2] = {};
    int kk0 = t >> 4, n4 = (t & 15)*4;
    for (int k0 = 0; k0 < 256; k0 += 16) {
        *(float4*)(Bs + kk0*64 + n4) = *(const float4*)(W1 + (size_t)(k0+kk0)*512 + nc + n4);
        __syncthreads();
        #pragma unroll
        for (int kk = 0; kk < 16; kk++) {
            ulonglong2 a2 = *(ulonglong2*)(Af + (k0+kk)*64 + tm*4);
            float4 bb = *(float4*)(Bs + kk*64 + tn*4);
            u64 q0 = PK1(bb.x), q1 = PK1(bb.y), q2 = PK1(bb.z), q3 = PK1(bb.w);
            FMA2(acc[0][0], a2.x, q0); FMA2(acc[0][1], a2.y, q0);
            FMA2(acc[1][0], a2.x, q1); FMA2(acc[1][1], a2.y, q1);
            FMA2(acc[2][0], a2.x, q2); FMA2(acc[2][1], a2.y, q2);
            FMA2(acc[3][0], a2.x, q3); FMA2(acc[3][1], a2.y, q3);
        }
        __syncthreads();
    }
    float4 bv = *(const float4*)(b1 + nc + tn*4);
    #pragma unroll
    for (int p = 0; p < 2; p++) {
        float2 f0 = UPK(acc[0][p]), f1 = UPK(acc[1][p]), f2 = UPK(acc[2][p]), f3 = UPK(acc[3][p]);
        float4 r0 = {gelu_exact(f0.x+bv.x), gelu_exact(f1.x+bv.y), gelu_exact(f2.x+bv.z), gelu_exact(f3.x+bv.w)};
        float4 r1 = {gelu_exact(f0.y+bv.x), gelu_exact(f1.y+bv.y), gelu_exact(f2.y+bv.z), gelu_exact(f3.y+bv.w)};
        int mm = tm*4 + p*2;
        *(float4*)(g_hidden + ((size_t)(b*NSLOT) + mm  )*512 + nc + tn*4) = r0;
        *(float4*)(g_hidden + ((size_t)(b*NSLOT) + mm+1)*512 + nc + tn*4) = r1;
    }
}

#define GEMMO_SMEM_FLOATS (32768 + 1024)
__global__ __launch_bounds__(256) void gemm_o_kernel(const float* __restrict__ W2,
                                                     const float* __restrict__ b2)
{
    extern __shared__ float smf[];
    float* Af = smf; float* Bs = smf + 32768;
    int b = blockIdx.y; int nc = blockIdx.x * 64;
    int t = threadIdx.x;
    {
        int r = t >> 2, part = t & 3;
        const float* row = g_hidden + ((size_t)(b*NSLOT) + r)*512 + part*128;
        #pragma unroll
        for (int i = 0; i < 128; i += 4) {
            float4 v = *(const float4*)(row + i);
            Af[(part*128+i+0)*64 + r] = v.x;
            Af[(part*128+i+1)*64 + r] = v.y;
            Af[(part*128+i+2)*64 + r] = v.z;
            Af[(part*128+i+3)*64 + r] = v.w;
        }
    }
    __syncthreads();
    int tm = t >> 4, tn = t & 15;
    u64 acc[4][2] = {};
    int kk0 = t >> 4, n4 = (t & 15)*4;
    for (int k0 = 0; k0 < 512; k0 += 16) {
        *(float4*)(Bs + kk0*64 + n4) = *(const float4*)(W2 + (size_t)(k0+kk0)*256 + nc + n4);
        __syncthreads();
        #pragma unroll
        for (int kk = 0; kk < 16; kk++) {
            ulonglong2 a2 = *(ulonglong2*)(Af + (k0+kk)*64 + tm*4);
            float4 bb = *(float4*)(Bs + kk*64 + tn*4);
            u64 q0 = PK1(bb.x), q1 = PK1(bb.y), q2 = PK1(bb.z), q3 = PK1(bb.w);
            FMA2(acc[0][0], a2.x, q0); FMA2(acc[0][1], a2.y, q0);
            FMA2(acc[1][0], a2.x, q1); FMA2(acc[1][1], a2.y, q1);
            FMA2(acc[2][0], a2.x, q2); FMA2(acc[2][1], a2.y, q2);
            FMA2(acc[3][0], a2.x, q3); FMA2(acc[3][1], a2.y, q3);
        }
        __syncthreads();
    }
    float4 bv = *(const float4*)(b2 + nc + tn*4);
    #pragma unroll
    for (int p = 0; p < 2; p++) {
        float2 f0 = UPK(acc[0][p]), f1 = UPK(acc[1][p]), f2 = UPK(acc[2][p]), f3 = UPK(acc[3][p]);
        int mm = tm*4 + p*2;
        float* C0 = g_templates + ((size_t)(b*NSLOT) + mm)*DIM + nc + tn*4;
        float4 c0 = *(float4*)C0;
        c0.x += f0.x + bv.x; c0.y += f1.x + bv.y; c0.z += f2.x + bv.z; c0.w += f3.x + bv.w;
        *(float4*)C0 = c0;
        float* C1 = C0 + DIM;
        float4 c1 = *(float4*)C1;
        c1.x += f0.y + bv.x; c1.y += f1.y + bv.y; c1.z += f2.y + bv.z; c1.w += f3.y + bv.w;
        *(float4*)C1 = c1;
    }
}

// ---------------- fused colsum + template update + LN_m. grid 8 ----------------
#define FIN_SMEM_FLOATS (16384 + 256 + 64)
__global__ __launch_bounds__(256) void finalize_kernel(const float* __restrict__ g,
                                                       const float* __restrict__ bb) {
    extern __shared__ float smf[];
    float* tv   = smf;
    float* csp  = smf + 16384;
    float* csin = smf + 16640;
    int b = blockIdx.x, t = threadIdx.x;
    {
        int part4 = t >> 6, n = t & 63;
        float s = 0.f;
        #pragma unroll
        for (int lb = 0; lb < 8; lb++)
            s += g_colsum_part[((size_t)b*64 + part4*8 + lb)*NSLOT + n];
        csp[part4*64 + n] = s;
    }
    __syncthreads();
    if (t < 64) {
        float tot = csp[t] + csp[64+t] + csp[128+t] + csp[192+t];
        g_colsum[b*NSLOT + t] = tot;
        csin[t] = 1.0f / tot;
    }
    __syncthreads();
    for (int n = 0; n < NSLOT; n++) {
        float s = 0.f;
        #pragma unroll
        for (int p = 0; p < 8; p++)
            s += g_accpart[((size_t)((p*BATCH + b)*NSLOT) + n)*DIM + t];
        size_t idx = ((size_t)(b*NSLOT) + n)*DIM + t;
        float val = g_templates[idx] + s * csin[n];
        g_templates[idx] = val;
        tv[n*256 + t] = val;
    }
    __syncthreads();
    {
        int r = t >> 2, part = t & 3;
        const float* row = tv + r*256 + part*64;
        float s = 0.f, sq = 0.f;
        #pragma unroll
        for (int i = 0; i < 64; i += 4) {
            float4 v = *(const float4*)(row + i);
            s += v.x+v.y+v.z+v.w;
            sq += v.x*v.x + v.y*v.y + v.z*v.z + v.w*v.w;
        }
        s  += __shfl_xor_sync(0xffffffffu, s, 1);  s  += __shfl_xor_sync(0xffffffffu, s, 2);
        sq += __shfl_xor_sync(0xffffffffu, sq, 1); sq += __shfl_xor_sync(0xffffffffu, sq, 2);
        float mu = s * (1.0f/256.0f);
        float rs = rsqrtf(sq * (1.0f/256.0f) - mu*mu + 1e-5f);
        float* drow = g_tbuf + ((size_t)(b*NSLOT) + r)*DIM + part*64;
        #pragma unroll
        for (int i = 0; i < 64; i += 4) {
            float4 v = *(const float4*)(row + i);
            float4 gg = *(const float4*)(g + part*64 + i);
            float4 bv = *(const float4*)(bb + part*64 + i);
            float4 o;
            o.x = (v.x - mu)*rs*gg.x + bv.x;
            o.y = (v.y - mu)*rs*gg.y + bv.y;
            o.z = (v.z - mu)*rs*gg.z + bv.z;
            o.w = (v.w - mu)*rs*gg.w + bv.w;
            *(float4*)(drow + i) = o;
        }
    }
}

// ---------------- outputs ----------------
__global__ void out_templates_kernel(float* __restrict__ out) {
    int b = blockIdx.x, d = threadIdx.x;
    for (int n = 0; n < NSLOT; n++)
        out[((size_t)(b*DIM) + d)*NSLOT + n] = g_templates[((size_t)(b*NSLOT) + n)*DIM + d];
}

__global__ void out_attn_kernel(float* __restrict__ out) {
    int n = blockIdx.x, b = blockIdx.y, t = threadIdx.x;
    float inv = 1.0f / g_colsum[b*NSLOT + n];
    size_t base = (size_t)BATCH*DIM*NSLOT + ((size_t)(b*NSLOT + n))*LTOK;
    for (int k = 0; k < 16; k++) {
        int l = k*256 + t;
        out[base + l] = g_attn[((size_t)b*LTOK + l)*NSLOT + n] * inv;
    }
}

// ---------------- launch ----------------
extern "C" void kernel_launch(void* const* d_in, const int* in_sizes, int n_in,
                              void* d_out, int out_size) {
    const float* x       = (const float*)d_in[0];
    const float* tinit   = (const float*)d_in[1];
    const float* conv_w  = (const float*)d_in[2];
    const float* conv_b  = (const float*)d_in[3];
    const float* Wq      = (const float*)d_in[4];
    const float* Wk      = (const float*)d_in[5];
    const float* Wv      = (const float*)d_in[6];
    const float* ln_in_g = (const float*)d_in[7];
    const float* ln_in_b = (const float*)d_in[8];
    const float* ln_t_g  = (const float*)d_in[9];
    const float* ln_t_b  = (const float*)d_in[10];
    const float* ln_m_g  = (const float*)d_in[11];
    const float* ln_m_b  = (const float*)d_in[12];
    const float* W1      = (const float*)d_in[13];
    const float* b1      = (const float*)d_in[14];
    const float* W2      = (const float*)d_in[15];
    const float* b2      = (const float*)d_in[16];
    float* out = (float*)d_out;

    cudaFuncSetAttribute(conv_mma_kernel, cudaFuncAttributeMaxDynamicSharedMemorySize, CMM_SMEM);
    cudaFuncSetAttribute(kv_mma_kernel, cudaFuncAttributeMaxDynamicSharedMemorySize, CMM_SMEM);
    cudaFuncSetAttribute(attn_mma_kernel, cudaFuncAttributeMaxDynamicSharedMemorySize, ATT_SMEM);
    cudaFuncSetAttribute(gemm_c_mma_kernel, cudaFuncAttributeMaxDynamicSharedMemorySize, GC_SMEM);
    cudaFuncSetAttribute(gemm_q_kernel, cudaFuncAttributeMaxDynamicSharedMemorySize, (16384+1024)*4);
    cudaFuncSetAttribute(gemm_h_kernel, cudaFuncAttributeMaxDynamicSharedMemorySize, (16384+1024)*4);
    cudaFuncSetAttribute(gemm_o_kernel, cudaFuncAttributeMaxDynamicSharedMemorySize, GEMMO_SMEM_FLOATS*4);
    cudaFuncSetAttribute(finalize_kernel, cudaFuncAttributeMaxDynamicSharedMemorySize, FIN_SMEM_FLOATS*4);

    templates_init_kernel<<<8, 256>>>(tinit);
    xsplit_kernel<<<8*33*33, 256>>>(x);
    cwsplit_kernel<<<3456, 256>>>(conv_w);
    kvsplit_kernel<<<512, 256>>>(Wk, Wv);
    conv_mma_kernel<<<256, 512, CMM_SMEM>>>(conv_b, ln_in_g, ln_in_b);
    kv_mma_kernel<<<512, 512, CMM_SMEM>>>();

    for (int it = 0; it < 6; it++) {
        gemm_q_kernel<<<dim3(4, 8), 256, (16384+1024)*4>>>(Wq, ln_t_g, ln_t_b);
        attn_mma_kernel<<<dim3(32, 8), 256, ATT_SMEM>>>();
        gemm_c_mma_kernel<<<dim3(2, 8, 8), 256, GC_SMEM>>>();
        finalize_kernel<<<8, 256, FIN_SMEM_FLOATS*4>>>(ln_m_g, ln_m_b);
        gemm_h_kernel<<<dim3(8, 8), 256, (16384+1024)*4>>>(W1, b1);
        gemm_o_kernel<<<dim3(4, 8), 256, GEMMO_SMEM_FLOATS*4>>>(W2, b2);
    }

    out_templates_kernel<<<8, 256>>>(out);
    out_attn_kernel<<<dim3(64, 8), 256>>>(out);
}

// round 13
// speedup vs baseline: 1.5453x; 1.1012x over previous
#include <cuda_runtime.h>
#include <cuda_bf16.h>
#include <stdint.h>
#include <math.h>

#define BATCH 8
#define DIM   256
#define NSLOT 64
#define LTOK  4096

typedef unsigned long long u64;

__device__ __forceinline__ u64 PK1(float v) {
    u64 r; asm("mov.b64 %0, {%1,%1};" : "=l"(r) : "f"(v)); return r;
}
__device__ __forceinline__ void FMA2(u64& d, u64 a, u64 b) {
    asm("fma.rn.f32x2 %0, %1, %2, %0;" : "+l"(d) : "l"(a), "l"(b));
}
__device__ __forceinline__ float2 UPK(u64 v) {
    float2 f; asm("mov.b64 {%0,%1}, %2;" : "=f"(f.x), "=f"(f.y) : "l"(v)); return f;
}

// ---------------- scratch ----------------
__device__ float g_templates[BATCH*NSLOT*DIM];
__device__ float g_tbuf[BATCH*NSLOT*DIM];
__device__ float g_attn[BATCH*LTOK*NSLOT];
__device__ float g_colsum_part[BATCH*64*NSLOT];
__device__ float g_colsum[BATCH*NSLOT];
__device__ float g_accpart[32*BATCH*NSLOT*DIM];
__device__ float g_hidden[BATCH*NSLOT*512];
// bf16 split operands
__device__ __nv_bfloat16 g_xh[36799488];
__device__ __nv_bfloat16 g_xl[36799488];
__device__ __nv_bfloat16 g_cwh[27*32768];
__device__ __nv_bfloat16 g_cwl[27*32768];
__device__ __nv_bfloat16 g_kvh[256*512];
__device__ __nv_bfloat16 g_kvl[256*512];
__device__ __nv_bfloat16 g_toksh[32768*256];
__device__ __nv_bfloat16 g_toksl[32768*256];
__device__ __nv_bfloat16 g_kh[32768*256];
__device__ __nv_bfloat16 g_kl[32768*256];
__device__ __nv_bfloat16 g_vh[32768*256];
__device__ __nv_bfloat16 g_vl[32768*256];
__device__ __nv_bfloat16 g_qh[BATCH*NSLOT*DIM];
__device__ __nv_bfloat16 g_ql[BATCH*NSLOT*DIM];

__device__ __forceinline__ float gelu_exact(float v) {
    return 0.5f * v * (1.0f + erff(v * 0.70710678118654752f));
}

// ========== mma.sync helpers ==========
__device__ __forceinline__ uint32_t smem_u32(const void* p) {
    uint32_t a;
    asm("{ .reg .u64 t; cvta.to.shared.u64 t, %1; cvt.u32.u64 %0, t; }" : "=r"(a) : "l"(p));
    return a;
}
__device__ __forceinline__ void ldsm_x4(uint32_t* r, uint32_t addr) {
    asm volatile("ldmatrix.sync.aligned.m8n8.x4.shared.b16 {%0,%1,%2,%3}, [%4];"
        : "=r"(r[0]), "=r"(r[1]), "=r"(r[2]), "=r"(r[3]) : "r"(addr));
}
__device__ __forceinline__ void ldsm_x4_t(uint32_t* r, uint32_t addr) {
    asm volatile("ldmatrix.sync.aligned.m8n8.x4.trans.shared.b16 {%0,%1,%2,%3}, [%4];"
        : "=r"(r[0]), "=r"(r[1]), "=r"(r[2]), "=r"(r[3]) : "r"(addr));
}
__device__ __forceinline__ void mma_bf16(float* d, const uint32_t* a, const uint32_t* b) {
    asm volatile("mma.sync.aligned.m16n8k16.row.col.f32.bf16.bf16.f32 "
        "{%0,%1,%2,%3}, {%4,%5,%6,%7}, {%8,%9}, {%0,%1,%2,%3};"
        : "+f"(d[0]), "+f"(d[1]), "+f"(d[2]), "+f"(d[3])
        : "r"(a[0]), "r"(a[1]), "r"(a[2]), "r"(a[3]), "r"(b[0]), "r"(b[1]));
}
__device__ __forceinline__ void bsplit(float v0, float v1, __nv_bfloat162& hh, __nv_bfloat162& ll) {
    __nv_bfloat16 h0 = __float2bfloat16(v0), h1 = __float2bfloat16(v1);
    hh.x = h0; hh.y = h1;
    ll.x = __float2bfloat16(v0 - __bfloat162float(h0));
    ll.y = __float2bfloat16(v1 - __bfloat162float(h1));
}
__device__ __forceinline__ void cpa16(uint32_t dst, const void* src) {
    asm volatile("cp.async.cg.shared.global [%0], [%1], 16;" :: "r"(dst), "l"(src) : "memory");
}
#define CP_COMMIT asm volatile("cp.async.commit_group;" ::: "memory")
#define CP_WAIT0  asm volatile("cp.async.wait_group 0;" ::: "memory")

// 128x256 += A(128x128, pitch 272B) x B(128k x 256n, pitch 528B); 3-term bf16 split.
__device__ __forceinline__ void mma_chunk(
    uint32_t sAh, uint32_t sAl, uint32_t sBh, uint32_t sBl,
    float d[2][8][4], int wm, int wn, int lane)
{
    uint32_t aoff0 = (uint32_t)((wm*32 + (lane & 15))*272 + (lane >> 4)*16);
    uint32_t boff0 = (uint32_t)((lane & 15)*528 + (wn*64 + (lane >> 4)*8)*2);
    #pragma unroll
    for (int kk = 0; kk < 8; kk++) {
        uint32_t ah[8], al[8], bb[16];
        uint32_t ao = aoff0 + kk*32;
        ldsm_x4(ah,     sAh + ao);
        ldsm_x4(ah + 4, sAh + ao + 4352);
        ldsm_x4(al,     sAl + ao);
        ldsm_x4(al + 4, sAl + ao + 4352);
        uint32_t bo = boff0 + kk*8448;
        #pragma unroll
        for (int jj = 0; jj < 4; jj++) ldsm_x4_t(bb + jj*4, sBh + bo + jj*32);
        #pragma unroll
        for (int mi = 0; mi < 2; mi++) {
            #pragma unroll
            for (int j = 0; j < 8; j++) {
                const uint32_t* bf = bb + (j >> 1)*4 + (j & 1)*2;
                mma_bf16(d[mi][j], mi ? ah + 4 : ah, bf);
                mma_bf16(d[mi][j], mi ? al + 4 : al, bf);
            }
        }
        #pragma unroll
        for (int jj = 0; jj < 4; jj++) ldsm_x4_t(bb + jj*4, sBl + bo + jj*32);
        #pragma unroll
        for (int mi = 0; mi < 2; mi++) {
            #pragma unroll
            for (int j = 0; j < 8; j++) {
                const uint32_t* bf = bb + (j >> 1)*4 + (j & 1)*2;
                mma_bf16(d[mi][j], mi ? ah + 4 : ah, bf);
            }
        }
    }
}

// dual-term pass: d += Ah*B + Al*B
__device__ __forceinline__ void mma_dual(
    uint32_t sAh, uint32_t sAl, uint32_t sB,
    float d[2][8][4], int wm, int wn, int lane)
{
    uint32_t aoff0 = (uint32_t)((wm*32 + (lane & 15))*272 + (lane >> 4)*16);
    uint32_t boff0 = (uint32_t)((lane & 15)*528 + (wn*64 + (lane >> 4)*8)*2);
    #pragma unroll
    for (int kk = 0; kk < 8; kk++) {
        uint32_t ah[8], al[8], bb[16];
        uint32_t ao = aoff0 + kk*32;
        ldsm_x4(ah,     sAh + ao);
        ldsm_x4(ah + 4, sAh + ao + 4352);
        ldsm_x4(al,     sAl + ao);
        ldsm_x4(al + 4, sAl + ao + 4352);
        uint32_t bo = boff0 + kk*8448;
        #pragma unroll
        for (int jj = 0; jj < 4; jj++) ldsm_x4_t(bb + jj*4, sB + bo + jj*32);
        #pragma unroll
        for (int mi = 0; mi < 2; mi++) {
            #pragma unroll
            for (int j = 0; j < 8; j++) {
                const uint32_t* bf = bb + (j >> 1)*4 + (j & 1)*2;
                mma_bf16(d[mi][j], mi ? ah + 4 : ah, bf);
                mma_bf16(d[mi][j], mi ? al + 4 : al, bf);
            }
        }
    }
}

// single-term pass: d += Ah*B
__device__ __forceinline__ void mma_single(
    uint32_t sAh, uint32_t sB,
    float d[2][8][4], int wm, int wn, int lane)
{
    uint32_t aoff0 = (uint32_t)((wm*32 + (lane & 15))*272 + (lane >> 4)*16);
    uint32_t boff0 = (uint32_t)((lane & 15)*528 + (wn*64 + (lane >> 4)*8)*2);
    #pragma unroll
    for (int kk = 0; kk < 8; kk++) {
        uint32_t ah[8], bb[16];
        uint32_t ao = aoff0 + kk*32;
        ldsm_x4(ah,     sAh + ao);
        ldsm_x4(ah + 4, sAh + ao + 4352);
        uint32_t bo = boff0 + kk*8448;
        #pragma unroll
        for (int jj = 0; jj < 4; jj++) ldsm_x4_t(bb + jj*4, sB + bo + jj*32);
        #pragma unroll
        for (int mi = 0; mi < 2; mi++) {
            #pragma unroll
            for (int j = 0; j < 8; j++) {
                const uint32_t* bf = bb + (j >> 1)*4 + (j & 1)*2;
                mma_bf16(d[mi][j], mi ? ah + 4 : ah, bf);
            }
        }
    }
}

// ---------------- prep kernels ----------------
__global__ void templates_init_kernel(const float* __restrict__ tinit) {
    int b = blockIdx.x, t = threadIdx.x;
    for (int n = 0; n < NSLOT; n++)
        g_templates[(b*NSLOT + n)*DIM + t] = tinit[n*DIM + t];
}

__global__ __launch_bounds__(256) void xsplit_kernel(const float* __restrict__ x) {
    __shared__ float st[128*33];
    int bid = blockIdx.x; int b = bid / 1089; int rem = bid % 1089; int d = rem / 33, h = rem % 33;
    int t = threadIdx.x, warp = t >> 5, lane = t & 31;
    const float* xb = x + ((((size_t)b*128)*33 + d)*33 + h)*33;
    for (int c = warp; c < 128; c += 8) {
        const float* src = xb + (size_t)c*35937;
        st[c*33 + lane] = src[lane];
        if (lane == 0) st[c*33 + 32] = src[32];
    }
    __syncthreads();
    size_t ob = ((((size_t)b*33 + d)*33 + h)*33)*128;
    for (int i = t; i < 33*128; i += 256) {
        int w = i >> 7, c = i & 127;
        float v = st[c*33 + w];
        __nv_bfloat16 hi = __float2bfloat16(v);
        g_xh[ob + (size_t)w*128 + c] = hi;
        g_xl[ob + (size_t)w*128 + c] = __float2bfloat16(v - __bfloat162float(hi));
    }
}

__global__ void cwsplit_kernel(const float* __restrict__ cw) {
    int idx = blockIdx.x*256 + threadIdx.x;
    int tap = idx >> 15, r = idx & 32767;
    int k = r >> 8, n = r & 255;
    float v = cw[(size_t)n*3456 + k*27 + tap];
    __nv_bfloat16 hi = __float2bfloat16(v);
    g_cwh[idx] = hi;
    g_cwl[idx] = __float2bfloat16(v - __bfloat162float(hi));
}

__global__ void kvsplit_kernel(const float* __restrict__ Wk, const float* __restrict__ Wv) {
    int idx = blockIdx.x*256 + threadIdx.x;
    int k = idx >> 9, c512 = idx & 511;
    int mat = c512 >> 8, col = c512 & 255;
    const float* W = mat ? Wv : Wk;
    float v = W[(size_t)k*256 + col];
    __nv_bfloat16 hi = __float2bfloat16(v);
    g_kvh[idx] = hi;
    g_kvl[idx] = __float2bfloat16(v - __bfloat162float(hi));
}

// ---------------- conv (implicit GEMM, cp.async-pipelined B) + bias + ReLU + LN ----------------
#define CMM_SMEM 204800
__global__ __launch_bounds__(512, 1) void conv_mma_kernel(
    const float* __restrict__ convb, const float* __restrict__ lng, const float* __restrict__ lnb)
{
    extern __shared__ char sm[];
    uint32_t sb = smem_u32(sm);
    const uint32_t oAh = 0, oAl = 34816, oB0 = 69632, oB1 = 137216;
    int t = threadIdx.x, lane = t & 31, wid = t >> 5;
    int wm = wid >> 2, wn = wid & 3;
    int bx = blockIdx.x; int b = bx >> 5, xd = (bx >> 1) & 15, half = bx & 1;

    float d[2][8][4];
    #pragma unroll
    for (int i = 0; i < 2; i++)
        #pragma unroll
        for (int j = 0; j < 8; j++)
            #pragma unroll
            for (int c = 0; c < 4; c++) d[i][j][c] = 0.f;

    int m = t >> 2, q = t & 3;
    int xhl = m >> 4, xw = m & 15;

    {
        const uint4* s1 = (const uint4*)(g_cwh);
        #pragma unroll
        for (int it = 0; it < 8; it++) {
            int i = t + it*512;
            cpa16(sb + oB0 + (uint32_t)((i >> 5)*528 + (i & 31)*16), s1 + i);
        }
        CP_COMMIT;
    }

    for (int tap = 0; tap < 27; tap++) {
        int kd = tap/9, r9 = tap%9, kh = r9/3, kw = r9%3;
        {
            size_t xi = ((((size_t)(b*33) + 2*xd + kd)*33 + 2*(half*8 + xhl) + kh)*33 + 2*xw + kw)*128 + q*32;
            const uint4* shi = (const uint4*)(g_xh + xi);
            const uint4* slo = (const uint4*)(g_xl + xi);
            char* dh = sm + oAh + m*272 + q*64;
            char* dl = sm + oAl + m*272 + q*64;
            #pragma unroll
            for (int j = 0; j < 4; j++) {
                *(uint4*)(dh + j*16) = shi[j];
                *(uint4*)(dl + j*16) = slo[j];
            }
        }
        CP_WAIT0;
        __syncthreads();
        {
            const uint4* s2 = (const uint4*)(g_cwl + tap*32768);
            #pragma unroll
            for (int it = 0; it < 8; it++) {
                int i = t + it*512;
                cpa16(sb + oB1 + (uint32_t)((i >> 5)*528 + (i & 31)*16), s2 + i);
            }
            CP_COMMIT;
        }
        mma_dual(sb + oAh, sb + oAl, sb + oB0, d, wm, wn, lane);
        CP_WAIT0;
        __syncthreads();
        if (tap < 26) {
            const uint4* s1 = (const uint4*)(g_cwh + (tap+1)*32768);
            #pragma unroll
            for (int it = 0; it < 8; it++) {
                int i = t + it*512;
                cpa16(sb + oB0 + (uint32_t)((i >> 5)*528 + (i & 31)*16), s1 + i);
            }
            CP_COMMIT;
        }
        mma_single(sb + oAh, sb + oB1, d, wm, wn, lane);
        __syncthreads();
    }

    float* stg = (float*)sm;
    {
        int r0 = wm*32 + (lane >> 2);
        int c0 = wn*64 + (lane & 3)*2;
        #pragma unroll
        for (int mi = 0; mi < 2; mi++)
            #pragma unroll
            for (int j = 0; j < 8; j++) {
                int rr = r0 + mi*16, cc = c0 + j*8;
                *(float2*)(stg + (size_t)rr*264 + cc)     = make_float2(d[mi][j][0], d[mi][j][1]);
                *(float2*)(stg + (size_t)(rr+8)*264 + cc) = make_float2(d[mi][j][2], d[mi][j][3]);
            }
    }
    __syncthreads();

    {
        int tok = t >> 2, q2 = t & 3;
        const float* src = stg + (size_t)tok*264 + q2*64;
        float z[64];
        float s = 0.f, sq = 0.f;
        #pragma unroll
        for (int i = 0; i < 64; i++) {
            float v = fmaxf(src[i] + convb[q2*64 + i], 0.f);
            z[i] = v; s += v; sq += v*v;
        }
        s  += __shfl_xor_sync(0xffffffffu, s, 1);  s  += __shfl_xor_sync(0xffffffffu, s, 2);
        sq += __shfl_xor_sync(0xffffffffu, sq, 1); sq += __shfl_xor_sync(0xffffffffu, sq, 2);
        float mu = s * (1.f/256.f);
        float rs = rsqrtf(sq * (1.f/256.f) - mu*mu + 1e-5f);
        int l = (xd*16 + half*8 + (tok >> 4))*16 + (tok & 15);
        size_t tg = ((size_t)b*4096 + l)*256 + q2*64;
        #pragma unroll
        for (int i = 0; i < 64; i += 2) {
            int ch = q2*64 + i;
            float v0 = (z[i]   - mu)*rs*lng[ch]   + lnb[ch];
            float v1 = (z[i+1] - mu)*rs*lng[ch+1] + lnb[ch+1];
            __nv_bfloat162 hh, ll;
            bsplit(v0, v1, hh, ll);
            *(__nv_bfloat162*)(g_toksh + tg + i) = hh;
            *(__nv_bfloat162*)(g_toksl + tg + i) = ll;
        }
    }
}

// ---------------- K/V projection via mma.sync -> bf16 split outputs ----------------
__global__ __launch_bounds__(512, 1) void kv_mma_kernel() {
    extern __shared__ char sm[];
    uint32_t sb = smem_u32(sm);
    const uint32_t oAh = 0, oAl = 34816, oBh = 69632, oBl = 137216;
    int t = threadIdx.x, lane = t & 31, wid = t >> 5;
    int wm = wid >> 2, wn = wid & 3;
    int nhalf = blockIdx.x & 1, chunk = blockIdx.x >> 1;

    float d[2][8][4];
    #pragma unroll
    for (int i = 0; i < 2; i++)
        #pragma unroll
        for (int j = 0; j < 8; j++)
            #pragma unroll
            for (int c = 0; c < 4; c++) d[i][j][c] = 0.f;

    int m = t >> 2, q = t & 3;
    for (int kc = 0; kc < 2; kc++) {
        {
            size_t ti = ((size_t)(chunk*128 + m))*256 + kc*128 + q*32;
            const uint4* shi = (const uint4*)(g_toksh + ti);
            const uint4* slo = (const uint4*)(g_toksl + ti);
            char* dh = sm + oAh + m*272 + q*64;
            char* dl = sm + oAl + m*272 + q*64;
            #pragma unroll
            for (int j = 0; j < 4; j++) {
                *(uint4*)(dh + j*16) = shi[j];
                *(uint4*)(dl + j*16) = slo[j];
            }
        }
        {
            #pragma unroll
            for (int it = 0; it < 8; it++) {
                int i = t + it*512;
                int row = i >> 5, seg = i & 31;
                size_t off = (size_t)(kc*128 + row)*512 + nhalf*256 + seg*8;
                *(uint4*)(sm + oBh + row*528 + seg*16) = *(const uint4*)(g_kvh + off);
                *(uint4*)(sm + oBl + row*528 + seg*16) = *(const uint4*)(g_kvl + off);
            }
        }
        __syncthreads();
        mma_chunk(sb + oAh, sb + oAl, sb + oBh, sb + oBl, d, wm, wn, lane);
        __syncthreads();
    }

    __nv_bfloat16* dh = nhalf ? g_vh : g_kh;
    __nv_bfloat16* dl = nhalf ? g_vl : g_kl;
    int r0 = wm*32 + (lane >> 2);
    int c0 = wn*64 + (lane & 3)*2;
    #pragma unroll
    for (int mi = 0; mi < 2; mi++)
        #pragma unroll
        for (int j = 0; j < 8; j++) {
            int rr = r0 + mi*16, cc = c0 + j*8;
            size_t tok = (size_t)chunk*128 + rr;
            __nv_bfloat162 hh, ll;
            bsplit(d[mi][j][0], d[mi][j][1], hh, ll);
            *(__nv_bfloat162*)(dh + tok*256 + cc) = hh;
            *(__nv_bfloat162*)(dl + tok*256 + cc) = ll;
            bsplit(d[mi][j][2], d[mi][j][3], hh, ll);
            *(__nv_bfloat162*)(dh + (tok+8)*256 + cc) = hh;
            *(__nv_bfloat162*)(dl + (tok+8)*256 + cc) = ll;
        }
}

// ---------------- fused LN_t + q-GEMM (scalar, proven) -> bf16 split q ----------------
__global__ __launch_bounds__(256) void gemm_q_kernel(
    const float* __restrict__ Wq, const float* __restrict__ lng, const float* __restrict__ lnb)
{
    extern __shared__ float smf[];
    float* Af = smf; float* Bs = smf + 16384;
    int b = blockIdx.y; int nc = blockIdx.x * 64;
    int t = threadIdx.x;
    {
        int r = t >> 2, part = t & 3;
        const float* row = g_templates + ((size_t)(b*NSLOT) + r)*DIM + part*64;
        float s = 0.f, sq = 0.f;
        #pragma unroll
        for (int i = 0; i < 64; i += 4) {
            float4 v = *(const float4*)(row + i);
            s += v.x+v.y+v.z+v.w;
            sq += v.x*v.x + v.y*v.y + v.z*v.z + v.w*v.w;
        }
        s  += __shfl_xor_sync(0xffffffffu, s, 1);  s  += __shfl_xor_sync(0xffffffffu, s, 2);
        sq += __shfl_xor_sync(0xffffffffu, sq, 1); sq += __shfl_xor_sync(0xffffffffu, sq, 2);
        float mu = s * (1.0f/256.0f);
        float rs = rsqrtf(sq * (1.0f/256.0f) - mu*mu + 1e-5f);
        #pragma unroll
        for (int i = 0; i < 64; i += 4) {
            float4 v = *(const float4*)(row + i);
            float4 gg = *(const float4*)(lng + part*64 + i);
            float4 bv = *(const float4*)(lnb + part*64 + i);
            Af[(part*64+i+0)*64 + r] = (v.x - mu)*rs*gg.x + bv.x;
            Af[(part*64+i+1)*64 + r] = (v.y - mu)*rs*gg.y + bv.y;
            Af[(part*64+i+2)*64 + r] = (v.z - mu)*rs*gg.z + bv.z;
            Af[(part*64+i+3)*64 + r] = (v.w - mu)*rs*gg.w + bv.w;
        }
    }
    __syncthreads();
    int tm = t >> 4, tn = t & 15;
    u64 acc[4][2] = {};
    int kk0 = t >> 4, n4 = (t & 15)*4;
    for (int k0 = 0; k0 < 256; k0 += 16) {
        *(float4*)(Bs + kk0*64 + n4) = *(const float4*)(Wq + (size_t)(k0+kk0)*256 + nc + n4);
        __syncthreads();
        #pragma unroll
        for (int kk = 0; kk < 16; kk++) {
            ulonglong2 a2 = *(ulonglong2*)(Af + (k0+kk)*64 + tm*4);
            float4 bb = *(float4*)(Bs + kk*64 + tn*4);
            u64 q0 = PK1(bb.x), q1 = PK1(bb.y), q2 = PK1(bb.z), q3 = PK1(bb.w);
            FMA2(acc[0][0], a2.x, q0); FMA2(acc[0][1], a2.y, q0);
            FMA2(acc[1][0], a2.x, q1); FMA2(acc[1][1], a2.y, q1);
            FMA2(acc[2][0], a2.x, q2); FMA2(acc[2][1], a2.y, q2);
            FMA2(acc[3][0], a2.x, q3); FMA2(acc[3][1], a2.y, q3);
        }
        __syncthreads();
    }
    const float scale = 0.0625f;
    #pragma unroll
    for (int p = 0; p < 2; p++) {
        float2 f0 = UPK(acc[0][p]), f1 = UPK(acc[1][p]), f2 = UPK(acc[2][p]), f3 = UPK(acc[3][p]);
        int mm = tm*4 + p*2;
        size_t o0 = ((size_t)(b*NSLOT) + mm)*DIM + nc + tn*4;
        __nv_bfloat162 hh, ll;
        bsplit(f0.x*scale, f1.x*scale, hh, ll);
        *(__nv_bfloat162*)(g_qh + o0) = hh; *(__nv_bfloat162*)(g_ql + o0) = ll;
        bsplit(f2.x*scale, f3.x*scale, hh, ll);
        *(__nv_bfloat162*)(g_qh + o0 + 2) = hh; *(__nv_bfloat162*)(g_ql + o0 + 2) = ll;
        bsplit(f0.y*scale, f1.y*scale, hh, ll);
        *(__nv_bfloat162*)(g_qh + o0 + DIM) = hh; *(__nv_bfloat162*)(g_ql + o0 + DIM) = ll;
        bsplit(f2.y*scale, f3.y*scale, hh, ll);
        *(__nv_bfloat162*)(g_qh + o0 + DIM + 2) = hh; *(__nv_bfloat162*)(g_ql + o0 + DIM + 2) = ll;
    }
}

// ---------------- FUSED attn logits + softmax + colsum + attn^T@v ----------------
// grid (32 lb, 8 b), block 256.
// smem phase1: Kh 0(34816), Kl 34816, Qh 69632(17408), Ql 87040  [inside V region]
// persistent:  stg 135168(34816 fp32 128x68), ath 169984(18432 128x144), atl 188416(18432)
// phase2:      Vh 0(67584 128x528), Vl 67584(67584)
#define AGC_SMEM 206848
__global__ __launch_bounds__(256) void attn_gc_kernel(int write_attn) {
    extern __shared__ char sm[];
    uint32_t sb = smem_u32(sm);
    const uint32_t oKh = 0, oKl = 34816, oQh = 69632, oQl = 87040;
    const uint32_t oStg = 135168, oAth = 169984, oAtl = 188416;
    const uint32_t oVh = 0, oVl = 67584;
    int t = threadIdx.x, lane = t & 31, wid = t >> 5;
    int lb = blockIdx.x, b = blockIdx.y;

    // ---- phase 1: attn logits (verbatim attn_mma) ----
    int wm = wid >> 1, wn = wid & 1;
    float d[2][4][4];
    #pragma unroll
    for (int i = 0; i < 2; i++)
        #pragma unroll
        for (int j = 0; j < 4; j++)
            #pragma unroll
            for (int c = 0; c < 4; c++) d[i][j][c] = 0.f;

    for (int kc = 0; kc < 2; kc++) {
        {
            int row = t >> 1, half = t & 1;
            size_t ti = ((size_t)(b*4096) + lb*128 + row)*256 + kc*128 + half*64;
            const uint4* shi = (const uint4*)(g_kh + ti);
            const uint4* slo = (const uint4*)(g_kl + ti);
            char* dh = sm + oKh + row*272 + half*128;
            char* dl = sm + oKl + row*272 + half*128;
            #pragma unroll
            for (int j = 0; j < 8; j++) {
                *(uint4*)(dh + j*16) = shi[j];
                *(uint4*)(dl + j*16) = slo[j];
            }
        }
        {
            int row = t >> 2, q4 = t & 3;
            size_t ti = ((size_t)(b*NSLOT) + row)*256 + kc*128 + q4*32;
            const uint4* shi = (const uint4*)(g_qh + ti);
            const uint4* slo = (const uint4*)(g_ql + ti);
            char* dh = sm + oQh + row*272 + q4*64;
            char* dl = sm + oQl + row*272 + q4*64;
            #pragma unroll
            for (int j = 0; j < 4; j++) {
                *(uint4*)(dh + j*16) = shi[j];
                *(uint4*)(dl + j*16) = slo[j];
            }
        }
        __syncthreads();
        uint32_t aoff0 = (uint32_t)((wm*32 + (lane & 15))*272 + (lane >> 4)*16);
        uint32_t qoff0 = (uint32_t)(((lane >> 4)*8 + (lane & 7) + wn*32)*272 + ((lane >> 3) & 1)*16);
        #pragma unroll
        for (int kk = 0; kk < 8; kk++) {
            uint32_t ah[8], al[8], qh8[8], ql8[8];
            uint32_t ao = aoff0 + kk*32;
            ldsm_x4(ah,     sb + oKh + ao);
            ldsm_x4(ah + 4, sb + oKh + ao + 16*272);
            ldsm_x4(al,     sb + oKl + ao);
            ldsm_x4(al + 4, sb + oKl + ao + 16*272);
            uint32_t qo = qoff0 + kk*32;
            ldsm_x4(qh8,     sb + oQh + qo);
            ldsm_x4(qh8 + 4, sb + oQh + qo + 16*272);
            ldsm_x4(ql8,     sb + oQl + qo);
            ldsm_x4(ql8 + 4, sb + oQl + qo + 16*272);
            #pragma unroll
            for (int mi = 0; mi < 2; mi++) {
                #pragma unroll
                for (int j = 0; j < 4; j++) {
                    const uint32_t* bh = qh8 + (j >> 1)*4 + (j & 1)*2;
                    const uint32_t* bl = ql8 + (j >> 1)*4 + (j & 1)*2;
                    const uint32_t* am = mi ? ah + 4 : ah;
                    const uint32_t* aml = mi ? al + 4 : al;
                    mma_bf16(d[mi][j], am, bh);
                    mma_bf16(d[mi][j], am, bl);
                    mma_bf16(d[mi][j], aml, bh);
                }
            }
        }
        __syncthreads();
    }

    // stage logits fp32 [128][68] at oStg
    float* stg = (float*)(sm + oStg);
    {
        int r0 = wm*32 + (lane >> 2);
        int c0 = wn*32 + (lane & 3)*2;
        #pragma unroll
        for (int mi = 0; mi < 2; mi++)
            #pragma unroll
            for (int j = 0; j < 4; j++) {
                int rr = r0 + mi*16, cc = c0 + j*8;
                *(float2*)(stg + rr*68 + cc)     = make_float2(d[mi][j][0], d[mi][j][1]);
                *(float2*)(stg + (rr+8)*68 + cc) = make_float2(d[mi][j][2], d[mi][j][3]);
            }
    }
    __syncthreads();

    // softmax per row; write at splits into smem (pitch 144), optional g_attn
    {
        int row = t >> 1, half = t & 1;
        float* sr = stg + row*68 + half*32;
        float a[32];
        float mx = -3.4e38f;
        #pragma unroll
        for (int i = 0; i < 32; i++) { a[i] = sr[i]; mx = fmaxf(mx, a[i]); }
        mx = fmaxf(mx, __shfl_xor_sync(0xffffffffu, mx, 1));
        float s = 0.f;
        #pragma unroll
        for (int i = 0; i < 32; i++) { a[i] = expf(a[i] - mx); s += a[i]; }
        s += __shfl_xor_sync(0xffffffffu, s, 1);
        float inv = 1.0f / s;
        #pragma unroll
        for (int i = 0; i < 32; i++) { a[i] = a[i]*inv + 1e-8f; sr[i] = a[i]; }
        if (write_attn) {
            size_t gi = ((size_t)(b*4096) + lb*128 + row)*64 + half*32;
            #pragma unroll
            for (int i = 0; i < 32; i += 4)
                *(float4*)(g_attn + gi + i) = make_float4(a[i], a[i+1], a[i+2], a[i+3]);
        }
        char* dst_h = sm + oAth + row*144 + half*64;
        char* dst_l = sm + oAtl + row*144 + half*64;
        #pragma unroll
        for (int i = 0; i < 32; i += 2) {
            __nv_bfloat162 hh, ll;
            bsplit(a[i], a[i+1], hh, ll);
            *(__nv_bfloat162*)(dst_h + i*2) = hh;
            *(__nv_bfloat162*)(dst_l + i*2) = ll;
        }
    }
    __syncthreads();
    if (t < 64) {
        float s = 0.f;
        for (int r = 0; r < 128; r++) s += stg[r*68 + t];
        g_colsum_part[((size_t)b*64 + lb)*NSLOT + t] = s;
    }

    // ---- phase 2: load V tile (128 l x 256 d, hi/lo) ----
    {
        int row = t >> 1, half = t & 1;
        size_t ti = ((size_t)(b*4096) + lb*128 + row)*256 + half*128;
        const uint4* shi = (const uint4*)(g_vh + ti);
        const uint4* slo = (const uint4*)(g_vl + ti);
        char* dst_h = sm + oVh + row*528 + half*256;
        char* dst_l = sm + oVl + row*528 + half*256;
        #pragma unroll
        for (int j = 0; j < 16; j++) {
            *(uint4*)(dst_h + j*16) = shi[j];
            *(uint4*)(dst_l + j*16) = slo[j];
        }
    }
    __syncthreads();

    // gemm_c: at^T (64 slots x 128 l) @ V (128 l x 256 d)
    int wm2 = wid & 1, wn2 = wid >> 1;  // wm2: 2 slot tiles of 32; wn2: 4 d tiles of 64
    float d2[2][8][4];
    #pragma unroll
    for (int i = 0; i < 2; i++)
        #pragma unroll
        for (int j = 0; j < 8; j++)
            #pragma unroll
            for (int c = 0; c < 4; c++) d2[i][j][c] = 0.f;
    {
        uint32_t aoff0 = (uint32_t)((((lane >> 4)*8 + (lane & 7)))*144 + ((lane >> 3) & 1)*16 + wm2*64);
        uint32_t boff0 = (uint32_t)((lane & 15)*528 + (wn2*64 + (lane >> 4)*8)*2);
        #pragma unroll
        for (int kk = 0; kk < 8; kk++) {
            uint32_t ah[8], al[8], bh8[16], bl8[16];
            uint32_t ao = aoff0 + kk*16*144;
            ldsm_x4_t(ah,     sb + oAth + ao);
            ldsm_x4_t(ah + 4, sb + oAth + ao + 32);
            ldsm_x4_t(al,     sb + oAtl + ao);
            ldsm_x4_t(al + 4, sb + oAtl + ao + 32);
            uint32_t bo = boff0 + kk*8448;
            #pragma unroll
            for (int jj = 0; jj < 4; jj++) ldsm_x4_t(bh8 + jj*4, sb + oVh + bo + jj*32);
            #pragma unroll
            for (int jj = 0; jj < 4; jj++) ldsm_x4_t(bl8 + jj*4, sb + oVl + bo + jj*32);
            #pragma unroll
            for (int mi = 0; mi < 2; mi++) {
                #pragma unroll
                for (int j = 0; j < 8; j++) {
                    const uint32_t* bfh = bh8 + (j >> 1)*4 + (j & 1)*2;
                    const uint32_t* bfl = bl8 + (j >> 1)*4 + (j & 1)*2;
                    const uint32_t* am = mi ? ah + 4 : ah;
                    const uint32_t* aml = mi ? al + 4 : al;
                    mma_bf16(d2[mi][j], am, bfh);
                    mma_bf16(d2[mi][j], am, bfl);
                    mma_bf16(d2[mi][j], aml, bfh);
                }
            }
        }
    }

    // write accpart partial [lb][b][slot][dim]
    int r0 = wm2*32 + (lane >> 2);
    int c0 = wn2*64 + (lane & 3)*2;
    float* C = g_accpart + ((size_t)((lb*BATCH + b)*NSLOT))*DIM;
    #pragma unroll
    for (int mi = 0; mi < 2; mi++)
        #pragma unroll
        for (int j = 0; j < 8; j++) {
            int slot = r0 + mi*16, cc = c0 + j*8;
            *(float2*)(C + (size_t)slot*DIM + cc)     = make_float2(d2[mi][j][0], d2[mi][j][1]);
            *(float2*)(C + (size_t)(slot+8)*DIM + cc) = make_float2(d2[mi][j][2], d2[mi][j][3]);
        }
}

// ---------------- colsum + template update + LN_m. grid (8 ng, 8 b) ----------------
__global__ __launch_bounds__(256) void finalize_kernel(const float* __restrict__ g,
                                                       const float* __restrict__ bb) {
    __shared__ float tv[8*256];
    __shared__ float csin_s[8];
    int ng = blockIdx.x, b = blockIdx.y, t = threadIdx.x;
    {
        int s = t >> 5, l = t & 31;
        int n = ng*8 + s;
        float v = g_colsum_part[((size_t)b*64 + l)*NSLOT + n];
        #pragma unroll
        for (int m = 16; m; m >>= 1) v += __shfl_xor_sync(0xffffffffu, v, m);
        if (l == 0) { csin_s[s] = 1.0f / v; g_colsum[b*NSLOT + n] = v; }
    }
    __syncthreads();
    #pragma unroll
    for (int s = 0; s < 8; s++) {
        int n = ng*8 + s;
        float acc = 0.f;
        #pragma unroll 8
        for (int p = 0; p < 32; p++)
            acc += g_accpart[((size_t)(p*BATCH + b)*NSLOT + n)*DIM + t];
        size_t idx = ((size_t)(b*NSLOT) + n)*DIM + t;
        float val = g_templates[idx] + acc * csin_s[s];
        g_templates[idx] = val;
        tv[s*256 + t] = val;
    }
    __syncthreads();
    {
        int w = t >> 5, l = t & 31;
        const float* row = tv + w*256;
        float s1 = 0.f, s2 = 0.f;
        #pragma unroll
        for (int i = l; i < 256; i += 32) { float v = row[i]; s1 += v; s2 += v*v; }
        #pragma unroll
        for (int m = 16; m; m >>= 1) {
            s1 += __shfl_xor_sync(0xffffffffu, s1, m);
            s2 += __shfl_xor_sync(0xffffffffu, s2, m);
        }
        float mu = s1 * (1.f/256.f);
        float rs = rsqrtf(s2 * (1.f/256.f) - mu*mu + 1e-5f);
        int n = ng*8 + w;
        float* drow = g_tbuf + ((size_t)(b*NSLOT) + n)*DIM;
        #pragma unroll
        for (int i = l; i < 256; i += 32)
            drow[i] = (row[i] - mu)*rs*g[i] + bb[i];
    }
}

// ---------------- MLP kernels (scalar, proven) ----------------
__global__ __launch_bounds__(256) void gemm_h_kernel(const float* __restrict__ W1,
                                                     const float* __restrict__ b1)
{
    extern __shared__ float smf[];
    float* Af = smf; float* Bs = smf + 16384;
    int b = blockIdx.y; int nc = blockIdx.x * 64;
    int t = threadIdx.x;
    {
        int r = t >> 2, part = t & 3;
        const float* row = g_tbuf + ((size_t)(b*NSLOT) + r)*DIM + part*64;
        #pragma unroll
        for (int i = 0; i < 64; i += 4) {
            float4 v = *(const float4*)(row + i);
            Af[(part*64+i+0)*64 + r] = v.x;
            Af[(part*64+i+1)*64 + r] = v.y;
            Af[(part*64+i+2)*64 + r] = v.z;
            Af[(part*64+i+3)*64 + r] = v.w;
        }
    }
    __syncthreads();
    int tm = t >> 4, tn = t & 15;
    u64 acc[4][2] = {};
    int kk0 = t >> 4, n4 = (t & 15)*4;
    for (int k0 = 0; k0 < 256; k0 += 16) {
        *(float4*)(Bs + kk0*64 + n4) = *(const float4*)(W1 + (size_t)(k0+kk0)*512 + nc + n4);
        __syncthreads();
        #pragma unroll
        for (int kk = 0; kk < 16; kk++) {
            ulonglong2 a2 = *(ulonglong2*)(Af + (k0+kk)*64 + tm*4);
            float4 bb = *(float4*)(Bs + kk*64 + tn*4);
            u64 q0 = PK1(bb.x), q1 = PK1(bb.y), q2 = PK1(bb.z), q3 = PK1(bb.w);
            FMA2(acc[0][0], a2.x, q0); FMA2(acc[0][1], a2.y, q0);
            FMA2(acc[1][0], a2.x, q1); FMA2(acc[1][1], a2.y, q1);
            FMA2(acc[2][0], a2.x, q2); FMA2(acc[2][1], a2.y, q2);
            FMA2(acc[3][0], a2.x, q3); FMA2(acc[3][1], a2.y, q3);
        }
        __syncthreads();
    }
    float4 bv = *(const float4*)(b1 + nc + tn*4);
    #pragma unroll
    for (int p = 0; p < 2; p++) {
        float2 f0 = UPK(acc[0][p]), f1 = UPK(acc[1][p]), f2 = UPK(acc[2][p]), f3 = UPK(acc[3][p]);
        float4 r0 = {gelu_exact(f0.x+bv.x), gelu_exact(f1.x+bv.y), gelu_exact(f2.x+bv.z), gelu_exact(f3.x+bv.w)};
        float4 r1 = {gelu_exact(f0.y+bv.x), gelu_exact(f1.y+bv.y), gelu_exact(f2.y+bv.z), gelu_exact(f3.y+bv.w)};
        int mm = tm*4 + p*2;
        *(float4*)(g_hidden + ((size_t)(b*NSLOT) + mm  )*512 + nc + tn*4) = r0;
        *(float4*)(g_hidden + ((size_t)(b*NSLOT) + mm+1)*512 + nc + tn*4) = r1;
    }
}

#define GEMMO_SMEM_FLOATS (32768 + 1024)
__global__ __launch_bounds__(256) void gemm_o_kernel(const float* __restrict__ W2,
                                                     const float* __restrict__ b2)
{
    extern __shared__ float smf[];
    float* Af = smf; float* Bs = smf + 32768;
    int b = blockIdx.y; int nc = blockIdx.x * 64;
    int t = threadIdx.x;
    {
        int r = t >> 2, part = t & 3;
        const float* row = g_hidden + ((size_t)(b*NSLOT) + r)*512 + part*128;
        #pragma unroll
        for (int i = 0; i < 128; i += 4) {
            float4 v = *(const float4*)(row + i);
            Af[(part*128+i+0)*64 + r] = v.x;
            Af[(part*128+i+1)*64 + r] = v.y;
            Af[(part*128+i+2)*64 + r] = v.z;
            Af[(part*128+i+3)*64 + r] = v.w;
        }
    }
    __syncthreads();
    int tm = t >> 4, tn = t & 15;
    u64 acc[4][2] = {};
    int kk0 = t >> 4, n4 = (t & 15)*4;
    for (int k0 = 0; k0 < 512; k0 += 16) {
        *(float4*)(Bs + kk0*64 + n4) = *(const float4*)(W2 + (size_t)(k0+kk0)*256 + nc + n4);
        __syncthreads();
        #pragma unroll
        for (int kk = 0; kk < 16; kk++) {
            ulonglong2 a2 = *(ulonglong2*)(Af + (k0+kk)*64 + tm*4);
            float4 bb = *(float4*)(Bs + kk*64 + tn*4);
            u64 q0 = PK1(bb.x), q1 = PK1(bb.y), q2 = PK1(bb.z), q3 = PK1(bb.w);
            FMA2(acc[0][0], a2.x, q0); FMA2(acc[0][1], a2.y, q0);
            FMA2(acc[1][0], a2.x, q1); FMA2(acc[1][1], a2.y, q1);
            FMA2(acc[2][0], a2.x, q2); FMA2(acc[2][1], a2.y, q2);
            FMA2(acc[3][0], a2.x, q3); FMA2(acc[3][1], a2.y, q3);
        }
        __syncthreads();
    }
    float4 bv = *(const float4*)(b2 + nc + tn*4);
    #pragma unroll
    for (int p = 0; p < 2; p++) {
        float2 f0 = UPK(acc[0][p]), f1 = UPK(acc[1][p]), f2 = UPK(acc[2][p]), f3 = UPK(acc[3][p]);
        int mm = tm*4 + p*2;
        float* C0 = g_templates + ((size_t)(b*NSLOT) + mm)*DIM + nc + tn*4;
        float4 c0 = *(float4*)C0;
        c0.x += f0.x + bv.x; c0.y += f1.x + bv.y; c0.z += f2.x + bv.z; c0.w += f3.x + bv.w;
        *(float4*)C0 = c0;
        float* C1 = C0 + DIM;
        float4 c1 = *(float4*)C1;
        c1.x += f0.y + bv.x; c1.y += f1.y + bv.y; c1.z += f2.y + bv.z; c1.w += f3.y + bv.w;
        *(float4*)C1 = c1;
    }
}

// ---------------- outputs ----------------
__global__ void out_templates_kernel(float* __restrict__ out) {
    int b = blockIdx.x, d = threadIdx.x;
    for (int n = 0; n < NSLOT; n++)
        out[((size_t)(b*DIM) + d)*NSLOT + n] = g_templates[((size_t)(b*NSLOT) + n)*DIM + d];
}

__global__ void out_attn_kernel(float* __restrict__ out) {
    int n = blockIdx.x, b = blockIdx.y, t = threadIdx.x;
    float inv = 1.0f / g_colsum[b*NSLOT + n];
    size_t base = (size_t)BATCH*DIM*NSLOT + ((size_t)(b*NSLOT + n))*LTOK;
    for (int k = 0; k < 16; k++) {
        int l = k*256 + t;
        out[base + l] = g_attn[((size_t)b*LTOK + l)*NSLOT + n] * inv;
    }
}

// ---------------- launch ----------------
extern "C" void kernel_launch(void* const* d_in, const int* in_sizes, int n_in,
                              void* d_out, int out_size) {
    const float* x       = (const float*)d_in[0];
    const float* tinit   = (const float*)d_in[1];
    const float* conv_w  = (const float*)d_in[2];
    const float* conv_b  = (const float*)d_in[3];
    const float* Wq      = (const float*)d_in[4];
    const float* Wk      = (const float*)d_in[5];
    const float* Wv      = (const float*)d_in[6];
    const float* ln_in_g = (const float*)d_in[7];
    const float* ln_in_b = (const float*)d_in[8];
    const float* ln_t_g  = (const float*)d_in[9];
    const float* ln_t_b  = (const float*)d_in[10];
    const float* ln_m_g  = (const float*)d_in[11];
    const float* ln_m_b  = (const float*)d_in[12];
    const float* W1      = (const float*)d_in[13];
    const float* b1      = (const float*)d_in[14];
    const float* W2      = (const float*)d_in[15];
    const float* b2      = (const float*)d_in[16];
    float* out = (float*)d_out;

    cudaFuncSetAttribute(conv_mma_kernel, cudaFuncAttributeMaxDynamicSharedMemorySize, CMM_SMEM);
    cudaFuncSetAttribute(kv_mma_kernel, cudaFuncAttributeMaxDynamicSharedMemorySize, CMM_SMEM);
    cudaFuncSetAttribute(attn_gc_kernel, cudaFuncAttributeMaxDynamicSharedMemorySize, AGC_SMEM);
    cudaFuncSetAttribute(gemm_q_kernel, cudaFuncAttributeMaxDynamicSharedMemorySize, (16384+1024)*4);
    cudaFuncSetAttribute(gemm_h_kernel, cudaFuncAttributeMaxDynamicSharedMemorySize, (16384+1024)*4);
    cudaFuncSetAttribute(gemm_o_kernel, cudaFuncAttributeMaxDynamicSharedMemorySize, GEMMO_SMEM_FLOATS*4);

    templates_init_kernel<<<8, 256>>>(tinit);
    xsplit_kernel<<<8*33*33, 256>>>(x);
    cwsplit_kernel<<<3456, 256>>>(conv_w);
    kvsplit_kernel<<<512, 256>>>(Wk, Wv);
    conv_mma_kernel<<<256, 512, CMM_SMEM>>>(conv_b, ln_in_g, ln_in_b);
    kv_mma_kernel<<<512, 512, CMM_SMEM>>>();

    for (int it = 0; it < 6; it++) {
        gemm_q_kernel<<<dim3(4, 8), 256, (16384+1024)*4>>>(Wq, ln_t_g, ln_t_b);
        attn_gc_kernel<<<dim3(32, 8), 256, AGC_SMEM>>>(it == 5 ? 1 : 0);
        finalize_kernel<<<dim3(8, 8), 256>>>(ln_m_g, ln_m_b);
        gemm_h_kernel<<<dim3(8, 8), 256, (16384+1024)*4>>>(W1, b1);
        gemm_o_kernel<<<dim3(4, 8), 256, GEMMO_SMEM_FLOATS*4>>>(W2, b2);
    }

    out_templates_kernel<<<8, 256>>>(out);
    out_attn_kernel<<<dim3(64, 8), 256>>>(out);
}

// round 14
// speedup vs baseline: 1.7248x; 1.1162x over previous
#include <cuda_runtime.h>
#include <cuda_bf16.h>
#include <stdint.h>
#include <math.h>

#define BATCH 8
#define DIM   256
#define NSLOT 64
#define LTOK  4096

typedef unsigned long long u64;

__device__ __forceinline__ u64 PK1(float v) {
    u64 r; asm("mov.b64 %0, {%1,%1};" : "=l"(r) : "f"(v)); return r;
}
__device__ __forceinline__ void FMA2(u64& d, u64 a, u64 b) {
    asm("fma.rn.f32x2 %0, %1, %2, %0;" : "+l"(d) : "l"(a), "l"(b));
}
__device__ __forceinline__ float2 UPK(u64 v) {
    float2 f; asm("mov.b64 {%0,%1}, %2;" : "=f"(f.x), "=f"(f.y) : "l"(v)); return f;
}

// ---------------- scratch ----------------
__device__ float g_templates[BATCH*NSLOT*DIM];
__device__ float g_tbuf[BATCH*NSLOT*DIM];
__device__ float g_attn[BATCH*LTOK*NSLOT];
__device__ float g_colsum_part[BATCH*64*NSLOT];
__device__ float g_colsum[BATCH*NSLOT];
__device__ float g_accpart[32*BATCH*NSLOT*DIM];
__device__ float g_hidden[BATCH*NSLOT*512];
// bf16 split operands
__device__ __nv_bfloat16 g_xh[36799488];
__device__ __nv_bfloat16 g_xl[36799488];
__device__ __nv_bfloat16 g_cwh[27*32768];
__device__ __nv_bfloat16 g_cwl[27*32768];
__device__ __nv_bfloat16 g_kvh[256*512];
__device__ __nv_bfloat16 g_kvl[256*512];
__device__ __nv_bfloat16 g_toksh[32768*256];
__device__ __nv_bfloat16 g_toksl[32768*256];
__device__ __nv_bfloat16 g_kh[32768*256];
__device__ __nv_bfloat16 g_kl[32768*256];
__device__ __nv_bfloat16 g_vh[32768*256];
__device__ __nv_bfloat16 g_vl[32768*256];
__device__ __nv_bfloat16 g_qh[BATCH*NSLOT*DIM];
__device__ __nv_bfloat16 g_ql[BATCH*NSLOT*DIM];

__device__ __forceinline__ float gelu_exact(float v) {
    return 0.5f * v * (1.0f + erff(v * 0.70710678118654752f));
}

// ========== mma.sync helpers ==========
__device__ __forceinline__ uint32_t smem_u32(const void* p) {
    uint32_t a;
    asm("{ .reg .u64 t; cvta.to.shared.u64 t, %1; cvt.u32.u64 %0, t; }" : "=r"(a) : "l"(p));
    return a;
}
__device__ __forceinline__ void ldsm_x4(uint32_t* r, uint32_t addr) {
    asm volatile("ldmatrix.sync.aligned.m8n8.x4.shared.b16 {%0,%1,%2,%3}, [%4];"
        : "=r"(r[0]), "=r"(r[1]), "=r"(r[2]), "=r"(r[3]) : "r"(addr));
}
__device__ __forceinline__ void ldsm_x4_t(uint32_t* r, uint32_t addr) {
    asm volatile("ldmatrix.sync.aligned.m8n8.x4.trans.shared.b16 {%0,%1,%2,%3}, [%4];"
        : "=r"(r[0]), "=r"(r[1]), "=r"(r[2]), "=r"(r[3]) : "r"(addr));
}
__device__ __forceinline__ void mma_bf16(float* d, const uint32_t* a, const uint32_t* b) {
    asm volatile("mma.sync.aligned.m16n8k16.row.col.f32.bf16.bf16.f32 "
        "{%0,%1,%2,%3}, {%4,%5,%6,%7}, {%8,%9}, {%0,%1,%2,%3};"
        : "+f"(d[0]), "+f"(d[1]), "+f"(d[2]), "+f"(d[3])
        : "r"(a[0]), "r"(a[1]), "r"(a[2]), "r"(a[3]), "r"(b[0]), "r"(b[1]));
}
__device__ __forceinline__ void bsplit(float v0, float v1, __nv_bfloat162& hh, __nv_bfloat162& ll) {
    __nv_bfloat16 h0 = __float2bfloat16(v0), h1 = __float2bfloat16(v1);
    hh.x = h0; hh.y = h1;
    ll.x = __float2bfloat16(v0 - __bfloat162float(h0));
    ll.y = __float2bfloat16(v1 - __bfloat162float(h1));
}
__device__ __forceinline__ void cpa16(uint32_t dst, const void* src) {
    asm volatile("cp.async.cg.shared.global [%0], [%1], 16;" :: "r"(dst), "l"(src) : "memory");
}
#define CP_COMMIT asm volatile("cp.async.commit_group;" ::: "memory")
#define CP_WAIT0  asm volatile("cp.async.wait_group 0;" ::: "memory")

// 128x256 += A(128x128, pitch 272B) x B(128k x 256n, pitch 528B); 3-term bf16 split.
__device__ __forceinline__ void mma_chunk(
    uint32_t sAh, uint32_t sAl, uint32_t sBh, uint32_t sBl,
    float d[2][8][4], int wm, int wn, int lane)
{
    uint32_t aoff0 = (uint32_t)((wm*32 + (lane & 15))*272 + (lane >> 4)*16);
    uint32_t boff0 = (uint32_t)((lane & 15)*528 + (wn*64 + (lane >> 4)*8)*2);
    #pragma unroll
    for (int kk = 0; kk < 8; kk++) {
        uint32_t ah[8], al[8], bb[16];
        uint32_t ao = aoff0 + kk*32;
        ldsm_x4(ah,     sAh + ao);
        ldsm_x4(ah + 4, sAh + ao + 4352);
        ldsm_x4(al,     sAl + ao);
        ldsm_x4(al + 4, sAl + ao + 4352);
        uint32_t bo = boff0 + kk*8448;
        #pragma unroll
        for (int jj = 0; jj < 4; jj++) ldsm_x4_t(bb + jj*4, sBh + bo + jj*32);
        #pragma unroll
        for (int mi = 0; mi < 2; mi++) {
            #pragma unroll
            for (int j = 0; j < 8; j++) {
                const uint32_t* bf = bb + (j >> 1)*4 + (j & 1)*2;
                mma_bf16(d[mi][j], mi ? ah + 4 : ah, bf);
                mma_bf16(d[mi][j], mi ? al + 4 : al, bf);
            }
        }
        #pragma unroll
        for (int jj = 0; jj < 4; jj++) ldsm_x4_t(bb + jj*4, sBl + bo + jj*32);
        #pragma unroll
        for (int mi = 0; mi < 2; mi++) {
            #pragma unroll
            for (int j = 0; j < 8; j++) {
                const uint32_t* bf = bb + (j >> 1)*4 + (j & 1)*2;
                mma_bf16(d[mi][j], mi ? ah + 4 : ah, bf);
            }
        }
    }
}

// dual-term pass: d += Ah*B + Al*B
__device__ __forceinline__ void mma_dual(
    uint32_t sAh, uint32_t sAl, uint32_t sB,
    float d[2][8][4], int wm, int wn, int lane)
{
    uint32_t aoff0 = (uint32_t)((wm*32 + (lane & 15))*272 + (lane >> 4)*16);
    uint32_t boff0 = (uint32_t)((lane & 15)*528 + (wn*64 + (lane >> 4)*8)*2);
    #pragma unroll
    for (int kk = 0; kk < 8; kk++) {
        uint32_t ah[8], al[8], bb[16];
        uint32_t ao = aoff0 + kk*32;
        ldsm_x4(ah,     sAh + ao);
        ldsm_x4(ah + 4, sAh + ao + 4352);
        ldsm_x4(al,     sAl + ao);
        ldsm_x4(al + 4, sAl + ao + 4352);
        uint32_t bo = boff0 + kk*8448;
        #pragma unroll
        for (int jj = 0; jj < 4; jj++) ldsm_x4_t(bb + jj*4, sB + bo + jj*32);
        #pragma unroll
        for (int mi = 0; mi < 2; mi++) {
            #pragma unroll
            for (int j = 0; j < 8; j++) {
                const uint32_t* bf = bb + (j >> 1)*4 + (j & 1)*2;
                mma_bf16(d[mi][j], mi ? ah + 4 : ah, bf);
                mma_bf16(d[mi][j], mi ? al + 4 : al, bf);
            }
        }
    }
}

// single-term pass: d += Ah*B
__device__ __forceinline__ void mma_single(
    uint32_t sAh, uint32_t sB,
    float d[2][8][4], int wm, int wn, int lane)
{
    uint32_t aoff0 = (uint32_t)((wm*32 + (lane & 15))*272 + (lane >> 4)*16);
    uint32_t boff0 = (uint32_t)((lane & 15)*528 + (wn*64 + (lane >> 4)*8)*2);
    #pragma unroll
    for (int kk = 0; kk < 8; kk++) {
        uint32_t ah[8], bb[16];
        uint32_t ao = aoff0 + kk*32;
        ldsm_x4(ah,     sAh + ao);
        ldsm_x4(ah + 4, sAh + ao + 4352);
        uint32_t bo = boff0 + kk*8448;
        #pragma unroll
        for (int jj = 0; jj < 4; jj++) ldsm_x4_t(bb + jj*4, sB + bo + jj*32);
        #pragma unroll
        for (int mi = 0; mi < 2; mi++) {
            #pragma unroll
            for (int j = 0; j < 8; j++) {
                const uint32_t* bf = bb + (j >> 1)*4 + (j & 1)*2;
                mma_bf16(d[mi][j], mi ? ah + 4 : ah, bf);
            }
        }
    }
}

// ---------------- prep kernels ----------------
__global__ void templates_init_kernel(const float* __restrict__ tinit) {
    int b = blockIdx.x, t = threadIdx.x;
    for (int n = 0; n < NSLOT; n++)
        g_templates[(b*NSLOT + n)*DIM + t] = tinit[n*DIM + t];
}

__global__ __launch_bounds__(256) void xsplit_kernel(const float* __restrict__ x) {
    __shared__ float st[128*33];
    int bid = blockIdx.x; int b = bid / 1089; int rem = bid % 1089; int d = rem / 33, h = rem % 33;
    int t = threadIdx.x, warp = t >> 5, lane = t & 31;
    const float* xb = x + ((((size_t)b*128)*33 + d)*33 + h)*33;
    for (int c = warp; c < 128; c += 8) {
        const float* src = xb + (size_t)c*35937;
        st[c*33 + lane] = src[lane];
        if (lane == 0) st[c*33 + 32] = src[32];
    }
    __syncthreads();
    size_t ob = ((((size_t)b*33 + d)*33 + h)*33)*128;
    for (int i = t; i < 33*128; i += 256) {
        int w = i >> 7, c = i & 127;
        float v = st[c*33 + w];
        __nv_bfloat16 hi = __float2bfloat16(v);
        g_xh[ob + (size_t)w*128 + c] = hi;
        g_xl[ob + (size_t)w*128 + c] = __float2bfloat16(v - __bfloat162float(hi));
    }
}

__global__ void cwsplit_kernel(const float* __restrict__ cw) {
    int idx = blockIdx.x*256 + threadIdx.x;
    int tap = idx >> 15, r = idx & 32767;
    int k = r >> 8, n = r & 255;
    float v = cw[(size_t)n*3456 + k*27 + tap];
    __nv_bfloat16 hi = __float2bfloat16(v);
    g_cwh[idx] = hi;
    g_cwl[idx] = __float2bfloat16(v - __bfloat162float(hi));
}

__global__ void kvsplit_kernel(const float* __restrict__ Wk, const float* __restrict__ Wv) {
    int idx = blockIdx.x*256 + threadIdx.x;
    int k = idx >> 9, c512 = idx & 511;
    int mat = c512 >> 8, col = c512 & 255;
    const float* W = mat ? Wv : Wk;
    float v = W[(size_t)k*256 + col];
    __nv_bfloat16 hi = __float2bfloat16(v);
    g_kvh[idx] = hi;
    g_kvl[idx] = __float2bfloat16(v - __bfloat162float(hi));
}

// ---------------- conv (implicit GEMM, cp.async-pipelined B) + bias + ReLU + LN ----------------
#define CMM_SMEM 204800
__global__ __launch_bounds__(512, 1) void conv_mma_kernel(
    const float* __restrict__ convb, const float* __restrict__ lng, const float* __restrict__ lnb)
{
    extern __shared__ char sm[];
    uint32_t sb = smem_u32(sm);
    const uint32_t oAh = 0, oAl = 34816, oB0 = 69632, oB1 = 137216;
    int t = threadIdx.x, lane = t & 31, wid = t >> 5;
    int wm = wid >> 2, wn = wid & 3;
    int bx = blockIdx.x; int b = bx >> 5, xd = (bx >> 1) & 15, half = bx & 1;

    float d[2][8][4];
    #pragma unroll
    for (int i = 0; i < 2; i++)
        #pragma unroll
        for (int j = 0; j < 8; j++)
            #pragma unroll
            for (int c = 0; c < 4; c++) d[i][j][c] = 0.f;

    int m = t >> 2, q = t & 3;
    int xhl = m >> 4, xw = m & 15;

    {
        const uint4* s1 = (const uint4*)(g_cwh);
        #pragma unroll
        for (int it = 0; it < 8; it++) {
            int i = t + it*512;
            cpa16(sb + oB0 + (uint32_t)((i >> 5)*528 + (i & 31)*16), s1 + i);
        }
        CP_COMMIT;
    }

    for (int tap = 0; tap < 27; tap++) {
        int kd = tap/9, r9 = tap%9, kh = r9/3, kw = r9%3;
        {
            size_t xi = ((((size_t)(b*33) + 2*xd + kd)*33 + 2*(half*8 + xhl) + kh)*33 + 2*xw + kw)*128 + q*32;
            const uint4* shi = (const uint4*)(g_xh + xi);
            const uint4* slo = (const uint4*)(g_xl + xi);
            char* dh = sm + oAh + m*272 + q*64;
            char* dl = sm + oAl + m*272 + q*64;
            #pragma unroll
            for (int j = 0; j < 4; j++) {
                *(uint4*)(dh + j*16) = shi[j];
                *(uint4*)(dl + j*16) = slo[j];
            }
        }
        CP_WAIT0;
        __syncthreads();
        {
            const uint4* s2 = (const uint4*)(g_cwl + tap*32768);
            #pragma unroll
            for (int it = 0; it < 8; it++) {
                int i = t + it*512;
                cpa16(sb + oB1 + (uint32_t)((i >> 5)*528 + (i & 31)*16), s2 + i);
            }
            CP_COMMIT;
        }
        mma_dual(sb + oAh, sb + oAl, sb + oB0, d, wm, wn, lane);
        CP_WAIT0;
        __syncthreads();
        if (tap < 26) {
            const uint4* s1 = (const uint4*)(g_cwh + (tap+1)*32768);
            #pragma unroll
            for (int it = 0; it < 8; it++) {
                int i = t + it*512;
                cpa16(sb + oB0 + (uint32_t)((i >> 5)*528 + (i & 31)*16), s1 + i);
            }
            CP_COMMIT;
        }
        mma_single(sb + oAh, sb + oB1, d, wm, wn, lane);
        __syncthreads();
    }

    float* stg = (float*)sm;
    {
        int r0 = wm*32 + (lane >> 2);
        int c0 = wn*64 + (lane & 3)*2;
        #pragma unroll
        for (int mi = 0; mi < 2; mi++)
            #pragma unroll
            for (int j = 0; j < 8; j++) {
                int rr = r0 + mi*16, cc = c0 + j*8;
                *(float2*)(stg + (size_t)rr*264 + cc)     = make_float2(d[mi][j][0], d[mi][j][1]);
                *(float2*)(stg + (size_t)(rr+8)*264 + cc) = make_float2(d[mi][j][2], d[mi][j][3]);
            }
    }
    __syncthreads();

    {
        int tok = t >> 2, q2 = t & 3;
        const float* src = stg + (size_t)tok*264 + q2*64;
        float z[64];
        float s = 0.f, sq = 0.f;
        #pragma unroll
        for (int i = 0; i < 64; i++) {
            float v = fmaxf(src[i] + convb[q2*64 + i], 0.f);
            z[i] = v; s += v; sq += v*v;
        }
        s  += __shfl_xor_sync(0xffffffffu, s, 1);  s  += __shfl_xor_sync(0xffffffffu, s, 2);
        sq += __shfl_xor_sync(0xffffffffu, sq, 1); sq += __shfl_xor_sync(0xffffffffu, sq, 2);
        float mu = s * (1.f/256.f);
        float rs = rsqrtf(sq * (1.f/256.f) - mu*mu + 1e-5f);
        int l = (xd*16 + half*8 + (tok >> 4))*16 + (tok & 15);
        size_t tg = ((size_t)b*4096 + l)*256 + q2*64;
        #pragma unroll
        for (int i = 0; i < 64; i += 2) {
            int ch = q2*64 + i;
            float v0 = (z[i]   - mu)*rs*lng[ch]   + lnb[ch];
            float v1 = (z[i+1] - mu)*rs*lng[ch+1] + lnb[ch+1];
            __nv_bfloat162 hh, ll;
            bsplit(v0, v1, hh, ll);
            *(__nv_bfloat162*)(g_toksh + tg + i) = hh;
            *(__nv_bfloat162*)(g_toksl + tg + i) = ll;
        }
    }
}

// ---------------- K/V projection via mma.sync -> bf16 split outputs ----------------
__global__ __launch_bounds__(512, 1) void kv_mma_kernel() {
    extern __shared__ char sm[];
    uint32_t sb = smem_u32(sm);
    const uint32_t oAh = 0, oAl = 34816, oBh = 69632, oBl = 137216;
    int t = threadIdx.x, lane = t & 31, wid = t >> 5;
    int wm = wid >> 2, wn = wid & 3;
    int nhalf = blockIdx.x & 1, chunk = blockIdx.x >> 1;

    float d[2][8][4];
    #pragma unroll
    for (int i = 0; i < 2; i++)
        #pragma unroll
        for (int j = 0; j < 8; j++)
            #pragma unroll
            for (int c = 0; c < 4; c++) d[i][j][c] = 0.f;

    int m = t >> 2, q = t & 3;
    for (int kc = 0; kc < 2; kc++) {
        {
            size_t ti = ((size_t)(chunk*128 + m))*256 + kc*128 + q*32;
            const uint4* shi = (const uint4*)(g_toksh + ti);
            const uint4* slo = (const uint4*)(g_toksl + ti);
            char* dh = sm + oAh + m*272 + q*64;
            char* dl = sm + oAl + m*272 + q*64;
            #pragma unroll
            for (int j = 0; j < 4; j++) {
                *(uint4*)(dh + j*16) = shi[j];
                *(uint4*)(dl + j*16) = slo[j];
            }
        }
        {
            #pragma unroll
            for (int it = 0; it < 8; it++) {
                int i = t + it*512;
                int row = i >> 5, seg = i & 31;
                size_t off = (size_t)(kc*128 + row)*512 + nhalf*256 + seg*8;
                *(uint4*)(sm + oBh + row*528 + seg*16) = *(const uint4*)(g_kvh + off);
                *(uint4*)(sm + oBl + row*528 + seg*16) = *(const uint4*)(g_kvl + off);
            }
        }
        __syncthreads();
        mma_chunk(sb + oAh, sb + oAl, sb + oBh, sb + oBl, d, wm, wn, lane);
        __syncthreads();
    }

    __nv_bfloat16* dh = nhalf ? g_vh : g_kh;
    __nv_bfloat16* dl = nhalf ? g_vl : g_kl;
    int r0 = wm*32 + (lane >> 2);
    int c0 = wn*64 + (lane & 3)*2;
    #pragma unroll
    for (int mi = 0; mi < 2; mi++)
        #pragma unroll
        for (int j = 0; j < 8; j++) {
            int rr = r0 + mi*16, cc = c0 + j*8;
            size_t tok = (size_t)chunk*128 + rr;
            __nv_bfloat162 hh, ll;
            bsplit(d[mi][j][0], d[mi][j][1], hh, ll);
            *(__nv_bfloat162*)(dh + tok*256 + cc) = hh;
            *(__nv_bfloat162*)(dl + tok*256 + cc) = ll;
            bsplit(d[mi][j][2], d[mi][j][3], hh, ll);
            *(__nv_bfloat162*)(dh + (tok+8)*256 + cc) = hh;
            *(__nv_bfloat162*)(dl + (tok+8)*256 + cc) = ll;
        }
}

// ---------------- fused LN_t + q-GEMM (full B preload, sync-free compute) ----------------
#define GEMMQ_SMEM ((16384 + 16384)*4)
__global__ __launch_bounds__(256) void gemm_q_kernel(
    const float* __restrict__ Wq, const float* __restrict__ lng, const float* __restrict__ lnb)
{
    extern __shared__ float smf[];
    float* Af = smf; float* Bf = smf + 16384;
    int b = blockIdx.y; int nc = blockIdx.x * 64;
    int t = threadIdx.x;
    int kk0 = t >> 4, n4 = (t & 15)*4;
    // B preload: all 256 k-rows, 16 independent loads per thread
    #pragma unroll
    for (int k0 = 0; k0 < 256; k0 += 16)
        *(float4*)(Bf + (k0 + kk0)*64 + n4) = *(const float4*)(Wq + (size_t)(k0+kk0)*256 + nc + n4);
    // LN staging (writes Af transposed)
    {
        int r = t >> 2, part = t & 3;
        const float* row = g_templates + ((size_t)(b*NSLOT) + r)*DIM + part*64;
        float s = 0.f, sq = 0.f;
        #pragma unroll
        for (int i = 0; i < 64; i += 4) {
            float4 v = *(const float4*)(row + i);
            s += v.x+v.y+v.z+v.w;
            sq += v.x*v.x + v.y*v.y + v.z*v.z + v.w*v.w;
        }
        s  += __shfl_xor_sync(0xffffffffu, s, 1);  s  += __shfl_xor_sync(0xffffffffu, s, 2);
        sq += __shfl_xor_sync(0xffffffffu, sq, 1); sq += __shfl_xor_sync(0xffffffffu, sq, 2);
        float mu = s * (1.0f/256.0f);
        float rs = rsqrtf(sq * (1.0f/256.0f) - mu*mu + 1e-5f);
        #pragma unroll
        for (int i = 0; i < 64; i += 4) {
            float4 v = *(const float4*)(row + i);
            float4 gg = *(const float4*)(lng + part*64 + i);
            float4 bv = *(const float4*)(lnb + part*64 + i);
            Af[(part*64+i+0)*64 + r] = (v.x - mu)*rs*gg.x + bv.x;
            Af[(part*64+i+1)*64 + r] = (v.y - mu)*rs*gg.y + bv.y;
            Af[(part*64+i+2)*64 + r] = (v.z - mu)*rs*gg.z + bv.z;
            Af[(part*64+i+3)*64 + r] = (v.w - mu)*rs*gg.w + bv.w;
        }
    }
    __syncthreads();

    int tm = t >> 4, tn = t & 15;
    u64 acc[4][2] = {};
    for (int k0 = 0; k0 < 256; k0 += 16) {
        #pragma unroll
        for (int kk = 0; kk < 16; kk++) {
            ulonglong2 a2 = *(ulonglong2*)(Af + (k0+kk)*64 + tm*4);
            float4 bb = *(float4*)(Bf + (k0+kk)*64 + tn*4);
            u64 q0 = PK1(bb.x), q1 = PK1(bb.y), q2 = PK1(bb.z), q3 = PK1(bb.w);
            FMA2(acc[0][0], a2.x, q0); FMA2(acc[0][1], a2.y, q0);
            FMA2(acc[1][0], a2.x, q1); FMA2(acc[1][1], a2.y, q1);
            FMA2(acc[2][0], a2.x, q2); FMA2(acc[2][1], a2.y, q2);
            FMA2(acc[3][0], a2.x, q3); FMA2(acc[3][1], a2.y, q3);
        }
    }
    const float scale = 0.0625f;
    #pragma unroll
    for (int p = 0; p < 2; p++) {
        float2 f0 = UPK(acc[0][p]), f1 = UPK(acc[1][p]), f2 = UPK(acc[2][p]), f3 = UPK(acc[3][p]);
        int mm = tm*4 + p*2;
        size_t o0 = ((size_t)(b*NSLOT) + mm)*DIM + nc + tn*4;
        __nv_bfloat162 hh, ll;
        bsplit(f0.x*scale, f1.x*scale, hh, ll);
        *(__nv_bfloat162*)(g_qh + o0) = hh; *(__nv_bfloat162*)(g_ql + o0) = ll;
        bsplit(f2.x*scale, f3.x*scale, hh, ll);
        *(__nv_bfloat162*)(g_qh + o0 + 2) = hh; *(__nv_bfloat162*)(g_ql + o0 + 2) = ll;
        bsplit(f0.y*scale, f1.y*scale, hh, ll);
        *(__nv_bfloat162*)(g_qh + o0 + DIM) = hh; *(__nv_bfloat162*)(g_ql + o0 + DIM) = ll;
        bsplit(f2.y*scale, f3.y*scale, hh, ll);
        *(__nv_bfloat162*)(g_qh + o0 + DIM + 2) = hh; *(__nv_bfloat162*)(g_ql + o0 + DIM + 2) = ll;
    }
}

// ---------------- FUSED attn logits + softmax + colsum + attn^T@v ----------------
#define AGC_SMEM 206848
__global__ __launch_bounds__(256) void attn_gc_kernel(int write_attn) {
    extern __shared__ char sm[];
    uint32_t sb = smem_u32(sm);
    const uint32_t oKh = 0, oKl = 34816, oQh = 69632, oQl = 87040;
    const uint32_t oStg = 135168, oAth = 169984, oAtl = 188416;
    const uint32_t oVh = 0, oVl = 67584;
    int t = threadIdx.x, lane = t & 31, wid = t >> 5;
    int lb = blockIdx.x, b = blockIdx.y;

    int wm = wid >> 1, wn = wid & 1;
    float d[2][4][4];
    #pragma unroll
    for (int i = 0; i < 2; i++)
        #pragma unroll
        for (int j = 0; j < 4; j++)
            #pragma unroll
            for (int c = 0; c < 4; c++) d[i][j][c] = 0.f;

    for (int kc = 0; kc < 2; kc++) {
        {
            int row = t >> 1, half = t & 1;
            size_t ti = ((size_t)(b*4096) + lb*128 + row)*256 + kc*128 + half*64;
            const uint4* shi = (const uint4*)(g_kh + ti);
            const uint4* slo = (const uint4*)(g_kl + ti);
            char* dh = sm + oKh + row*272 + half*128;
            char* dl = sm + oKl + row*272 + half*128;
            #pragma unroll
            for (int j = 0; j < 8; j++) {
                *(uint4*)(dh + j*16) = shi[j];
                *(uint4*)(dl + j*16) = slo[j];
            }
        }
        {
            int row = t >> 2, q4 = t & 3;
            size_t ti = ((size_t)(b*NSLOT) + row)*256 + kc*128 + q4*32;
            const uint4* shi = (const uint4*)(g_qh + ti);
            const uint4* slo = (const uint4*)(g_ql + ti);
            char* dh = sm + oQh + row*272 + q4*64;
            char* dl = sm + oQl + row*272 + q4*64;
            #pragma unroll
            for (int j = 0; j < 4; j++) {
                *(uint4*)(dh + j*16) = shi[j];
                *(uint4*)(dl + j*16) = slo[j];
            }
        }
        __syncthreads();
        uint32_t aoff0 = (uint32_t)((wm*32 + (lane & 15))*272 + (lane >> 4)*16);
        uint32_t qoff0 = (uint32_t)(((lane >> 4)*8 + (lane & 7) + wn*32)*272 + ((lane >> 3) & 1)*16);
        #pragma unroll
        for (int kk = 0; kk < 8; kk++) {
            uint32_t ah[8], al[8], qh8[8], ql8[8];
            uint32_t ao = aoff0 + kk*32;
            ldsm_x4(ah,     sb + oKh + ao);
            ldsm_x4(ah + 4, sb + oKh + ao + 16*272);
            ldsm_x4(al,     sb + oKl + ao);
            ldsm_x4(al + 4, sb + oKl + ao + 16*272);
            uint32_t qo = qoff0 + kk*32;
            ldsm_x4(qh8,     sb + oQh + qo);
            ldsm_x4(qh8 + 4, sb + oQh + qo + 16*272);
            ldsm_x4(ql8,     sb + oQl + qo);
            ldsm_x4(ql8 + 4, sb + oQl + qo + 16*272);
            #pragma unroll
            for (int mi = 0; mi < 2; mi++) {
                #pragma unroll
                for (int j = 0; j < 4; j++) {
                    const uint32_t* bh = qh8 + (j >> 1)*4 + (j & 1)*2;
                    const uint32_t* bl = ql8 + (j >> 1)*4 + (j & 1)*2;
                    const uint32_t* am = mi ? ah + 4 : ah;
                    const uint32_t* aml = mi ? al + 4 : al;
                    mma_bf16(d[mi][j], am, bh);
                    mma_bf16(d[mi][j], am, bl);
                    mma_bf16(d[mi][j], aml, bh);
                }
            }
        }
        __syncthreads();
    }

    float* stg = (float*)(sm + oStg);
    {
        int r0 = wm*32 + (lane >> 2);
        int c0 = wn*32 + (lane & 3)*2;
        #pragma unroll
        for (int mi = 0; mi < 2; mi++)
            #pragma unroll
            for (int j = 0; j < 4; j++) {
                int rr = r0 + mi*16, cc = c0 + j*8;
                *(float2*)(stg + rr*68 + cc)     = make_float2(d[mi][j][0], d[mi][j][1]);
                *(float2*)(stg + (rr+8)*68 + cc) = make_float2(d[mi][j][2], d[mi][j][3]);
            }
    }
    __syncthreads();

    {
        int row = t >> 1, half = t & 1;
        float* sr = stg + row*68 + half*32;
        float a[32];
        float mx = -3.4e38f;
        #pragma unroll
        for (int i = 0; i < 32; i++) { a[i] = sr[i]; mx = fmaxf(mx, a[i]); }
        mx = fmaxf(mx, __shfl_xor_sync(0xffffffffu, mx, 1));
        float s = 0.f;
        #pragma unroll
        for (int i = 0; i < 32; i++) { a[i] = expf(a[i] - mx); s += a[i]; }
        s += __shfl_xor_sync(0xffffffffu, s, 1);
        float inv = 1.0f / s;
        #pragma unroll
        for (int i = 0; i < 32; i++) { a[i] = a[i]*inv + 1e-8f; sr[i] = a[i]; }
        if (write_attn) {
            size_t gi = ((size_t)(b*4096) + lb*128 + row)*64 + half*32;
            #pragma unroll
            for (int i = 0; i < 32; i += 4)
                *(float4*)(g_attn + gi + i) = make_float4(a[i], a[i+1], a[i+2], a[i+3]);
        }
        char* dst_h = sm + oAth + row*144 + half*64;
        char* dst_l = sm + oAtl + row*144 + half*64;
        #pragma unroll
        for (int i = 0; i < 32; i += 2) {
            __nv_bfloat162 hh, ll;
            bsplit(a[i], a[i+1], hh, ll);
            *(__nv_bfloat162*)(dst_h + i*2) = hh;
            *(__nv_bfloat162*)(dst_l + i*2) = ll;
        }
    }
    __syncthreads();
    if (t < 64) {
        float s = 0.f;
        for (int r = 0; r < 128; r++) s += stg[r*68 + t];
        g_colsum_part[((size_t)b*64 + lb)*NSLOT + t] = s;
    }

    {
        int row = t >> 1, half = t & 1;
        size_t ti = ((size_t)(b*4096) + lb*128 + row)*256 + half*128;
        const uint4* shi = (const uint4*)(g_vh + ti);
        const uint4* slo = (const uint4*)(g_vl + ti);
        char* dst_h = sm + oVh + row*528 + half*256;
        char* dst_l = sm + oVl + row*528 + half*256;
        #pragma unroll
        for (int j = 0; j < 16; j++) {
            *(uint4*)(dst_h + j*16) = shi[j];
            *(uint4*)(dst_l + j*16) = slo[j];
        }
    }
    __syncthreads();

    int wm2 = wid & 1, wn2 = wid >> 1;
    float d2[2][8][4];
    #pragma unroll
    for (int i = 0; i < 2; i++)
        #pragma unroll
        for (int j = 0; j < 8; j++)
            #pragma unroll
            for (int c = 0; c < 4; c++) d2[i][j][c] = 0.f;
    {
        uint32_t aoff0 = (uint32_t)((((lane >> 4)*8 + (lane & 7)))*144 + ((lane >> 3) & 1)*16 + wm2*64);
        uint32_t boff0 = (uint32_t)((lane & 15)*528 + (wn2*64 + (lane >> 4)*8)*2);
        #pragma unroll
        for (int kk = 0; kk < 8; kk++) {
            uint32_t ah[8], al[8], bh8[16], bl8[16];
            uint32_t ao = aoff0 + kk*16*144;
            ldsm_x4_t(ah,     sb + oAth + ao);
            ldsm_x4_t(ah + 4, sb + oAth + ao + 32);
            ldsm_x4_t(al,     sb + oAtl + ao);
            ldsm_x4_t(al + 4, sb + oAtl + ao + 32);
            uint32_t bo = boff0 + kk*8448;
            #pragma unroll
            for (int jj = 0; jj < 4; jj++) ldsm_x4_t(bh8 + jj*4, sb + oVh + bo + jj*32);
            #pragma unroll
            for (int jj = 0; jj < 4; jj++) ldsm_x4_t(bl8 + jj*4, sb + oVl + bo + jj*32);
            #pragma unroll
            for (int mi = 0; mi < 2; mi++) {
                #pragma unroll
                for (int j = 0; j < 8; j++) {
                    const uint32_t* bfh = bh8 + (j >> 1)*4 + (j & 1)*2;
                    const uint32_t* bfl = bl8 + (j >> 1)*4 + (j & 1)*2;
                    const uint32_t* am = mi ? ah + 4 : ah;
                    const uint32_t* aml = mi ? al + 4 : al;
                    mma_bf16(d2[mi][j], am, bfh);
                    mma_bf16(d2[mi][j], am, bfl);
                    mma_bf16(d2[mi][j], aml, bfh);
                }
            }
        }
    }

    int r0 = wm2*32 + (lane >> 2);
    int c0 = wn2*64 + (lane & 3)*2;
    float* C = g_accpart + ((size_t)((lb*BATCH + b)*NSLOT))*DIM;
    #pragma unroll
    for (int mi = 0; mi < 2; mi++)
        #pragma unroll
        for (int j = 0; j < 8; j++) {
            int slot = r0 + mi*16, cc = c0 + j*8;
            *(float2*)(C + (size_t)slot*DIM + cc)     = make_float2(d2[mi][j][0], d2[mi][j][1]);
            *(float2*)(C + (size_t)(slot+8)*DIM + cc) = make_float2(d2[mi][j][2], d2[mi][j][3]);
        }
}

// ---------------- colsum + template update + LN_m. grid (8 ng, 8 b) ----------------
__global__ __launch_bounds__(256) void finalize_kernel(const float* __restrict__ g,
                                                       const float* __restrict__ bb) {
    __shared__ float tv[8*256];
    __shared__ float csin_s[8];
    int ng = blockIdx.x, b = blockIdx.y, t = threadIdx.x;
    {
        int s = t >> 5, l = t & 31;
        int n = ng*8 + s;
        float v = g_colsum_part[((size_t)b*64 + l)*NSLOT + n];
        #pragma unroll
        for (int m = 16; m; m >>= 1) v += __shfl_xor_sync(0xffffffffu, v, m);
        if (l == 0) { csin_s[s] = 1.0f / v; g_colsum[b*NSLOT + n] = v; }
    }
    __syncthreads();
    #pragma unroll
    for (int s = 0; s < 8; s++) {
        int n = ng*8 + s;
        float acc = 0.f;
        #pragma unroll 8
        for (int p = 0; p < 32; p++)
            acc += g_accpart[((size_t)(p*BATCH + b)*NSLOT + n)*DIM + t];
        size_t idx = ((size_t)(b*NSLOT) + n)*DIM + t;
        float val = g_templates[idx] + acc * csin_s[s];
        g_templates[idx] = val;
        tv[s*256 + t] = val;
    }
    __syncthreads();
    {
        int w = t >> 5, l = t & 31;
        const float* row = tv + w*256;
        float s1 = 0.f, s2 = 0.f;
        #pragma unroll
        for (int i = l; i < 256; i += 32) { float v = row[i]; s1 += v; s2 += v*v; }
        #pragma unroll
        for (int m = 16; m; m >>= 1) {
            s1 += __shfl_xor_sync(0xffffffffu, s1, m);
            s2 += __shfl_xor_sync(0xffffffffu, s2, m);
        }
        float mu = s1 * (1.f/256.f);
        float rs = rsqrtf(s2 * (1.f/256.f) - mu*mu + 1e-5f);
        int n = ng*8 + w;
        float* drow = g_tbuf + ((size_t)(b*NSLOT) + n)*DIM;
        #pragma unroll
        for (int i = l; i < 256; i += 32)
            drow[i] = (row[i] - mu)*rs*g[i] + bb[i];
    }
}

// ---------------- hidden = GELU(tbuf @ W1 + b1), full preload ----------------
#define GEMMH_SMEM ((16384 + 16384)*4)
__global__ __launch_bounds__(256) void gemm_h_kernel(const float* __restrict__ W1,
                                                     const float* __restrict__ b1)
{
    extern __shared__ float smf[];
    float* Af = smf; float* Bf = smf + 16384;
    int b = blockIdx.y; int nc = blockIdx.x * 64;
    int t = threadIdx.x;
    int kk0 = t >> 4, n4 = (t & 15)*4;
    #pragma unroll
    for (int k0 = 0; k0 < 256; k0 += 16)
        *(float4*)(Bf + (k0 + kk0)*64 + n4) = *(const float4*)(W1 + (size_t)(k0+kk0)*512 + nc + n4);
    {
        int r = t >> 2, part = t & 3;
        const float* row = g_tbuf + ((size_t)(b*NSLOT) + r)*DIM + part*64;
        #pragma unroll
        for (int i = 0; i < 64; i += 4) {
            float4 v = *(const float4*)(row + i);
            Af[(part*64+i+0)*64 + r] = v.x;
            Af[(part*64+i+1)*64 + r] = v.y;
            Af[(part*64+i+2)*64 + r] = v.z;
            Af[(part*64+i+3)*64 + r] = v.w;
        }
    }
    __syncthreads();
    int tm = t >> 4, tn = t & 15;
    u64 acc[4][2] = {};
    for (int k0 = 0; k0 < 256; k0 += 16) {
        #pragma unroll
        for (int kk = 0; kk < 16; kk++) {
            ulonglong2 a2 = *(ulonglong2*)(Af + (k0+kk)*64 + tm*4);
            float4 bb = *(float4*)(Bf + (k0+kk)*64 + tn*4);
            u64 q0 = PK1(bb.x), q1 = PK1(bb.y), q2 = PK1(bb.z), q3 = PK1(bb.w);
            FMA2(acc[0][0], a2.x, q0); FMA2(acc[0][1], a2.y, q0);
            FMA2(acc[1][0], a2.x, q1); FMA2(acc[1][1], a2.y, q1);
            FMA2(acc[2][0], a2.x, q2); FMA2(acc[2][1], a2.y, q2);
            FMA2(acc[3][0], a2.x, q3); FMA2(acc[3][1], a2.y, q3);
        }
    }
    float4 bv = *(const float4*)(b1 + nc + tn*4);
    #pragma unroll
    for (int p = 0; p < 2; p++) {
        float2 f0 = UPK(acc[0][p]), f1 = UPK(acc[1][p]), f2 = UPK(acc[2][p]), f3 = UPK(acc[3][p]);
        float4 r0 = {gelu_exact(f0.x+bv.x), gelu_exact(f1.x+bv.y), gelu_exact(f2.x+bv.z), gelu_exact(f3.x+bv.w)};
        float4 r1 = {gelu_exact(f0.y+bv.x), gelu_exact(f1.y+bv.y), gelu_exact(f2.y+bv.z), gelu_exact(f3.y+bv.w)};
        int mm = tm*4 + p*2;
        *(float4*)(g_hidden + ((size_t)(b*NSLOT) + mm  )*512 + nc + tn*4) = r0;
        *(float4*)(g_hidden + ((size_t)(b*NSLOT) + mm+1)*512 + nc + tn*4) = r1;
    }
}

// ---------------- templates += hidden @ W2 + b2, 2-phase preload ----------------
#define GEMMO_SMEM ((16384 + 16384)*4)
__global__ __launch_bounds__(256) void gemm_o_kernel(const float* __restrict__ W2,
                                                     const float* __restrict__ b2)
{
    extern __shared__ float smf[];
    float* Af = smf; float* Bf = smf + 16384;
    int b = blockIdx.y; int nc = blockIdx.x * 64;
    int t = threadIdx.x;
    int kk0 = t >> 4, n4 = (t & 15)*4;
    int tm = t >> 4, tn = t & 15;
    u64 acc[4][2] = {};
    for (int hc = 0; hc < 2; hc++) {
        // B-half preload (16 independent loads)
        #pragma unroll
        for (int k0 = 0; k0 < 256; k0 += 16)
            *(float4*)(Bf + (k0 + kk0)*64 + n4) =
                *(const float4*)(W2 + (size_t)(hc*256 + k0 + kk0)*256 + nc + n4);
        // A-half staging (transposed)
        {
            int r = t >> 2, part = t & 3;
            const float* row = g_hidden + ((size_t)(b*NSLOT) + r)*512 + hc*256 + part*64;
            #pragma unroll
            for (int i = 0; i < 64; i += 4) {
                float4 v = *(const float4*)(row + i);
                Af[(part*64+i+0)*64 + r] = v.x;
                Af[(part*64+i+1)*64 + r] = v.y;
                Af[(part*64+i+2)*64 + r] = v.z;
                Af[(part*64+i+3)*64 + r] = v.w;
            }
        }
        __syncthreads();
        for (int k0 = 0; k0 < 256; k0 += 16) {
            #pragma unroll
            for (int kk = 0; kk < 16; kk++) {
                ulonglong2 a2 = *(ulonglong2*)(Af + (k0+kk)*64 + tm*4);
                float4 bb = *(float4*)(Bf + (k0+kk)*64 + tn*4);
                u64 q0 = PK1(bb.x), q1 = PK1(bb.y), q2 = PK1(bb.z), q3 = PK1(bb.w);
                FMA2(acc[0][0], a2.x, q0); FMA2(acc[0][1], a2.y, q0);
                FMA2(acc[1][0], a2.x, q1); FMA2(acc[1][1], a2.y, q1);
                FMA2(acc[2][0], a2.x, q2); FMA2(acc[2][1], a2.y, q2);
                FMA2(acc[3][0], a2.x, q3); FMA2(acc[3][1], a2.y, q3);
            }
        }
        __syncthreads();
    }
    float4 bv = *(const float4*)(b2 + nc + tn*4);
    #pragma unroll
    for (int p = 0; p < 2; p++) {
        float2 f0 = UPK(acc[0][p]), f1 = UPK(acc[1][p]), f2 = UPK(acc[2][p]), f3 = UPK(acc[3][p]);
        int mm = tm*4 + p*2;
        float* C0 = g_templates + ((size_t)(b*NSLOT) + mm)*DIM + nc + tn*4;
        float4 c0 = *(float4*)C0;
        c0.x += f0.x + bv.x; c0.y += f1.x + bv.y; c0.z += f2.x + bv.z; c0.w += f3.x + bv.w;
        *(float4*)C0 = c0;
        float* C1 = C0 + DIM;
        float4 c1 = *(float4*)C1;
        c1.x += f0.y + bv.x; c1.y += f1.y + bv.y; c1.z += f2.y + bv.z; c1.w += f3.y + bv.w;
        *(float4*)C1 = c1;
    }
}

// ---------------- outputs ----------------
__global__ void out_templates_kernel(float* __restrict__ out) {
    int b = blockIdx.x, d = threadIdx.x;
    for (int n = 0; n < NSLOT; n++)
        out[((size_t)(b*DIM) + d)*NSLOT + n] = g_templates[((size_t)(b*NSLOT) + n)*DIM + d];
}

__global__ void out_attn_kernel(float* __restrict__ out) {
    int n = blockIdx.x, b = blockIdx.y, t = threadIdx.x;
    float inv = 1.0f / g_colsum[b*NSLOT + n];
    size_t base = (size_t)BATCH*DIM*NSLOT + ((size_t)(b*NSLOT + n))*LTOK;
    for (int k = 0; k < 16; k++) {
        int l = k*256 + t;
        out[base + l] = g_attn[((size_t)b*LTOK + l)*NSLOT + n] * inv;
    }
}

// ---------------- launch ----------------
extern "C" void kernel_launch(void* const* d_in, const int* in_sizes, int n_in,
                              void* d_out, int out_size) {
    const float* x       = (const float*)d_in[0];
    const float* tinit   = (const float*)d_in[1];
    const float* conv_w  = (const float*)d_in[2];
    const float* conv_b  = (const float*)d_in[3];
    const float* Wq      = (const float*)d_in[4];
    const float* Wk      = (const float*)d_in[5];
    const float* Wv      = (const float*)d_in[6];
    const float* ln_in_g = (const float*)d_in[7];
    const float* ln_in_b = (const float*)d_in[8];
    const float* ln_t_g  = (const float*)d_in[9];
    const float* ln_t_b  = (const float*)d_in[10];
    const float* ln_m_g  = (const float*)d_in[11];
    const float* ln_m_b  = (const float*)d_in[12];
    const float* W1      = (const float*)d_in[13];
    const float* b1      = (const float*)d_in[14];
    const float* W2      = (const float*)d_in[15];
    const float* b2      = (const float*)d_in[16];
    float* out = (float*)d_out;

    cudaFuncSetAttribute(conv_mma_kernel, cudaFuncAttributeMaxDynamicSharedMemorySize, CMM_SMEM);
    cudaFuncSetAttribute(kv_mma_kernel, cudaFuncAttributeMaxDynamicSharedMemorySize, CMM_SMEM);
    cudaFuncSetAttribute(attn_gc_kernel, cudaFuncAttributeMaxDynamicSharedMemorySize, AGC_SMEM);
    cudaFuncSetAttribute(gemm_q_kernel, cudaFuncAttributeMaxDynamicSharedMemorySize, GEMMQ_SMEM);
    cudaFuncSetAttribute(gemm_h_kernel, cudaFuncAttributeMaxDynamicSharedMemorySize, GEMMH_SMEM);
    cudaFuncSetAttribute(gemm_o_kernel, cudaFuncAttributeMaxDynamicSharedMemorySize, GEMMO_SMEM);

    templates_init_kernel<<<8, 256>>>(tinit);
    xsplit_kernel<<<8*33*33, 256>>>(x);
    cwsplit_kernel<<<3456, 256>>>(conv_w);
    kvsplit_kernel<<<512, 256>>>(Wk, Wv);
    conv_mma_kernel<<<256, 512, CMM_SMEM>>>(conv_b, ln_in_g, ln_in_b);
    kv_mma_kernel<<<512, 512, CMM_SMEM>>>();

    for (int it = 0; it < 6; it++) {
        gemm_q_kernel<<<dim3(4, 8), 256, GEMMQ_SMEM>>>(Wq, ln_t_g, ln_t_b);
        attn_gc_kernel<<<dim3(32, 8), 256, AGC_SMEM>>>(it == 5 ? 1 : 0);
        finalize_kernel<<<dim3(8, 8), 256>>>(ln_m_g, ln_m_b);
        gemm_h_kernel<<<dim3(8, 8), 256, GEMMH_SMEM>>>(W1, b1);
        gemm_o_kernel<<<dim3(4, 8), 256, GEMMO_SMEM>>>(W2, b2);
    }

    out_templates_kernel<<<8, 256>>>(out);
    out_attn_kernel<<<dim3(64, 8), 256>>>(out);
}

// round 15
// speedup vs baseline: 1.7697x; 1.0260x over previous
#include <cuda_runtime.h>
#include <cuda_bf16.h>
#include <stdint.h>
#include <math.h>

#define BATCH 8
#define DIM   256
#define NSLOT 64
#define LTOK  4096

typedef unsigned long long u64;

__device__ __forceinline__ u64 PK1(float v) {
    u64 r; asm("mov.b64 %0, {%1,%1};" : "=l"(r) : "f"(v)); return r;
}
__device__ __forceinline__ void FMA2(u64& d, u64 a, u64 b) {
    asm("fma.rn.f32x2 %0, %1, %2, %0;" : "+l"(d) : "l"(a), "l"(b));
}
__device__ __forceinline__ float2 UPK(u64 v) {
    float2 f; asm("mov.b64 {%0,%1}, %2;" : "=f"(f.x), "=f"(f.y) : "l"(v)); return f;
}

// ---------------- scratch ----------------
__device__ float g_templates[BATCH*NSLOT*DIM];
__device__ float g_tbuf[BATCH*NSLOT*DIM];
__device__ float g_attn[BATCH*LTOK*NSLOT];
__device__ float g_colsum_part[BATCH*64*NSLOT];
__device__ float g_colsum[BATCH*NSLOT];
__device__ float g_accpart[32*BATCH*NSLOT*DIM];
__device__ float g_hidden[BATCH*NSLOT*512];
// bf16 split operands
__device__ __nv_bfloat16 g_xh[36799488];
__device__ __nv_bfloat16 g_xl[36799488];
__device__ __nv_bfloat16 g_cwh[27*32768];
__device__ __nv_bfloat16 g_cwl[27*32768];
__device__ __nv_bfloat16 g_kvh[256*512];
__device__ __nv_bfloat16 g_kvl[256*512];
__device__ __nv_bfloat16 g_toksh[32768*256];
__device__ __nv_bfloat16 g_toksl[32768*256];
__device__ __nv_bfloat16 g_kh[32768*256];
__device__ __nv_bfloat16 g_kl[32768*256];
__device__ __nv_bfloat16 g_vh[32768*256];
__device__ __nv_bfloat16 g_vl[32768*256];
__device__ __nv_bfloat16 g_qh[BATCH*NSLOT*DIM];
__device__ __nv_bfloat16 g_ql[BATCH*NSLOT*DIM];

__device__ __forceinline__ float gelu_exact(float v) {
    return 0.5f * v * (1.0f + erff(v * 0.70710678118654752f));
}

// ========== mma.sync helpers ==========
__device__ __forceinline__ uint32_t smem_u32(const void* p) {
    uint32_t a;
    asm("{ .reg .u64 t; cvta.to.shared.u64 t, %1; cvt.u32.u64 %0, t; }" : "=r"(a) : "l"(p));
    return a;
}
__device__ __forceinline__ void ldsm_x4(uint32_t* r, uint32_t addr) {
    asm volatile("ldmatrix.sync.aligned.m8n8.x4.shared.b16 {%0,%1,%2,%3}, [%4];"
        : "=r"(r[0]), "=r"(r[1]), "=r"(r[2]), "=r"(r[3]) : "r"(addr));
}
__device__ __forceinline__ void ldsm_x4_t(uint32_t* r, uint32_t addr) {
    asm volatile("ldmatrix.sync.aligned.m8n8.x4.trans.shared.b16 {%0,%1,%2,%3}, [%4];"
        : "=r"(r[0]), "=r"(r[1]), "=r"(r[2]), "=r"(r[3]) : "r"(addr));
}
__device__ __forceinline__ void mma_bf16(float* d, const uint32_t* a, const uint32_t* b) {
    asm volatile("mma.sync.aligned.m16n8k16.row.col.f32.bf16.bf16.f32 "
        "{%0,%1,%2,%3}, {%4,%5,%6,%7}, {%8,%9}, {%0,%1,%2,%3};"
        : "+f"(d[0]), "+f"(d[1]), "+f"(d[2]), "+f"(d[3])
        : "r"(a[0]), "r"(a[1]), "r"(a[2]), "r"(a[3]), "r"(b[0]), "r"(b[1]));
}
__device__ __forceinline__ void bsplit(float v0, float v1, __nv_bfloat162& hh, __nv_bfloat162& ll) {
    __nv_bfloat16 h0 = __float2bfloat16(v0), h1 = __float2bfloat16(v1);
    hh.x = h0; hh.y = h1;
    ll.x = __float2bfloat16(v0 - __bfloat162float(h0));
    ll.y = __float2bfloat16(v1 - __bfloat162float(h1));
}
__device__ __forceinline__ void cpa16(uint32_t dst, const void* src) {
    asm volatile("cp.async.cg.shared.global [%0], [%1], 16;" :: "r"(dst), "l"(src) : "memory");
}
#define CP_COMMIT asm volatile("cp.async.commit_group;" ::: "memory")
#define CP_WAIT0  asm volatile("cp.async.wait_group 0;" ::: "memory")

// 128x256 += A(128x128, pitch 272B) x B(128k x 256n, pitch 528B); 3-term bf16 split.
__device__ __forceinline__ void mma_chunk(
    uint32_t sAh, uint32_t sAl, uint32_t sBh, uint32_t sBl,
    float d[2][8][4], int wm, int wn, int lane)
{
    uint32_t aoff0 = (uint32_t)((wm*32 + (lane & 15))*272 + (lane >> 4)*16);
    uint32_t boff0 = (uint32_t)((lane & 15)*528 + (wn*64 + (lane >> 4)*8)*2);
    #pragma unroll
    for (int kk = 0; kk < 8; kk++) {
        uint32_t ah[8], al[8], bb[16];
        uint32_t ao = aoff0 + kk*32;
        ldsm_x4(ah,     sAh + ao);
        ldsm_x4(ah + 4, sAh + ao + 4352);
        ldsm_x4(al,     sAl + ao);
        ldsm_x4(al + 4, sAl + ao + 4352);
        uint32_t bo = boff0 + kk*8448;
        #pragma unroll
        for (int jj = 0; jj < 4; jj++) ldsm_x4_t(bb + jj*4, sBh + bo + jj*32);
        #pragma unroll
        for (int mi = 0; mi < 2; mi++) {
            #pragma unroll
            for (int j = 0; j < 8; j++) {
                const uint32_t* bf = bb + (j >> 1)*4 + (j & 1)*2;
                mma_bf16(d[mi][j], mi ? ah + 4 : ah, bf);
                mma_bf16(d[mi][j], mi ? al + 4 : al, bf);
            }
        }
        #pragma unroll
        for (int jj = 0; jj < 4; jj++) ldsm_x4_t(bb + jj*4, sBl + bo + jj*32);
        #pragma unroll
        for (int mi = 0; mi < 2; mi++) {
            #pragma unroll
            for (int j = 0; j < 8; j++) {
                const uint32_t* bf = bb + (j >> 1)*4 + (j & 1)*2;
                mma_bf16(d[mi][j], mi ? ah + 4 : ah, bf);
            }
        }
    }
}

// dual-term pass: d += Ah*B + Al*B
__device__ __forceinline__ void mma_dual(
    uint32_t sAh, uint32_t sAl, uint32_t sB,
    float d[2][8][4], int wm, int wn, int lane)
{
    uint32_t aoff0 = (uint32_t)((wm*32 + (lane & 15))*272 + (lane >> 4)*16);
    uint32_t boff0 = (uint32_t)((lane & 15)*528 + (wn*64 + (lane >> 4)*8)*2);
    #pragma unroll
    for (int kk = 0; kk < 8; kk++) {
        uint32_t ah[8], al[8], bb[16];
        uint32_t ao = aoff0 + kk*32;
        ldsm_x4(ah,     sAh + ao);
        ldsm_x4(ah + 4, sAh + ao + 4352);
        ldsm_x4(al,     sAl + ao);
        ldsm_x4(al + 4, sAl + ao + 4352);
        uint32_t bo = boff0 + kk*8448;
        #pragma unroll
        for (int jj = 0; jj < 4; jj++) ldsm_x4_t(bb + jj*4, sB + bo + jj*32);
        #pragma unroll
        for (int mi = 0; mi < 2; mi++) {
            #pragma unroll
            for (int j = 0; j < 8; j++) {
                const uint32_t* bf = bb + (j >> 1)*4 + (j & 1)*2;
                mma_bf16(d[mi][j], mi ? ah + 4 : ah, bf);
                mma_bf16(d[mi][j], mi ? al + 4 : al, bf);
            }
        }
    }
}

// single-term pass: d += Ah*B
__device__ __forceinline__ void mma_single(
    uint32_t sAh, uint32_t sB,
    float d[2][8][4], int wm, int wn, int lane)
{
    uint32_t aoff0 = (uint32_t)((wm*32 + (lane & 15))*272 + (lane >> 4)*16);
    uint32_t boff0 = (uint32_t)((lane & 15)*528 + (wn*64 + (lane >> 4)*8)*2);
    #pragma unroll
    for (int kk = 0; kk < 8; kk++) {
        uint32_t ah[8], bb[16];
        uint32_t ao = aoff0 + kk*32;
        ldsm_x4(ah,     sAh + ao);
        ldsm_x4(ah + 4, sAh + ao + 4352);
        uint32_t bo = boff0 + kk*8448;
        #pragma unroll
        for (int jj = 0; jj < 4; jj++) ldsm_x4_t(bb + jj*4, sB + bo + jj*32);
        #pragma unroll
        for (int mi = 0; mi < 2; mi++) {
            #pragma unroll
            for (int j = 0; j < 8; j++) {
                const uint32_t* bf = bb + (j >> 1)*4 + (j & 1)*2;
                mma_bf16(d[mi][j], mi ? ah + 4 : ah, bf);
            }
        }
    }
}

// ---------------- prep kernels ----------------
__global__ void templates_init_kernel(const float* __restrict__ tinit) {
    int b = blockIdx.x, t = threadIdx.x;
    for (int n = 0; n < NSLOT; n++)
        g_templates[(b*NSLOT + n)*DIM + t] = tinit[n*DIM + t];
}

__global__ __launch_bounds__(256) void xsplit_kernel(const float* __restrict__ x) {
    __shared__ float st[128*33];
    int bid = blockIdx.x; int b = bid / 1089; int rem = bid % 1089; int d = rem / 33, h = rem % 33;
    int t = threadIdx.x, warp = t >> 5, lane = t & 31;
    const float* xb = x + ((((size_t)b*128)*33 + d)*33 + h)*33;
    for (int c = warp; c < 128; c += 8) {
        const float* src = xb + (size_t)c*35937;
        st[c*33 + lane] = src[lane];
        if (lane == 0) st[c*33 + 32] = src[32];
    }
    __syncthreads();
    size_t ob = ((((size_t)b*33 + d)*33 + h)*33)*128;
    for (int i = t; i < 33*128; i += 256) {
        int w = i >> 7, c = i & 127;
        float v = st[c*33 + w];
        __nv_bfloat16 hi = __float2bfloat16(v);
        g_xh[ob + (size_t)w*128 + c] = hi;
        g_xl[ob + (size_t)w*128 + c] = __float2bfloat16(v - __bfloat162float(hi));
    }
}

__global__ void cwsplit_kernel(const float* __restrict__ cw) {
    int idx = blockIdx.x*256 + threadIdx.x;
    int tap = idx >> 15, r = idx & 32767;
    int k = r >> 8, n = r & 255;
    float v = cw[(size_t)n*3456 + k*27 + tap];
    __nv_bfloat16 hi = __float2bfloat16(v);
    g_cwh[idx] = hi;
    g_cwl[idx] = __float2bfloat16(v - __bfloat162float(hi));
}

__global__ void kvsplit_kernel(const float* __restrict__ Wk, const float* __restrict__ Wv) {
    int idx = blockIdx.x*256 + threadIdx.x;
    int k = idx >> 9, c512 = idx & 511;
    int mat = c512 >> 8, col = c512 & 255;
    const float* W = mat ? Wv : Wk;
    float v = W[(size_t)k*256 + col];
    __nv_bfloat16 hi = __float2bfloat16(v);
    g_kvh[idx] = hi;
    g_kvl[idx] = __float2bfloat16(v - __bfloat162float(hi));
}

// ---------------- conv (implicit GEMM, cp.async-pipelined B) + bias + ReLU + LN ----------------
#define CMM_SMEM 204800
__global__ __launch_bounds__(512, 1) void conv_mma_kernel(
    const float* __restrict__ convb, const float* __restrict__ lng, const float* __restrict__ lnb)
{
    extern __shared__ char sm[];
    uint32_t sb = smem_u32(sm);
    const uint32_t oAh = 0, oAl = 34816, oB0 = 69632, oB1 = 137216;
    int t = threadIdx.x, lane = t & 31, wid = t >> 5;
    int wm = wid >> 2, wn = wid & 3;
    int bx = blockIdx.x; int b = bx >> 5, xd = (bx >> 1) & 15, half = bx & 1;

    float d[2][8][4];
    #pragma unroll
    for (int i = 0; i < 2; i++)
        #pragma unroll
        for (int j = 0; j < 8; j++)
            #pragma unroll
            for (int c = 0; c < 4; c++) d[i][j][c] = 0.f;

    int m = t >> 2, q = t & 3;
    int xhl = m >> 4, xw = m & 15;

    {
        const uint4* s1 = (const uint4*)(g_cwh);
        #pragma unroll
        for (int it = 0; it < 8; it++) {
            int i = t + it*512;
            cpa16(sb + oB0 + (uint32_t)((i >> 5)*528 + (i & 31)*16), s1 + i);
        }
        CP_COMMIT;
    }

    for (int tap = 0; tap < 27; tap++) {
        int kd = tap/9, r9 = tap%9, kh = r9/3, kw = r9%3;
        {
            size_t xi = ((((size_t)(b*33) + 2*xd + kd)*33 + 2*(half*8 + xhl) + kh)*33 + 2*xw + kw)*128 + q*32;
            const uint4* shi = (const uint4*)(g_xh + xi);
            const uint4* slo = (const uint4*)(g_xl + xi);
            char* dh = sm + oAh + m*272 + q*64;
            char* dl = sm + oAl + m*272 + q*64;
            #pragma unroll
            for (int j = 0; j < 4; j++) {
                *(uint4*)(dh + j*16) = shi[j];
                *(uint4*)(dl + j*16) = slo[j];
            }
        }
        CP_WAIT0;
        __syncthreads();
        {
            const uint4* s2 = (const uint4*)(g_cwl + tap*32768);
            #pragma unroll
            for (int it = 0; it < 8; it++) {
                int i = t + it*512;
                cpa16(sb + oB1 + (uint32_t)((i >> 5)*528 + (i & 31)*16), s2 + i);
            }
            CP_COMMIT;
        }
        mma_dual(sb + oAh, sb + oAl, sb + oB0, d, wm, wn, lane);
        CP_WAIT0;
        __syncthreads();
        if (tap < 26) {
            const uint4* s1 = (const uint4*)(g_cwh + (tap+1)*32768);
            #pragma unroll
            for (int it = 0; it < 8; it++) {
                int i = t + it*512;
                cpa16(sb + oB0 + (uint32_t)((i >> 5)*528 + (i & 31)*16), s1 + i);
            }
            CP_COMMIT;
        }
        mma_single(sb + oAh, sb + oB1, d, wm, wn, lane);
        __syncthreads();
    }

    float* stg = (float*)sm;
    {
        int r0 = wm*32 + (lane >> 2);
        int c0 = wn*64 + (lane & 3)*2;
        #pragma unroll
        for (int mi = 0; mi < 2; mi++)
            #pragma unroll
            for (int j = 0; j < 8; j++) {
                int rr = r0 + mi*16, cc = c0 + j*8;
                *(float2*)(stg + (size_t)rr*264 + cc)     = make_float2(d[mi][j][0], d[mi][j][1]);
                *(float2*)(stg + (size_t)(rr+8)*264 + cc) = make_float2(d[mi][j][2], d[mi][j][3]);
            }
    }
    __syncthreads();

    {
        int tok = t >> 2, q2 = t & 3;
        const float* src = stg + (size_t)tok*264 + q2*64;
        float z[64];
        float s = 0.f, sq = 0.f;
        #pragma unroll
        for (int i = 0; i < 64; i++) {
            float v = fmaxf(src[i] + convb[q2*64 + i], 0.f);
            z[i] = v; s += v; sq += v*v;
        }
        s  += __shfl_xor_sync(0xffffffffu, s, 1);  s  += __shfl_xor_sync(0xffffffffu, s, 2);
        sq += __shfl_xor_sync(0xffffffffu, sq, 1); sq += __shfl_xor_sync(0xffffffffu, sq, 2);
        float mu = s * (1.f/256.f);
        float rs = rsqrtf(sq * (1.f/256.f) - mu*mu + 1e-5f);
        int l = (xd*16 + half*8 + (tok >> 4))*16 + (tok & 15);
        size_t tg = ((size_t)b*4096 + l)*256 + q2*64;
        #pragma unroll
        for (int i = 0; i < 64; i += 2) {
            int ch = q2*64 + i;
            float v0 = (z[i]   - mu)*rs*lng[ch]   + lnb[ch];
            float v1 = (z[i+1] - mu)*rs*lng[ch+1] + lnb[ch+1];
            __nv_bfloat162 hh, ll;
            bsplit(v0, v1, hh, ll);
            *(__nv_bfloat162*)(g_toksh + tg + i) = hh;
            *(__nv_bfloat162*)(g_toksl + tg + i) = ll;
        }
    }
}

// ---------------- K/V projection via mma.sync -> bf16 split outputs ----------------
__global__ __launch_bounds__(512, 1) void kv_mma_kernel() {
    extern __shared__ char sm[];
    uint32_t sb = smem_u32(sm);
    const uint32_t oAh = 0, oAl = 34816, oBh = 69632, oBl = 137216;
    int t = threadIdx.x, lane = t & 31, wid = t >> 5;
    int wm = wid >> 2, wn = wid & 3;
    int nhalf = blockIdx.x & 1, chunk = blockIdx.x >> 1;

    float d[2][8][4];
    #pragma unroll
    for (int i = 0; i < 2; i++)
        #pragma unroll
        for (int j = 0; j < 8; j++)
            #pragma unroll
            for (int c = 0; c < 4; c++) d[i][j][c] = 0.f;

    int m = t >> 2, q = t & 3;
    for (int kc = 0; kc < 2; kc++) {
        {
            size_t ti = ((size_t)(chunk*128 + m))*256 + kc*128 + q*32;
            const uint4* shi = (const uint4*)(g_toksh + ti);
            const uint4* slo = (const uint4*)(g_toksl + ti);
            char* dh = sm + oAh + m*272 + q*64;
            char* dl = sm + oAl + m*272 + q*64;
            #pragma unroll
            for (int j = 0; j < 4; j++) {
                *(uint4*)(dh + j*16) = shi[j];
                *(uint4*)(dl + j*16) = slo[j];
            }
        }
        {
            #pragma unroll
            for (int it = 0; it < 8; it++) {
                int i = t + it*512;
                int row = i >> 5, seg = i & 31;
                size_t off = (size_t)(kc*128 + row)*512 + nhalf*256 + seg*8;
                *(uint4*)(sm + oBh + row*528 + seg*16) = *(const uint4*)(g_kvh + off);
                *(uint4*)(sm + oBl + row*528 + seg*16) = *(const uint4*)(g_kvl + off);
            }
        }
        __syncthreads();
        mma_chunk(sb + oAh, sb + oAl, sb + oBh, sb + oBl, d, wm, wn, lane);
        __syncthreads();
    }

    __nv_bfloat16* dh = nhalf ? g_vh : g_kh;
    __nv_bfloat16* dl = nhalf ? g_vl : g_kl;
    int r0 = wm*32 + (lane >> 2);
    int c0 = wn*64 + (lane & 3)*2;
    #pragma unroll
    for (int mi = 0; mi < 2; mi++)
        #pragma unroll
        for (int j = 0; j < 8; j++) {
            int rr = r0 + mi*16, cc = c0 + j*8;
            size_t tok = (size_t)chunk*128 + rr;
            __nv_bfloat162 hh, ll;
            bsplit(d[mi][j][0], d[mi][j][1], hh, ll);
            *(__nv_bfloat162*)(dh + tok*256 + cc) = hh;
            *(__nv_bfloat162*)(dl + tok*256 + cc) = ll;
            bsplit(d[mi][j][2], d[mi][j][3], hh, ll);
            *(__nv_bfloat162*)(dh + (tok+8)*256 + cc) = hh;
            *(__nv_bfloat162*)(dl + (tok+8)*256 + cc) = ll;
        }
}

// ---------------- fused LN_t + q-GEMM (full B preload, sync-free compute) ----------------
#define GEMMQ_SMEM ((16384 + 16384)*4)
__global__ __launch_bounds__(256) void gemm_q_kernel(
    const float* __restrict__ Wq, const float* __restrict__ lng, const float* __restrict__ lnb)
{
    extern __shared__ float smf[];
    float* Af = smf; float* Bf = smf + 16384;
    int b = blockIdx.y; int nc = blockIdx.x * 64;
    int t = threadIdx.x;
    int kk0 = t >> 4, n4 = (t & 15)*4;
    #pragma unroll
    for (int k0 = 0; k0 < 256; k0 += 16)
        *(float4*)(Bf + (k0 + kk0)*64 + n4) = *(const float4*)(Wq + (size_t)(k0+kk0)*256 + nc + n4);
    {
        int r = t >> 2, part = t & 3;
        const float* row = g_templates + ((size_t)(b*NSLOT) + r)*DIM + part*64;
        float s = 0.f, sq = 0.f;
        #pragma unroll
        for (int i = 0; i < 64; i += 4) {
            float4 v = *(const float4*)(row + i);
            s += v.x+v.y+v.z+v.w;
            sq += v.x*v.x + v.y*v.y + v.z*v.z + v.w*v.w;
        }
        s  += __shfl_xor_sync(0xffffffffu, s, 1);  s  += __shfl_xor_sync(0xffffffffu, s, 2);
        sq += __shfl_xor_sync(0xffffffffu, sq, 1); sq += __shfl_xor_sync(0xffffffffu, sq, 2);
        float mu = s * (1.0f/256.0f);
        float rs = rsqrtf(sq * (1.0f/256.0f) - mu*mu + 1e-5f);
        #pragma unroll
        for (int i = 0; i < 64; i += 4) {
            float4 v = *(const float4*)(row + i);
            float4 gg = *(const float4*)(lng + part*64 + i);
            float4 bv = *(const float4*)(lnb + part*64 + i);
            Af[(part*64+i+0)*64 + r] = (v.x - mu)*rs*gg.x + bv.x;
            Af[(part*64+i+1)*64 + r] = (v.y - mu)*rs*gg.y + bv.y;
            Af[(part*64+i+2)*64 + r] = (v.z - mu)*rs*gg.z + bv.z;
            Af[(part*64+i+3)*64 + r] = (v.w - mu)*rs*gg.w + bv.w;
        }
    }
    __syncthreads();

    int tm = t >> 4, tn = t & 15;
    u64 acc[4][2] = {};
    for (int k0 = 0; k0 < 256; k0 += 16) {
        #pragma unroll
        for (int kk = 0; kk < 16; kk++) {
            ulonglong2 a2 = *(ulonglong2*)(Af + (k0+kk)*64 + tm*4);
            float4 bb = *(float4*)(Bf + (k0+kk)*64 + tn*4);
            u64 q0 = PK1(bb.x), q1 = PK1(bb.y), q2 = PK1(bb.z), q3 = PK1(bb.w);
            FMA2(acc[0][0], a2.x, q0); FMA2(acc[0][1], a2.y, q0);
            FMA2(acc[1][0], a2.x, q1); FMA2(acc[1][1], a2.y, q1);
            FMA2(acc[2][0], a2.x, q2); FMA2(acc[2][1], a2.y, q2);
            FMA2(acc[3][0], a2.x, q3); FMA2(acc[3][1], a2.y, q3);
        }
    }
    const float scale = 0.0625f;
    #pragma unroll
    for (int p = 0; p < 2; p++) {
        float2 f0 = UPK(acc[0][p]), f1 = UPK(acc[1][p]), f2 = UPK(acc[2][p]), f3 = UPK(acc[3][p]);
        int mm = tm*4 + p*2;
        size_t o0 = ((size_t)(b*NSLOT) + mm)*DIM + nc + tn*4;
        __nv_bfloat162 hh, ll;
        bsplit(f0.x*scale, f1.x*scale, hh, ll);
        *(__nv_bfloat162*)(g_qh + o0) = hh; *(__nv_bfloat162*)(g_ql + o0) = ll;
        bsplit(f2.x*scale, f3.x*scale, hh, ll);
        *(__nv_bfloat162*)(g_qh + o0 + 2) = hh; *(__nv_bfloat162*)(g_ql + o0 + 2) = ll;
        bsplit(f0.y*scale, f1.y*scale, hh, ll);
        *(__nv_bfloat162*)(g_qh + o0 + DIM) = hh; *(__nv_bfloat162*)(g_ql + o0 + DIM) = ll;
        bsplit(f2.y*scale, f3.y*scale, hh, ll);
        *(__nv_bfloat162*)(g_qh + o0 + DIM + 2) = hh; *(__nv_bfloat162*)(g_ql + o0 + DIM + 2) = ll;
    }
}

// ---------------- FUSED attn logits + softmax + colsum + attn^T@v ----------------
// V prefetched via cp.async into the dead K/Q region during softmax/colsum.
#define AGC_SMEM 206848
__global__ __launch_bounds__(256) void attn_gc_kernel(int write_attn) {
    extern __shared__ char sm[];
    uint32_t sb = smem_u32(sm);
    const uint32_t oKh = 0, oKl = 34816, oQh = 69632, oQl = 87040;
    const uint32_t oStg = 135168, oAth = 169984, oAtl = 188416;
    const uint32_t oVh = 0, oVl = 67584;
    int t = threadIdx.x, lane = t & 31, wid = t >> 5;
    int lb = blockIdx.x, b = blockIdx.y;

    int wm = wid >> 1, wn = wid & 1;
    float d[2][4][4];
    #pragma unroll
    for (int i = 0; i < 2; i++)
        #pragma unroll
        for (int j = 0; j < 4; j++)
            #pragma unroll
            for (int c = 0; c < 4; c++) d[i][j][c] = 0.f;

    for (int kc = 0; kc < 2; kc++) {
        {
            int row = t >> 1, half = t & 1;
            size_t ti = ((size_t)(b*4096) + lb*128 + row)*256 + kc*128 + half*64;
            const uint4* shi = (const uint4*)(g_kh + ti);
            const uint4* slo = (const uint4*)(g_kl + ti);
            char* dh = sm + oKh + row*272 + half*128;
            char* dl = sm + oKl + row*272 + half*128;
            #pragma unroll
            for (int j = 0; j < 8; j++) {
                *(uint4*)(dh + j*16) = shi[j];
                *(uint4*)(dl + j*16) = slo[j];
            }
        }
        {
            int row = t >> 2, q4 = t & 3;
            size_t ti = ((size_t)(b*NSLOT) + row)*256 + kc*128 + q4*32;
            const uint4* shi = (const uint4*)(g_qh + ti);
            const uint4* slo = (const uint4*)(g_ql + ti);
            char* dh = sm + oQh + row*272 + q4*64;
            char* dl = sm + oQl + row*272 + q4*64;
            #pragma unroll
            for (int j = 0; j < 4; j++) {
                *(uint4*)(dh + j*16) = shi[j];
                *(uint4*)(dl + j*16) = slo[j];
            }
        }
        __syncthreads();
        uint32_t aoff0 = (uint32_t)((wm*32 + (lane & 15))*272 + (lane >> 4)*16);
        uint32_t qoff0 = (uint32_t)(((lane >> 4)*8 + (lane & 7) + wn*32)*272 + ((lane >> 3) & 1)*16);
        #pragma unroll
        for (int kk = 0; kk < 8; kk++) {
            uint32_t ah[8], al[8], qh8[8], ql8[8];
            uint32_t ao = aoff0 + kk*32;
            ldsm_x4(ah,     sb + oKh + ao);
            ldsm_x4(ah + 4, sb + oKh + ao + 16*272);
            ldsm_x4(al,     sb + oKl + ao);
            ldsm_x4(al + 4, sb + oKl + ao + 16*272);
            uint32_t qo = qoff0 + kk*32;
            ldsm_x4(qh8,     sb + oQh + qo);
            ldsm_x4(qh8 + 4, sb + oQh + qo + 16*272);
            ldsm_x4(ql8,     sb + oQl + qo);
            ldsm_x4(ql8 + 4, sb + oQl + qo + 16*272);
            #pragma unroll
            for (int mi = 0; mi < 2; mi++) {
                #pragma unroll
                for (int j = 0; j < 4; j++) {
                    const uint32_t* bh = qh8 + (j >> 1)*4 + (j & 1)*2;
                    const uint32_t* bl = ql8 + (j >> 1)*4 + (j & 1)*2;
                    const uint32_t* am = mi ? ah + 4 : ah;
                    const uint32_t* aml = mi ? al + 4 : al;
                    mma_bf16(d[mi][j], am, bh);
                    mma_bf16(d[mi][j], am, bl);
                    mma_bf16(d[mi][j], aml, bh);
                }
            }
        }
        __syncthreads();
    }

    // prefetch V into the (now dead) K/Q region, overlapped with softmax/colsum
    {
        int row = t >> 1, half = t & 1;
        size_t ti = ((size_t)(b*4096) + lb*128 + row)*256 + half*128;
        const uint4* shi = (const uint4*)(g_vh + ti);
        const uint4* slo = (const uint4*)(g_vl + ti);
        uint32_t dsh = sb + oVh + (uint32_t)(row*528 + half*256);
        uint32_t dsl = sb + oVl + (uint32_t)(row*528 + half*256);
        #pragma unroll
        for (int j = 0; j < 16; j++) {
            cpa16(dsh + j*16, shi + j);
            cpa16(dsl + j*16, slo + j);
        }
        CP_COMMIT;
    }

    float* stg = (float*)(sm + oStg);
    {
        int r0 = wm*32 + (lane >> 2);
        int c0 = wn*32 + (lane & 3)*2;
        #pragma unroll
        for (int mi = 0; mi < 2; mi++)
            #pragma unroll
            for (int j = 0; j < 4; j++) {
                int rr = r0 + mi*16, cc = c0 + j*8;
                *(float2*)(stg + rr*68 + cc)     = make_float2(d[mi][j][0], d[mi][j][1]);
                *(float2*)(stg + (rr+8)*68 + cc) = make_float2(d[mi][j][2], d[mi][j][3]);
            }
    }
    __syncthreads();

    {
        int row = t >> 1, half = t & 1;
        float* sr = stg + row*68 + half*32;
        float a[32];
        float mx = -3.4e38f;
        #pragma unroll
        for (int i = 0; i < 32; i++) { a[i] = sr[i]; mx = fmaxf(mx, a[i]); }
        mx = fmaxf(mx, __shfl_xor_sync(0xffffffffu, mx, 1));
        float s = 0.f;
        #pragma unroll
        for (int i = 0; i < 32; i++) { a[i] = expf(a[i] - mx); s += a[i]; }
        s += __shfl_xor_sync(0xffffffffu, s, 1);
        float inv = 1.0f / s;
        #pragma unroll
        for (int i = 0; i < 32; i++) { a[i] = a[i]*inv + 1e-8f; sr[i] = a[i]; }
        if (write_attn) {
            size_t gi = ((size_t)(b*4096) + lb*128 + row)*64 + half*32;
            #pragma unroll
            for (int i = 0; i < 32; i += 4)
                *(float4*)(g_attn + gi + i) = make_float4(a[i], a[i+1], a[i+2], a[i+3]);
        }
        char* dst_h = sm + oAth + row*144 + half*64;
        char* dst_l = sm + oAtl + row*144 + half*64;
        #pragma unroll
        for (int i = 0; i < 32; i += 2) {
            __nv_bfloat162 hh, ll;
            bsplit(a[i], a[i+1], hh, ll);
            *(__nv_bfloat162*)(dst_h + i*2) = hh;
            *(__nv_bfloat162*)(dst_l + i*2) = ll;
        }
    }
    __syncthreads();
    if (t < 64) {
        float s = 0.f;
        for (int r = 0; r < 128; r++) s += stg[r*68 + t];
        g_colsum_part[((size_t)b*64 + lb)*NSLOT + t] = s;
    }

    CP_WAIT0;         // V landed
    __syncthreads();

    int wm2 = wid & 1, wn2 = wid >> 1;
    float d2[2][8][4];
    #pragma unroll
    for (int i = 0; i < 2; i++)
        #pragma unroll
        for (int j = 0; j < 8; j++)
            #pragma unroll
            for (int c = 0; c < 4; c++) d2[i][j][c] = 0.f;
    {
        uint32_t aoff0 = (uint32_t)((((lane >> 4)*8 + (lane & 7)))*144 + ((lane >> 3) & 1)*16 + wm2*64);
        uint32_t boff0 = (uint32_t)((lane & 15)*528 + (wn2*64 + (lane >> 4)*8)*2);
        #pragma unroll
        for (int kk = 0; kk < 8; kk++) {
            uint32_t ah[8], al[8], bh8[16], bl8[16];
            uint32_t ao = aoff0 + kk*16*144;
            ldsm_x4_t(ah,     sb + oAth + ao);
            ldsm_x4_t(ah + 4, sb + oAth + ao + 32);
            ldsm_x4_t(al,     sb + oAtl + ao);
            ldsm_x4_t(al + 4, sb + oAtl + ao + 32);
            uint32_t bo = boff0 + kk*8448;
            #pragma unroll
            for (int jj = 0; jj < 4; jj++) ldsm_x4_t(bh8 + jj*4, sb + oVh + bo + jj*32);
            #pragma unroll
            for (int jj = 0; jj < 4; jj++) ldsm_x4_t(bl8 + jj*4, sb + oVl + bo + jj*32);
            #pragma unroll
            for (int mi = 0; mi < 2; mi++) {
                #pragma unroll
                for (int j = 0; j < 8; j++) {
                    const uint32_t* bfh = bh8 + (j >> 1)*4 + (j & 1)*2;
                    const uint32_t* bfl = bl8 + (j >> 1)*4 + (j & 1)*2;
                    const uint32_t* am = mi ? ah + 4 : ah;
                    const uint32_t* aml = mi ? al + 4 : al;
                    mma_bf16(d2[mi][j], am, bfh);
                    mma_bf16(d2[mi][j], am, bfl);
                    mma_bf16(d2[mi][j], aml, bfh);
                }
            }
        }
    }

    int r0 = wm2*32 + (lane >> 2);
    int c0 = wn2*64 + (lane & 3)*2;
    float* C = g_accpart + ((size_t)((lb*BATCH + b)*NSLOT))*DIM;
    #pragma unroll
    for (int mi = 0; mi < 2; mi++)
        #pragma unroll
        for (int j = 0; j < 8; j++) {
            int slot = r0 + mi*16, cc = c0 + j*8;
            *(float2*)(C + (size_t)slot*DIM + cc)     = make_float2(d2[mi][j][0], d2[mi][j][1]);
            *(float2*)(C + (size_t)(slot+8)*DIM + cc) = make_float2(d2[mi][j][2], d2[mi][j][3]);
        }
}

// ---------------- colsum + template update + LN_m. grid (8 ng, 8 b) ----------------
__global__ __launch_bounds__(256) void finalize_kernel(const float* __restrict__ g,
                                                       const float* __restrict__ bb) {
    __shared__ float tv[8*256];
    __shared__ float csin_s[8];
    int ng = blockIdx.x, b = blockIdx.y, t = threadIdx.x;
    {
        int s = t >> 5, l = t & 31;
        int n = ng*8 + s;
        float v = g_colsum_part[((size_t)b*64 + l)*NSLOT + n];
        #pragma unroll
        for (int m = 16; m; m >>= 1) v += __shfl_xor_sync(0xffffffffu, v, m);
        if (l == 0) { csin_s[s] = 1.0f / v; g_colsum[b*NSLOT + n] = v; }
    }
    __syncthreads();
    #pragma unroll
    for (int s = 0; s < 8; s++) {
        int n = ng*8 + s;
        float acc = 0.f;
        #pragma unroll 8
        for (int p = 0; p < 32; p++)
            acc += g_accpart[((size_t)(p*BATCH + b)*NSLOT + n)*DIM + t];
        size_t idx = ((size_t)(b*NSLOT) + n)*DIM + t;
        float val = g_templates[idx] + acc * csin_s[s];
        g_templates[idx] = val;
        tv[s*256 + t] = val;
    }
    __syncthreads();
    {
        int w = t >> 5, l = t & 31;
        const float* row = tv + w*256;
        float s1 = 0.f, s2 = 0.f;
        #pragma unroll
        for (int i = l; i < 256; i += 32) { float v = row[i]; s1 += v; s2 += v*v; }
        #pragma unroll
        for (int m = 16; m; m >>= 1) {
            s1 += __shfl_xor_sync(0xffffffffu, s1, m);
            s2 += __shfl_xor_sync(0xffffffffu, s2, m);
        }
        float mu = s1 * (1.f/256.f);
        float rs = rsqrtf(s2 * (1.f/256.f) - mu*mu + 1e-5f);
        int n = ng*8 + w;
        float* drow = g_tbuf + ((size_t)(b*NSLOT) + n)*DIM;
        #pragma unroll
        for (int i = l; i < 256; i += 32)
            drow[i] = (row[i] - mu)*rs*g[i] + bb[i];
    }
}

// ---------------- hidden = GELU(tbuf @ W1 + b1), full preload ----------------
#define GEMMH_SMEM ((16384 + 16384)*4)
__global__ __launch_bounds__(256) void gemm_h_kernel(const float* __restrict__ W1,
                                                     const float* __restrict__ b1)
{
    extern __shared__ float smf[];
    float* Af = smf; float* Bf = smf + 16384;
    int b = blockIdx.y; int nc = blockIdx.x * 64;
    int t = threadIdx.x;
    int kk0 = t >> 4, n4 = (t & 15)*4;
    #pragma unroll
    for (int k0 = 0; k0 < 256; k0 += 16)
        *(float4*)(Bf + (k0 + kk0)*64 + n4) = *(const float4*)(W1 + (size_t)(k0+kk0)*512 + nc + n4);
    {
        int r = t >> 2, part = t & 3;
        const float* row = g_tbuf + ((size_t)(b*NSLOT) + r)*DIM + part*64;
        #pragma unroll
        for (int i = 0; i < 64; i += 4) {
            float4 v = *(const float4*)(row + i);
            Af[(part*64+i+0)*64 + r] = v.x;
            Af[(part*64+i+1)*64 + r] = v.y;
            Af[(part*64+i+2)*64 + r] = v.z;
            Af[(part*64+i+3)*64 + r] = v.w;
        }
    }
    __syncthreads();
    int tm = t >> 4, tn = t & 15;
    u64 acc[4][2] = {};
    for (int k0 = 0; k0 < 256; k0 += 16) {
        #pragma unroll
        for (int kk = 0; kk < 16; kk++) {
            ulonglong2 a2 = *(ulonglong2*)(Af + (k0+kk)*64 + tm*4);
            float4 bb = *(float4*)(Bf + (k0+kk)*64 + tn*4);
            u64 q0 = PK1(bb.x), q1 = PK1(bb.y), q2 = PK1(bb.z), q3 = PK1(bb.w);
            FMA2(acc[0][0], a2.x, q0); FMA2(acc[0][1], a2.y, q0);
            FMA2(acc[1][0], a2.x, q1); FMA2(acc[1][1], a2.y, q1);
            FMA2(acc[2][0], a2.x, q2); FMA2(acc[2][1], a2.y, q2);
            FMA2(acc[3][0], a2.x, q3); FMA2(acc[3][1], a2.y, q3);
        }
    }
    float4 bv = *(const float4*)(b1 + nc + tn*4);
    #pragma unroll
    for (int p = 0; p < 2; p++) {
        float2 f0 = UPK(acc[0][p]), f1 = UPK(acc[1][p]), f2 = UPK(acc[2][p]), f3 = UPK(acc[3][p]);
        float4 r0 = {gelu_exact(f0.x+bv.x), gelu_exact(f1.x+bv.y), gelu_exact(f2.x+bv.z), gelu_exact(f3.x+bv.w)};
        float4 r1 = {gelu_exact(f0.y+bv.x), gelu_exact(f1.y+bv.y), gelu_exact(f2.y+bv.z), gelu_exact(f3.y+bv.w)};
        int mm = tm*4 + p*2;
        *(float4*)(g_hidden + ((size_t)(b*NSLOT) + mm  )*512 + nc + tn*4) = r0;
        *(float4*)(g_hidden + ((size_t)(b*NSLOT) + mm+1)*512 + nc + tn*4) = r1;
    }
}

// ---------------- templates += hidden @ W2 + b2, 2-phase preload ----------------
#define GEMMO_SMEM ((16384 + 16384)*4)
__global__ __launch_bounds__(256) void gemm_o_kernel(const float* __restrict__ W2,
                                                     const float* __restrict__ b2)
{
    extern __shared__ float smf[];
    float* Af = smf; float* Bf = smf + 16384;
    int b = blockIdx.y; int nc = blockIdx.x * 64;
    int t = threadIdx.x;
    int kk0 = t >> 4, n4 = (t & 15)*4;
    int tm = t >> 4, tn = t & 15;
    u64 acc[4][2] = {};
    for (int hc = 0; hc < 2; hc++) {
        #pragma unroll
        for (int k0 = 0; k0 < 256; k0 += 16)
            *(float4*)(Bf + (k0 + kk0)*64 + n4) =
                *(const float4*)(W2 + (size_t)(hc*256 + k0 + kk0)*256 + nc + n4);
        {
            int r = t >> 2, part = t & 3;
            const float* row = g_hidden + ((size_t)(b*NSLOT) + r)*512 + hc*256 + part*64;
            #pragma unroll
            for (int i = 0; i < 64; i += 4) {
                float4 v = *(const float4*)(row + i);
                Af[(part*64+i+0)*64 + r] = v.x;
                Af[(part*64+i+1)*64 + r] = v.y;
                Af[(part*64+i+2)*64 + r] = v.z;
                Af[(part*64+i+3)*64 + r] = v.w;
            }
        }
        __syncthreads();
        for (int k0 = 0; k0 < 256; k0 += 16) {
            #pragma unroll
            for (int kk = 0; kk < 16; kk++) {
                ulonglong2 a2 = *(ulonglong2*)(Af + (k0+kk)*64 + tm*4);
                float4 bb = *(float4*)(Bf + (k0+kk)*64 + tn*4);
                u64 q0 = PK1(bb.x), q1 = PK1(bb.y), q2 = PK1(bb.z), q3 = PK1(bb.w);
                FMA2(acc[0][0], a2.x, q0); FMA2(acc[0][1], a2.y, q0);
                FMA2(acc[1][0], a2.x, q1); FMA2(acc[1][1], a2.y, q1);
                FMA2(acc[2][0], a2.x, q2); FMA2(acc[2][1], a2.y, q2);
                FMA2(acc[3][0], a2.x, q3); FMA2(acc[3][1], a2.y, q3);
            }
        }
        __syncthreads();
    }
    float4 bv = *(const float4*)(b2 + nc + tn*4);
    #pragma unroll
    for (int p = 0; p < 2; p++) {
        float2 f0 = UPK(acc[0][p]), f1 = UPK(acc[1][p]), f2 = UPK(acc[2][p]), f3 = UPK(acc[3][p]);
        int mm = tm*4 + p*2;
        float* C0 = g_templates + ((size_t)(b*NSLOT) + mm)*DIM + nc + tn*4;
        float4 c0 = *(float4*)C0;
        c0.x += f0.x + bv.x; c0.y += f1.x + bv.y; c0.z += f2.x + bv.z; c0.w += f3.x + bv.w;
        *(float4*)C0 = c0;
        float* C1 = C0 + DIM;
        float4 c1 = *(float4*)C1;
        c1.x += f0.y + bv.x; c1.y += f1.y + bv.y; c1.z += f2.y + bv.z; c1.w += f3.y + bv.w;
        *(float4*)C1 = c1;
    }
}

// ---------------- outputs ----------------
__global__ void out_templates_kernel(float* __restrict__ out) {
    int b = blockIdx.x, d = threadIdx.x;
    for (int n = 0; n < NSLOT; n++)
        out[((size_t)(b*DIM) + d)*NSLOT + n] = g_templates[((size_t)(b*NSLOT) + n)*DIM + d];
}

// transposed copy: coalesced reads of g_attn + coalesced writes of out. grid (32, 8)
__global__ __launch_bounds__(256) void out_attn_kernel(float* __restrict__ out) {
    __shared__ float smt[128*65];
    __shared__ float inv_s[64];
    int lt = blockIdx.x, b = blockIdx.y, t = threadIdx.x;
    if (t < 64) inv_s[t] = 1.0f / g_colsum[b*NSLOT + t];
    #pragma unroll 4
    for (int i = 0; i < 32; i++) {
        int r = i*4 + (t >> 6);
        smt[r*65 + (t & 63)] = g_attn[((size_t)(b*4096) + lt*128 + r)*64 + (t & 63)];
    }
    __syncthreads();
    size_t ob = (size_t)BATCH*DIM*NSLOT + ((size_t)b*NSLOT)*LTOK + lt*128;
    for (int ng = 0; ng < 16; ng++) {
        int n = ng*4 + (t >> 6);
        float inv = inv_s[n];
        #pragma unroll
        for (int lc = 0; lc < 2; lc++) {
            int l = lc*64 + (t & 63);
            out[ob + (size_t)n*LTOK + l] = smt[l*65 + n] * inv;
        }
    }
}

// ---------------- launch ----------------
extern "C" void kernel_launch(void* const* d_in, const int* in_sizes, int n_in,
                              void* d_out, int out_size) {
    const float* x       = (const float*)d_in[0];
    const float* tinit   = (const float*)d_in[1];
    const float* conv_w  = (const float*)d_in[2];
    const float* conv_b  = (const float*)d_in[3];
    const float* Wq      = (const float*)d_in[4];
    const float* Wk      = (const float*)d_in[5];
    const float* Wv      = (const float*)d_in[6];
    const float* ln_in_g = (const float*)d_in[7];
    const float* ln_in_b = (const float*)d_in[8];
    const float* ln_t_g  = (const float*)d_in[9];
    const float* ln_t_b  = (const float*)d_in[10];
    const float* ln_m_g  = (const float*)d_in[11];
    const float* ln_m_b  = (const float*)d_in[12];
    const float* W1      = (const float*)d_in[13];
    const float* b1      = (const float*)d_in[14];
    const float* W2      = (const float*)d_in[15];
    const float* b2      = (const float*)d_in[16];
    float* out = (float*)d_out;

    cudaFuncSetAttribute(conv_mma_kernel, cudaFuncAttributeMaxDynamicSharedMemorySize, CMM_SMEM);
    cudaFuncSetAttribute(kv_mma_kernel, cudaFuncAttributeMaxDynamicSharedMemorySize, CMM_SMEM);
    cudaFuncSetAttribute(attn_gc_kernel, cudaFuncAttributeMaxDynamicSharedMemorySize, AGC_SMEM);
    cudaFuncSetAttribute(gemm_q_kernel, cudaFuncAttributeMaxDynamicSharedMemorySize, GEMMQ_SMEM);
    cudaFuncSetAttribute(gemm_h_kernel, cudaFuncAttributeMaxDynamicSharedMemorySize, GEMMH_SMEM);
    cudaFuncSetAttribute(gemm_o_kernel, cudaFuncAttributeMaxDynamicSharedMemorySize, GEMMO_SMEM);

    templates_init_kernel<<<8, 256>>>(tinit);
    xsplit_kernel<<<8*33*33, 256>>>(x);
    cwsplit_kernel<<<3456, 256>>>(conv_w);
    kvsplit_kernel<<<512, 256>>>(Wk, Wv);
    conv_mma_kernel<<<256, 512, CMM_SMEM>>>(conv_b, ln_in_g, ln_in_b);
    kv_mma_kernel<<<512, 512, CMM_SMEM>>>();

    for (int it = 0; it < 6; it++) {
        gemm_q_kernel<<<dim3(4, 8), 256, GEMMQ_SMEM>>>(Wq, ln_t_g, ln_t_b);
        attn_gc_kernel<<<dim3(32, 8), 256, AGC_SMEM>>>(it == 5 ? 1 : 0);
        finalize_kernel<<<dim3(8, 8), 256>>>(ln_m_g, ln_m_b);
        gemm_h_kernel<<<dim3(8, 8), 256, GEMMH_SMEM>>>(W1, b1);
        gemm_o_kernel<<<dim3(4, 8), 256, GEMMO_SMEM>>>(W2, b2);
    }

    out_templates_kernel<<<8, 256>>>(out);
    out_attn_kernel<<<dim3(32, 8), 256>>>(out);
}

// round 16
// speedup vs baseline: 1.8503x; 1.0456x over previous
#include <cuda_runtime.h>
#include <cuda_bf16.h>
#include <stdint.h>
#include <math.h>

#define BATCH 8
#define DIM   256
#define NSLOT 64
#define LTOK  4096

typedef unsigned long long u64;

__device__ __forceinline__ u64 PK1(float v) {
    u64 r; asm("mov.b64 %0, {%1,%1};" : "=l"(r) : "f"(v)); return r;
}
__device__ __forceinline__ void FMA2(u64& d, u64 a, u64 b) {
    asm("fma.rn.f32x2 %0, %1, %2, %0;" : "+l"(d) : "l"(a), "l"(b));
}
__device__ __forceinline__ float2 UPK(u64 v) {
    float2 f; asm("mov.b64 {%0,%1}, %2;" : "=f"(f.x), "=f"(f.y) : "l"(v)); return f;
}

// ---------------- scratch ----------------
__device__ float g_templates[BATCH*NSLOT*DIM];
__device__ float g_tbuf[BATCH*NSLOT*DIM];
__device__ float g_attn[BATCH*LTOK*NSLOT];
__device__ float g_colsum_part[BATCH*64*NSLOT];
__device__ float g_colsum[BATCH*NSLOT];
__device__ float g_accpart[32*BATCH*NSLOT*DIM];
__device__ float g_hidden[BATCH*NSLOT*512];
// bf16 split operands
__device__ __nv_bfloat16 g_xh[36799488];
__device__ __nv_bfloat16 g_xl[36799488];
__device__ __nv_bfloat16 g_cwh[27*32768];
__device__ __nv_bfloat16 g_cwl[27*32768];
__device__ __nv_bfloat16 g_kvh[256*512];
__device__ __nv_bfloat16 g_kvl[256*512];
__device__ __nv_bfloat16 g_toksh[32768*256];
__device__ __nv_bfloat16 g_toksl[32768*256];
__device__ __nv_bfloat16 g_kh[32768*256];
__device__ __nv_bfloat16 g_kl[32768*256];
__device__ __nv_bfloat16 g_vh[32768*256];
__device__ __nv_bfloat16 g_vl[32768*256];
__device__ __nv_bfloat16 g_qh[BATCH*NSLOT*DIM];
__device__ __nv_bfloat16 g_ql[BATCH*NSLOT*DIM];

__device__ __forceinline__ float gelu_exact(float v) {
    return 0.5f * v * (1.0f + erff(v * 0.70710678118654752f));
}

// ========== mma.sync helpers ==========
__device__ __forceinline__ uint32_t smem_u32(const void* p) {
    uint32_t a;
    asm("{ .reg .u64 t; cvta.to.shared.u64 t, %1; cvt.u32.u64 %0, t; }" : "=r"(a) : "l"(p));
    return a;
}
__device__ __forceinline__ void ldsm_x4(uint32_t* r, uint32_t addr) {
    asm volatile("ldmatrix.sync.aligned.m8n8.x4.shared.b16 {%0,%1,%2,%3}, [%4];"
        : "=r"(r[0]), "=r"(r[1]), "=r"(r[2]), "=r"(r[3]) : "r"(addr));
}
__device__ __forceinline__ void ldsm_x4_t(uint32_t* r, uint32_t addr) {
    asm volatile("ldmatrix.sync.aligned.m8n8.x4.trans.shared.b16 {%0,%1,%2,%3}, [%4];"
        : "=r"(r[0]), "=r"(r[1]), "=r"(r[2]), "=r"(r[3]) : "r"(addr));
}
__device__ __forceinline__ void mma_bf16(float* d, const uint32_t* a, const uint32_t* b) {
    asm volatile("mma.sync.aligned.m16n8k16.row.col.f32.bf16.bf16.f32 "
        "{%0,%1,%2,%3}, {%4,%5,%6,%7}, {%8,%9}, {%0,%1,%2,%3};"
        : "+f"(d[0]), "+f"(d[1]), "+f"(d[2]), "+f"(d[3])
        : "r"(a[0]), "r"(a[1]), "r"(a[2]), "r"(a[3]), "r"(b[0]), "r"(b[1]));
}
__device__ __forceinline__ void bsplit(float v0, float v1, __nv_bfloat162& hh, __nv_bfloat162& ll) {
    __nv_bfloat16 h0 = __float2bfloat16(v0), h1 = __float2bfloat16(v1);
    hh.x = h0; hh.y = h1;
    ll.x = __float2bfloat16(v0 - __bfloat162float(h0));
    ll.y = __float2bfloat16(v1 - __bfloat162float(h1));
}
__device__ __forceinline__ void cpa16(uint32_t dst, const void* src) {
    asm volatile("cp.async.cg.shared.global [%0], [%1], 16;" :: "r"(dst), "l"(src) : "memory");
}
#define CP_COMMIT asm volatile("cp.async.commit_group;" ::: "memory")
#define CP_WAIT0  asm volatile("cp.async.wait_group 0;" ::: "memory")
#define CP_WAIT1  asm volatile("cp.async.wait_group 1;" ::: "memory")

// 128x256 += A(128x128, pitch 272B) x B(128k x 256n, pitch 528B); 3-term bf16 split.
__device__ __forceinline__ void mma_chunk(
    uint32_t sAh, uint32_t sAl, uint32_t sBh, uint32_t sBl,
    float d[2][8][4], int wm, int wn, int lane)
{
    uint32_t aoff0 = (uint32_t)((wm*32 + (lane & 15))*272 + (lane >> 4)*16);
    uint32_t boff0 = (uint32_t)((lane & 15)*528 + (wn*64 + (lane >> 4)*8)*2);
    #pragma unroll
    for (int kk = 0; kk < 8; kk++) {
        uint32_t ah[8], al[8], bb[16];
        uint32_t ao = aoff0 + kk*32;
        ldsm_x4(ah,     sAh + ao);
        ldsm_x4(ah + 4, sAh + ao + 4352);
        ldsm_x4(al,     sAl + ao);
        ldsm_x4(al + 4, sAl + ao + 4352);
        uint32_t bo = boff0 + kk*8448;
        #pragma unroll
        for (int jj = 0; jj < 4; jj++) ldsm_x4_t(bb + jj*4, sBh + bo + jj*32);
        #pragma unroll
        for (int mi = 0; mi < 2; mi++) {
            #pragma unroll
            for (int j = 0; j < 8; j++) {
                const uint32_t* bf = bb + (j >> 1)*4 + (j & 1)*2;
                mma_bf16(d[mi][j], mi ? ah + 4 : ah, bf);
                mma_bf16(d[mi][j], mi ? al + 4 : al, bf);
            }
        }
        #pragma unroll
        for (int jj = 0; jj < 4; jj++) ldsm_x4_t(bb + jj*4, sBl + bo + jj*32);
        #pragma unroll
        for (int mi = 0; mi < 2; mi++) {
            #pragma unroll
            for (int j = 0; j < 8; j++) {
                const uint32_t* bf = bb + (j >> 1)*4 + (j & 1)*2;
                mma_bf16(d[mi][j], mi ? ah + 4 : ah, bf);
            }
        }
    }
}

// dual-term pass: d += Ah*B + Al*B
__device__ __forceinline__ void mma_dual(
    uint32_t sAh, uint32_t sAl, uint32_t sB,
    float d[2][8][4], int wm, int wn, int lane)
{
    uint32_t aoff0 = (uint32_t)((wm*32 + (lane & 15))*272 + (lane >> 4)*16);
    uint32_t boff0 = (uint32_t)((lane & 15)*528 + (wn*64 + (lane >> 4)*8)*2);
    #pragma unroll
    for (int kk = 0; kk < 8; kk++) {
        uint32_t ah[8], al[8], bb[16];
        uint32_t ao = aoff0 + kk*32;
        ldsm_x4(ah,     sAh + ao);
        ldsm_x4(ah + 4, sAh + ao + 4352);
        ldsm_x4(al,     sAl + ao);
        ldsm_x4(al + 4, sAl + ao + 4352);
        uint32_t bo = boff0 + kk*8448;
        #pragma unroll
        for (int jj = 0; jj < 4; jj++) ldsm_x4_t(bb + jj*4, sB + bo + jj*32);
        #pragma unroll
        for (int mi = 0; mi < 2; mi++) {
            #pragma unroll
            for (int j = 0; j < 8; j++) {
                const uint32_t* bf = bb + (j >> 1)*4 + (j & 1)*2;
                mma_bf16(d[mi][j], mi ? ah + 4 : ah, bf);
                mma_bf16(d[mi][j], mi ? al + 4 : al, bf);
            }
        }
    }
}

// single-term pass: d += Ah*B
__device__ __forceinline__ void mma_single(
    uint32_t sAh, uint32_t sB,
    float d[2][8][4], int wm, int wn, int lane)
{
    uint32_t aoff0 = (uint32_t)((wm*32 + (lane & 15))*272 + (lane >> 4)*16);
    uint32_t boff0 = (uint32_t)((lane & 15)*528 + (wn*64 + (lane >> 4)*8)*2);
    #pragma unroll
    for (int kk = 0; kk < 8; kk++) {
        uint32_t ah[8], bb[16];
        uint32_t ao = aoff0 + kk*32;
        ldsm_x4(ah,     sAh + ao);
        ldsm_x4(ah + 4, sAh + ao + 4352);
        uint32_t bo = boff0 + kk*8448;
        #pragma unroll
        for (int jj = 0; jj < 4; jj++) ldsm_x4_t(bb + jj*4, sB + bo + jj*32);
        #pragma unroll
        for (int mi = 0; mi < 2; mi++) {
            #pragma unroll
            for (int j = 0; j < 8; j++) {
                const uint32_t* bf = bb + (j >> 1)*4 + (j & 1)*2;
                mma_bf16(d[mi][j], mi ? ah + 4 : ah, bf);
            }
        }
    }
}

// ---------------- merged prep: cwsplit | kvsplit | templates_init ----------------
__global__ void prep_kernel(const float* __restrict__ tinit, const float* __restrict__ cw,
                            const float* __restrict__ Wk, const float* __restrict__ Wv) {
    int bid = blockIdx.x;
    if (bid < 3456) {
        int idx = bid*256 + threadIdx.x;
        int tap = idx >> 15, r = idx & 32767;
        int k = r >> 8, n = r & 255;
        float v = cw[(size_t)n*3456 + k*27 + tap];
        __nv_bfloat16 hi = __float2bfloat16(v);
        g_cwh[idx] = hi;
        g_cwl[idx] = __float2bfloat16(v - __bfloat162float(hi));
    } else if (bid < 3968) {
        int idx = (bid - 3456)*256 + threadIdx.x;
        int k = idx >> 9, c512 = idx & 511;
        int mat = c512 >> 8, col = c512 & 255;
        const float* W = mat ? Wv : Wk;
        float v = W[(size_t)k*256 + col];
        __nv_bfloat16 hi = __float2bfloat16(v);
        g_kvh[idx] = hi;
        g_kvl[idx] = __float2bfloat16(v - __bfloat162float(hi));
    } else {
        int b = bid - 3968, t = threadIdx.x;
        for (int n = 0; n < NSLOT; n++)
            g_templates[(b*NSLOT + n)*DIM + t] = tinit[n*DIM + t];
    }
}

__global__ __launch_bounds__(256) void xsplit_kernel(const float* __restrict__ x) {
    __shared__ float st[128*33];
    int bid = blockIdx.x; int b = bid / 1089; int rem = bid % 1089; int d = rem / 33, h = rem % 33;
    int t = threadIdx.x, warp = t >> 5, lane = t & 31;
    const float* xb = x + ((((size_t)b*128)*33 + d)*33 + h)*33;
    for (int c = warp; c < 128; c += 8) {
        const float* src = xb + (size_t)c*35937;
        st[c*33 + lane] = src[lane];
        if (lane == 0) st[c*33 + 32] = src[32];
    }
    __syncthreads();
    size_t ob = ((((size_t)b*33 + d)*33 + h)*33)*128;
    for (int i = t; i < 33*128; i += 256) {
        int w = i >> 7, c = i & 127;
        float v = st[c*33 + w];
        __nv_bfloat16 hi = __float2bfloat16(v);
        g_xh[ob + (size_t)w*128 + c] = hi;
        g_xl[ob + (size_t)w*128 + c] = __float2bfloat16(v - __bfloat162float(hi));
    }
}

// ---------------- conv (implicit GEMM, cp.async-pipelined A+B) + bias + ReLU + LN ----------------
#define CMM_SMEM 204800
__global__ __launch_bounds__(512, 1) void conv_mma_kernel(
    const float* __restrict__ convb, const float* __restrict__ lng, const float* __restrict__ lnb)
{
    extern __shared__ char sm[];
    uint32_t sb = smem_u32(sm);
    const uint32_t oAh = 0, oAl = 34816, oB0 = 69632, oB1 = 137216;
    int t = threadIdx.x, lane = t & 31, wid = t >> 5;
    int wm = wid >> 2, wn = wid & 3;
    int bx = blockIdx.x; int b = bx >> 5, xd = (bx >> 1) & 15, half = bx & 1;

    float d[2][8][4];
    #pragma unroll
    for (int i = 0; i < 2; i++)
        #pragma unroll
        for (int j = 0; j < 8; j++)
            #pragma unroll
            for (int c = 0; c < 4; c++) d[i][j][c] = 0.f;

    int m = t >> 2, q = t & 3;
    int xhl = m >> 4, xw = m & 15;

    {
        const uint4* s1 = (const uint4*)(g_cwh);
        #pragma unroll
        for (int it = 0; it < 8; it++) {
            int i = t + it*512;
            cpa16(sb + oB0 + (uint32_t)((i >> 5)*528 + (i & 31)*16), s1 + i);
        }
        CP_COMMIT;
    }

    for (int tap = 0; tap < 27; tap++) {
        int kd = tap/9, r9 = tap%9, kh = r9/3, kw = r9%3;
        {   // A tiles via cp.async (waited together with Bh below)
            size_t xi = ((((size_t)(b*33) + 2*xd + kd)*33 + 2*(half*8 + xhl) + kh)*33 + 2*xw + kw)*128 + q*32;
            const uint4* shi = (const uint4*)(g_xh + xi);
            const uint4* slo = (const uint4*)(g_xl + xi);
            uint32_t dh = sb + oAh + (uint32_t)(m*272 + q*64);
            uint32_t dl = sb + oAl + (uint32_t)(m*272 + q*64);
            #pragma unroll
            for (int j = 0; j < 4; j++) {
                cpa16(dh + j*16, shi + j);
                cpa16(dl + j*16, slo + j);
            }
            CP_COMMIT;
        }
        CP_WAIT0;          // A(tap) + Bh(tap)
        __syncthreads();
        {
            const uint4* s2 = (const uint4*)(g_cwl + tap*32768);
            #pragma unroll
            for (int it = 0; it < 8; it++) {
                int i = t + it*512;
                cpa16(sb + oB1 + (uint32_t)((i >> 5)*528 + (i & 31)*16), s2 + i);
            }
            CP_COMMIT;
        }
        mma_dual(sb + oAh, sb + oAl, sb + oB0, d, wm, wn, lane);
        CP_WAIT0;          // Bl(tap)
        __syncthreads();
        if (tap < 26) {
            const uint4* s1 = (const uint4*)(g_cwh + (tap+1)*32768);
            #pragma unroll
            for (int it = 0; it < 8; it++) {
                int i = t + it*512;
                cpa16(sb + oB0 + (uint32_t)((i >> 5)*528 + (i & 31)*16), s1 + i);
            }
            CP_COMMIT;
        }
        mma_single(sb + oAh, sb + oB1, d, wm, wn, lane);
        __syncthreads();
    }

    float* stg = (float*)sm;
    {
        int r0 = wm*32 + (lane >> 2);
        int c0 = wn*64 + (lane & 3)*2;
        #pragma unroll
        for (int mi = 0; mi < 2; mi++)
            #pragma unroll
            for (int j = 0; j < 8; j++) {
                int rr = r0 + mi*16, cc = c0 + j*8;
                *(float2*)(stg + (size_t)rr*264 + cc)     = make_float2(d[mi][j][0], d[mi][j][1]);
                *(float2*)(stg + (size_t)(rr+8)*264 + cc) = make_float2(d[mi][j][2], d[mi][j][3]);
            }
    }
    __syncthreads();

    {
        int tok = t >> 2, q2 = t & 3;
        const float* src = stg + (size_t)tok*264 + q2*64;
        float z[64];
        float s = 0.f, sq = 0.f;
        #pragma unroll
        for (int i = 0; i < 64; i++) {
            float v = fmaxf(src[i] + convb[q2*64 + i], 0.f);
            z[i] = v; s += v; sq += v*v;
        }
        s  += __shfl_xor_sync(0xffffffffu, s, 1);  s  += __shfl_xor_sync(0xffffffffu, s, 2);
        sq += __shfl_xor_sync(0xffffffffu, sq, 1); sq += __shfl_xor_sync(0xffffffffu, sq, 2);
        float mu = s * (1.f/256.f);
        float rs = rsqrtf(sq * (1.f/256.f) - mu*mu + 1e-5f);
        int l = (xd*16 + half*8 + (tok >> 4))*16 + (tok & 15);
        size_t tg = ((size_t)b*4096 + l)*256 + q2*64;
        #pragma unroll
        for (int i = 0; i < 64; i += 2) {
            int ch = q2*64 + i;
            float v0 = (z[i]   - mu)*rs*lng[ch]   + lnb[ch];
            float v1 = (z[i+1] - mu)*rs*lng[ch+1] + lnb[ch+1];
            __nv_bfloat162 hh, ll;
            bsplit(v0, v1, hh, ll);
            *(__nv_bfloat162*)(g_toksh + tg + i) = hh;
            *(__nv_bfloat162*)(g_toksl + tg + i) = ll;
        }
    }
}

// ---------------- K/V projection via mma.sync -> bf16 split outputs ----------------
__global__ __launch_bounds__(512, 1) void kv_mma_kernel() {
    extern __shared__ char sm[];
    uint32_t sb = smem_u32(sm);
    const uint32_t oAh = 0, oAl = 34816, oBh = 69632, oBl = 137216;
    int t = threadIdx.x, lane = t & 31, wid = t >> 5;
    int wm = wid >> 2, wn = wid & 3;
    int nhalf = blockIdx.x & 1, chunk = blockIdx.x >> 1;

    float d[2][8][4];
    #pragma unroll
    for (int i = 0; i < 2; i++)
        #pragma unroll
        for (int j = 0; j < 8; j++)
            #pragma unroll
            for (int c = 0; c < 4; c++) d[i][j][c] = 0.f;

    int m = t >> 2, q = t & 3;
    for (int kc = 0; kc < 2; kc++) {
        {
            size_t ti = ((size_t)(chunk*128 + m))*256 + kc*128 + q*32;
            const uint4* shi = (const uint4*)(g_toksh + ti);
            const uint4* slo = (const uint4*)(g_toksl + ti);
            char* dh = sm + oAh + m*272 + q*64;
            char* dl = sm + oAl + m*272 + q*64;
            #pragma unroll
            for (int j = 0; j < 4; j++) {
                *(uint4*)(dh + j*16) = shi[j];
                *(uint4*)(dl + j*16) = slo[j];
            }
        }
        {
            #pragma unroll
            for (int it = 0; it < 8; it++) {
                int i = t + it*512;
                int row = i >> 5, seg = i & 31;
                size_t off = (size_t)(kc*128 + row)*512 + nhalf*256 + seg*8;
                *(uint4*)(sm + oBh + row*528 + seg*16) = *(const uint4*)(g_kvh + off);
                *(uint4*)(sm + oBl + row*528 + seg*16) = *(const uint4*)(g_kvl + off);
            }
        }
        __syncthreads();
        mma_chunk(sb + oAh, sb + oAl, sb + oBh, sb + oBl, d, wm, wn, lane);
        __syncthreads();
    }

    __nv_bfloat16* dh = nhalf ? g_vh : g_kh;
    __nv_bfloat16* dl = nhalf ? g_vl : g_kl;
    int r0 = wm*32 + (lane >> 2);
    int c0 = wn*64 + (lane & 3)*2;
    #pragma unroll
    for (int mi = 0; mi < 2; mi++)
        #pragma unroll
        for (int j = 0; j < 8; j++) {
            int rr = r0 + mi*16, cc = c0 + j*8;
            size_t tok = (size_t)chunk*128 + rr;
            __nv_bfloat162 hh, ll;
            bsplit(d[mi][j][0], d[mi][j][1], hh, ll);
            *(__nv_bfloat162*)(dh + tok*256 + cc) = hh;
            *(__nv_bfloat162*)(dl + tok*256 + cc) = ll;
            bsplit(d[mi][j][2], d[mi][j][3], hh, ll);
            *(__nv_bfloat162*)(dh + (tok+8)*256 + cc) = hh;
            *(__nv_bfloat162*)(dl + (tok+8)*256 + cc) = ll;
        }
}

// ---------------- fused LN_t + q-GEMM (full B preload, sync-free compute) ----------------
#define GEMMQ_SMEM ((16384 + 16384)*4)
__global__ __launch_bounds__(256) void gemm_q_kernel(
    const float* __restrict__ Wq, const float* __restrict__ lng, const float* __restrict__ lnb)
{
    extern __shared__ float smf[];
    float* Af = smf; float* Bf = smf + 16384;
    int b = blockIdx.y; int nc = blockIdx.x * 64;
    int t = threadIdx.x;
    int kk0 = t >> 4, n4 = (t & 15)*4;
    #pragma unroll
    for (int k0 = 0; k0 < 256; k0 += 16)
        *(float4*)(Bf + (k0 + kk0)*64 + n4) = *(const float4*)(Wq + (size_t)(k0+kk0)*256 + nc + n4);
    {
        int r = t >> 2, part = t & 3;
        const float* row = g_templates + ((size_t)(b*NSLOT) + r)*DIM + part*64;
        float s = 0.f, sq = 0.f;
        #pragma unroll
        for (int i = 0; i < 64; i += 4) {
            float4 v = *(const float4*)(row + i);
            s += v.x+v.y+v.z+v.w;
            sq += v.x*v.x + v.y*v.y + v.z*v.z + v.w*v.w;
        }
        s  += __shfl_xor_sync(0xffffffffu, s, 1);  s  += __shfl_xor_sync(0xffffffffu, s, 2);
        sq += __shfl_xor_sync(0xffffffffu, sq, 1); sq += __shfl_xor_sync(0xffffffffu, sq, 2);
        float mu = s * (1.0f/256.0f);
        float rs = rsqrtf(sq * (1.0f/256.0f) - mu*mu + 1e-5f);
        #pragma unroll
        for (int i = 0; i < 64; i += 4) {
            float4 v = *(const float4*)(row + i);
            float4 gg = *(const float4*)(lng + part*64 + i);
            float4 bv = *(const float4*)(lnb + part*64 + i);
            Af[(part*64+i+0)*64 + r] = (v.x - mu)*rs*gg.x + bv.x;
            Af[(part*64+i+1)*64 + r] = (v.y - mu)*rs*gg.y + bv.y;
            Af[(part*64+i+2)*64 + r] = (v.z - mu)*rs*gg.z + bv.z;
            Af[(part*64+i+3)*64 + r] = (v.w - mu)*rs*gg.w + bv.w;
        }
    }
    __syncthreads();

    int tm = t >> 4, tn = t & 15;
    u64 acc[4][2] = {};
    for (int k0 = 0; k0 < 256; k0 += 16) {
        #pragma unroll
        for (int kk = 0; kk < 16; kk++) {
            ulonglong2 a2 = *(ulonglong2*)(Af + (k0+kk)*64 + tm*4);
            float4 bb = *(float4*)(Bf + (k0+kk)*64 + tn*4);
            u64 q0 = PK1(bb.x), q1 = PK1(bb.y), q2 = PK1(bb.z), q3 = PK1(bb.w);
            FMA2(acc[0][0], a2.x, q0); FMA2(acc[0][1], a2.y, q0);
            FMA2(acc[1][0], a2.x, q1); FMA2(acc[1][1], a2.y, q1);
            FMA2(acc[2][0], a2.x, q2); FMA2(acc[2][1], a2.y, q2);
            FMA2(acc[3][0], a2.x, q3); FMA2(acc[3][1], a2.y, q3);
        }
    }
    const float scale = 0.0625f;
    #pragma unroll
    for (int p = 0; p < 2; p++) {
        float2 f0 = UPK(acc[0][p]), f1 = UPK(acc[1][p]), f2 = UPK(acc[2][p]), f3 = UPK(acc[3][p]);
        int mm = tm*4 + p*2;
        size_t o0 = ((size_t)(b*NSLOT) + mm)*DIM + nc + tn*4;
        __nv_bfloat162 hh, ll;
        bsplit(f0.x*scale, f1.x*scale, hh, ll);
        *(__nv_bfloat162*)(g_qh + o0) = hh; *(__nv_bfloat162*)(g_ql + o0) = ll;
        bsplit(f2.x*scale, f3.x*scale, hh, ll);
        *(__nv_bfloat162*)(g_qh + o0 + 2) = hh; *(__nv_bfloat162*)(g_ql + o0 + 2) = ll;
        bsplit(f0.y*scale, f1.y*scale, hh, ll);
        *(__nv_bfloat162*)(g_qh + o0 + DIM) = hh; *(__nv_bfloat162*)(g_ql + o0 + DIM) = ll;
        bsplit(f2.y*scale, f3.y*scale, hh, ll);
        *(__nv_bfloat162*)(g_qh + o0 + DIM + 2) = hh; *(__nv_bfloat162*)(g_ql + o0 + DIM + 2) = ll;
    }
}

// ---------------- FUSED attn logits + softmax + colsum + attn^T@v ----------------
// kc double-buffered cp.async K/Q, V prefetched during softmax.
// P0: K0h 0(34816) K0l 34816 Q0h 69632(17408) Q0l 87040  -> 104448
// P1: K1h 104448  K1l 139264 Q1h 174080       Q1l 191488 -> 208896
// stg 0(34816 fp32), ath 34816(18432), atl 53248(18432)  [alias P0]
// V: Vh 71680(67584), Vl 139264(67584)                   [alias Q0 tail + P1]
#define AGC_SMEM 208896
__global__ __launch_bounds__(256) void attn_gc_kernel(int write_attn) {
    extern __shared__ char sm[];
    uint32_t sb = smem_u32(sm);
    const uint32_t oK0h = 0, oK0l = 34816, oQ0h = 69632, oQ0l = 87040;
    const uint32_t oK1h = 104448, oK1l = 139264, oQ1h = 174080, oQ1l = 191488;
    const uint32_t oStg = 0, oAth = 34816, oAtl = 53248;
    const uint32_t oVh = 71680, oVl = 139264;
    int t = threadIdx.x, lane = t & 31, wid = t >> 5;
    int lb = blockIdx.x, b = blockIdx.y;

    int wm = wid >> 1, wn = wid & 1;
    float d[2][4][4];
    #pragma unroll
    for (int i = 0; i < 2; i++)
        #pragma unroll
        for (int j = 0; j < 4; j++)
            #pragma unroll
            for (int c = 0; c < 4; c++) d[i][j][c] = 0.f;

    // issue BOTH kc tile loads up-front (cp.async)
    #pragma unroll
    for (int kc = 0; kc < 2; kc++) {
        uint32_t bKh = kc ? oK1h : oK0h, bKl = kc ? oK1l : oK0l;
        uint32_t bQh = kc ? oQ1h : oQ0h, bQl = kc ? oQ1l : oQ0l;
        {
            int row = t >> 1, half = t & 1;
            size_t ti = ((size_t)(b*4096) + lb*128 + row)*256 + kc*128 + half*64;
            const uint4* shi = (const uint4*)(g_kh + ti);
            const uint4* slo = (const uint4*)(g_kl + ti);
            uint32_t dh = sb + bKh + (uint32_t)(row*272 + half*128);
            uint32_t dl = sb + bKl + (uint32_t)(row*272 + half*128);
            #pragma unroll
            for (int j = 0; j < 8; j++) {
                cpa16(dh + j*16, shi + j);
                cpa16(dl + j*16, slo + j);
            }
        }
        {
            int row = t >> 2, q4 = t & 3;
            size_t ti = ((size_t)(b*NSLOT) + row)*256 + kc*128 + q4*32;
            const uint4* shi = (const uint4*)(g_qh + ti);
            const uint4* slo = (const uint4*)(g_ql + ti);
            uint32_t dh = sb + bQh + (uint32_t)(row*272 + q4*64);
            uint32_t dl = sb + bQl + (uint32_t)(row*272 + q4*64);
            #pragma unroll
            for (int j = 0; j < 4; j++) {
                cpa16(dh + j*16, shi + j);
                cpa16(dl + j*16, slo + j);
            }
        }
        CP_COMMIT;
    }

    #pragma unroll
    for (int kc = 0; kc < 2; kc++) {
        if (kc == 0) { CP_WAIT1; } else { CP_WAIT0; }
        __syncthreads();
        uint32_t bKh = kc ? oK1h : oK0h, bKl = kc ? oK1l : oK0l;
        uint32_t bQh = kc ? oQ1h : oQ0h, bQl = kc ? oQ1l : oQ0l;
        uint32_t aoff0 = (uint32_t)((wm*32 + (lane & 15))*272 + (lane >> 4)*16);
        uint32_t qoff0 = (uint32_t)(((lane >> 4)*8 + (lane & 7) + wn*32)*272 + ((lane >> 3) & 1)*16);
        #pragma unroll
        for (int kk = 0; kk < 8; kk++) {
            uint32_t ah[8], al[8], qh8[8], ql8[8];
            uint32_t ao = aoff0 + kk*32;
            ldsm_x4(ah,     sb + bKh + ao);
            ldsm_x4(ah + 4, sb + bKh + ao + 16*272);
            ldsm_x4(al,     sb + bKl + ao);
            ldsm_x4(al + 4, sb + bKl + ao + 16*272);
            uint32_t qo = qoff0 + kk*32;
            ldsm_x4(qh8,     sb + bQh + qo);
            ldsm_x4(qh8 + 4, sb + bQh + qo + 16*272);
            ldsm_x4(ql8,     sb + bQl + qo);
            ldsm_x4(ql8 + 4, sb + bQl + qo + 16*272);
            #pragma unroll
            for (int mi = 0; mi < 2; mi++) {
                #pragma unroll
                for (int j = 0; j < 4; j++) {
                    const uint32_t* bh = qh8 + (j >> 1)*4 + (j & 1)*2;
                    const uint32_t* bl = ql8 + (j >> 1)*4 + (j & 1)*2;
                    const uint32_t* am = mi ? ah + 4 : ah;
                    const uint32_t* aml = mi ? al + 4 : al;
                    mma_bf16(d[mi][j], am, bh);
                    mma_bf16(d[mi][j], am, bl);
                    mma_bf16(d[mi][j], aml, bh);
                }
            }
        }
        __syncthreads();
    }

    // prefetch V (dest aliases dead Q0/K1/Q1 regions), overlapped with softmax/colsum
    {
        int row = t >> 1, half = t & 1;
        size_t ti = ((size_t)(b*4096) + lb*128 + row)*256 + half*128;
        const uint4* shi = (const uint4*)(g_vh + ti);
        const uint4* slo = (const uint4*)(g_vl + ti);
        uint32_t dsh = sb + oVh + (uint32_t)(row*528 + half*256);
        uint32_t dsl = sb + oVl + (uint32_t)(row*528 + half*256);
        #pragma unroll
        for (int j = 0; j < 16; j++) {
            cpa16(dsh + j*16, shi + j);
            cpa16(dsl + j*16, slo + j);
        }
        CP_COMMIT;
    }

    float* stg = (float*)(sm + oStg);
    {
        int r0 = wm*32 + (lane >> 2);
        int c0 = wn*32 + (lane & 3)*2;
        #pragma unroll
        for (int mi = 0; mi < 2; mi++)
            #pragma unroll
            for (int j = 0; j < 4; j++) {
                int rr = r0 + mi*16, cc = c0 + j*8;
                *(float2*)(stg + rr*68 + cc)     = make_float2(d[mi][j][0], d[mi][j][1]);
                *(float2*)(stg + (rr+8)*68 + cc) = make_float2(d[mi][j][2], d[mi][j][3]);
            }
    }
    __syncthreads();

    {
        int row = t >> 1, half = t & 1;
        float* sr = stg + row*68 + half*32;
        float a[32];
        float mx = -3.4e38f;
        #pragma unroll
        for (int i = 0; i < 32; i++) { a[i] = sr[i]; mx = fmaxf(mx, a[i]); }
        mx = fmaxf(mx, __shfl_xor_sync(0xffffffffu, mx, 1));
        float s = 0.f;
        #pragma unroll
        for (int i = 0; i < 32; i++) { a[i] = expf(a[i] - mx); s += a[i]; }
        s += __shfl_xor_sync(0xffffffffu, s, 1);
        float inv = 1.0f / s;
        #pragma unroll
        for (int i = 0; i < 32; i++) { a[i] = a[i]*inv + 1e-8f; sr[i] = a[i]; }
        if (write_attn) {
            size_t gi = ((size_t)(b*4096) + lb*128 + row)*64 + half*32;
            #pragma unroll
            for (int i = 0; i < 32; i += 4)
                *(float4*)(g_attn + gi + i) = make_float4(a[i], a[i+1], a[i+2], a[i+3]);
        }
        char* dst_h = sm + oAth + row*144 + half*64;
        char* dst_l = sm + oAtl + row*144 + half*64;
        #pragma unroll
        for (int i = 0; i < 32; i += 2) {
            __nv_bfloat162 hh, ll;
            bsplit(a[i], a[i+1], hh, ll);
            *(__nv_bfloat162*)(dst_h + i*2) = hh;
            *(__nv_bfloat162*)(dst_l + i*2) = ll;
        }
    }
    __syncthreads();
    if (t < 64) {
        float s = 0.f;
        for (int r = 0; r < 128; r++) s += stg[r*68 + t];
        g_colsum_part[((size_t)b*64 + lb)*NSLOT + t] = s;
    }

    CP_WAIT0;         // V landed
    __syncthreads();

    int wm2 = wid & 1, wn2 = wid >> 1;
    float d2[2][8][4];
    #pragma unroll
    for (int i = 0; i < 2; i++)
        #pragma unroll
        for (int j = 0; j < 8; j++)
            #pragma unroll
            for (int c = 0; c < 4; c++) d2[i][j][c] = 0.f;
    {
        uint32_t aoff0 = (uint32_t)((((lane >> 4)*8 + (lane & 7)))*144 + ((lane >> 3) & 1)*16 + wm2*64);
        uint32_t boff0 = (uint32_t)((lane & 15)*528 + (wn2*64 + (lane >> 4)*8)*2);
        #pragma unroll
        for (int kk = 0; kk < 8; kk++) {
            uint32_t ah[8], al[8], bh8[16], bl8[16];
            uint32_t ao = aoff0 + kk*16*144;
            ldsm_x4_t(ah,     sb + oAth + ao);
            ldsm_x4_t(ah + 4, sb + oAth + ao + 32);
            ldsm_x4_t(al,     sb + oAtl + ao);
            ldsm_x4_t(al + 4, sb + oAtl + ao + 32);
            uint32_t bo = boff0 + kk*8448;
            #pragma unroll
            for (int jj = 0; jj < 4; jj++) ldsm_x4_t(bh8 + jj*4, sb + oVh + bo + jj*32);
            #pragma unroll
            for (int jj = 0; jj < 4; jj++) ldsm_x4_t(bl8 + jj*4, sb + oVl + bo + jj*32);
            #pragma unroll
            for (int mi = 0; mi < 2; mi++) {
                #pragma unroll
                for (int j = 0; j < 8; j++) {
                    const uint32_t* bfh = bh8 + (j >> 1)*4 + (j & 1)*2;
                    const uint32_t* bfl = bl8 + (j >> 1)*4 + (j & 1)*2;
                    const uint32_t* am = mi ? ah + 4 : ah;
                    const uint32_t* aml = mi ? al + 4 : al;
                    mma_bf16(d2[mi][j], am, bfh);
                    mma_bf16(d2[mi][j], am, bfl);
                    mma_bf16(d2[mi][j], aml, bfh);
                }
            }
        }
    }

    int r0 = wm2*32 + (lane >> 2);
    int c0 = wn2*64 + (lane & 3)*2;
    float* C = g_accpart + ((size_t)((lb*BATCH + b)*NSLOT))*DIM;
    #pragma unroll
    for (int mi = 0; mi < 2; mi++)
        #pragma unroll
        for (int j = 0; j < 8; j++) {
            int slot = r0 + mi*16, cc = c0 + j*8;
            *(float2*)(C + (size_t)slot*DIM + cc)     = make_float2(d2[mi][j][0], d2[mi][j][1]);
            *(float2*)(C + (size_t)(slot+8)*DIM + cc) = make_float2(d2[mi][j][2], d2[mi][j][3]);
        }
}

// ---------------- colsum + template update + LN_m. grid (8 ng, 8 b) ----------------
__global__ __launch_bounds__(256) void finalize_kernel(const float* __restrict__ g,
                                                       const float* __restrict__ bb) {
    __shared__ float tv[8*256];
    __shared__ float csin_s[8];
    int ng = blockIdx.x, b = blockIdx.y, t = threadIdx.x;
    {
        int s = t >> 5, l = t & 31;
        int n = ng*8 + s;
        float v = g_colsum_part[((size_t)b*64 + l)*NSLOT + n];
        #pragma unroll
        for (int m = 16; m; m >>= 1) v += __shfl_xor_sync(0xffffffffu, v, m);
        if (l == 0) { csin_s[s] = 1.0f / v; g_colsum[b*NSLOT + n] = v; }
    }
    __syncthreads();
    #pragma unroll
    for (int s = 0; s < 8; s++) {
        int n = ng*8 + s;
        float acc = 0.f;
        #pragma unroll 8
        for (int p = 0; p < 32; p++)
            acc += g_accpart[((size_t)(p*BATCH + b)*NSLOT + n)*DIM + t];
        size_t idx = ((size_t)(b*NSLOT) + n)*DIM + t;
        float val = g_templates[idx] + acc * csin_s[s];
        g_templates[idx] = val;
        tv[s*256 + t] = val;
    }
    __syncthreads();
    {
        int w = t >> 5, l = t & 31;
        const float* row = tv + w*256;
        float s1 = 0.f, s2 = 0.f;
        #pragma unroll
        for (int i = l; i < 256; i += 32) { float v = row[i]; s1 += v; s2 += v*v; }
        #pragma unroll
        for (int m = 16; m; m >>= 1) {
            s1 += __shfl_xor_sync(0xffffffffu, s1, m);
            s2 += __shfl_xor_sync(0xffffffffu, s2, m);
        }
        float mu = s1 * (1.f/256.f);
        float rs = rsqrtf(s2 * (1.f/256.f) - mu*mu + 1e-5f);
        int n = ng*8 + w;
        float* drow = g_tbuf + ((size_t)(b*NSLOT) + n)*DIM;
        #pragma unroll
        for (int i = l; i < 256; i += 32)
            drow[i] = (row[i] - mu)*rs*g[i] + bb[i];
    }
}

// ---------------- hidden = GELU(tbuf @ W1 + b1), full preload ----------------
#define GEMMH_SMEM ((16384 + 16384)*4)
__global__ __launch_bounds__(256) void gemm_h_kernel(const float* __restrict__ W1,
                                                     const float* __restrict__ b1)
{
    extern __shared__ float smf[];
    float* Af = smf; float* Bf = smf + 16384;
    int b = blockIdx.y; int nc = blockIdx.x * 64;
    int t = threadIdx.x;
    int kk0 = t >> 4, n4 = (t & 15)*4;
    #pragma unroll
    for (int k0 = 0; k0 < 256; k0 += 16)
        *(float4*)(Bf + (k0 + kk0)*64 + n4) = *(const float4*)(W1 + (size_t)(k0+kk0)*512 + nc + n4);
    {
        int r = t >> 2, part = t & 3;
        const float* row = g_tbuf + ((size_t)(b*NSLOT) + r)*DIM + part*64;
        #pragma unroll
        for (int i = 0; i < 64; i += 4) {
            float4 v = *(const float4*)(row + i);
            Af[(part*64+i+0)*64 + r] = v.x;
            Af[(part*64+i+1)*64 + r] = v.y;
            Af[(part*64+i+2)*64 + r] = v.z;
            Af[(part*64+i+3)*64 + r] = v.w;
        }
    }
    __syncthreads();
    int tm = t >> 4, tn = t & 15;
    u64 acc[4][2] = {};
    for (int k0 = 0; k0 < 256; k0 += 16) {
        #pragma unroll
        for (int kk = 0; kk < 16; kk++) {
            ulonglong2 a2 = *(ulonglong2*)(Af + (k0+kk)*64 + tm*4);
            float4 bb = *(float4*)(Bf + (k0+kk)*64 + tn*4);
            u64 q0 = PK1(bb.x), q1 = PK1(bb.y), q2 = PK1(bb.z), q3 = PK1(bb.w);
            FMA2(acc[0][0], a2.x, q0); FMA2(acc[0][1], a2.y, q0);
            FMA2(acc[1][0], a2.x, q1); FMA2(acc[1][1], a2.y, q1);
            FMA2(acc[2][0], a2.x, q2); FMA2(acc[2][1], a2.y, q2);
            FMA2(acc[3][0], a2.x, q3); FMA2(acc[3][1], a2.y, q3);
        }
    }
    float4 bv = *(const float4*)(b1 + nc + tn*4);
    #pragma unroll
    for (int p = 0; p < 2; p++) {
        float2 f0 = UPK(acc[0][p]), f1 = UPK(acc[1][p]), f2 = UPK(acc[2][p]), f3 = UPK(acc[3][p]);
        float4 r0 = {gelu_exact(f0.x+bv.x), gelu_exact(f1.x+bv.y), gelu_exact(f2.x+bv.z), gelu_exact(f3.x+bv.w)};
        float4 r1 = {gelu_exact(f0.y+bv.x), gelu_exact(f1.y+bv.y), gelu_exact(f2.y+bv.z), gelu_exact(f3.y+bv.w)};
        int mm = tm*4 + p*2;
        *(float4*)(g_hidden + ((size_t)(b*NSLOT) + mm  )*512 + nc + tn*4) = r0;
        *(float4*)(g_hidden + ((size_t)(b*NSLOT) + mm+1)*512 + nc + tn*4) = r1;
    }
}

// ---------------- templates += hidden @ W2 + b2, 2-phase preload ----------------
#define GEMMO_SMEM ((16384 + 16384)*4)
__global__ __launch_bounds__(256) void gemm_o_kernel(const float* __restrict__ W2,
                                                     const float* __restrict__ b2)
{
    extern __shared__ float smf[];
    float* Af = smf; float* Bf = smf + 16384;
    int b = blockIdx.y; int nc = blockIdx.x * 64;
    int t = threadIdx.x;
    int kk0 = t >> 4, n4 = (t & 15)*4;
    int tm = t >> 4, tn = t & 15;
    u64 acc[4][2] = {};
    for (int hc = 0; hc < 2; hc++) {
        #pragma unroll
        for (int k0 = 0; k0 < 256; k0 += 16)
            *(float4*)(Bf + (k0 + kk0)*64 + n4) =
                *(const float4*)(W2 + (size_t)(hc*256 + k0 + kk0)*256 + nc + n4);
        {
            int r = t >> 2, part = t & 3;
            const float* row = g_hidden + ((size_t)(b*NSLOT) + r)*512 + hc*256 + part*64;
            #pragma unroll
            for (int i = 0; i < 64; i += 4) {
                float4 v = *(const float4*)(row + i);
                Af[(part*64+i+0)*64 + r] = v.x;
                Af[(part*64+i+1)*64 + r] = v.y;
                Af[(part*64+i+2)*64 + r] = v.z;
                Af[(part*64+i+3)*64 + r] = v.w;
            }
        }
        __syncthreads();
        for (int k0 = 0; k0 < 256; k0 += 16) {
            #pragma unroll
            for (int kk = 0; kk < 16; kk++) {
                ulonglong2 a2 = *(ulonglong2*)(Af + (k0+kk)*64 + tm*4);
                float4 bb = *(float4*)(Bf + (k0+kk)*64 + tn*4);
                u64 q0 = PK1(bb.x), q1 = PK1(bb.y), q2 = PK1(bb.z), q3 = PK1(bb.w);
                FMA2(acc[0][0], a2.x, q0); FMA2(acc[0][1], a2.y, q0);
                FMA2(acc[1][0], a2.x, q1); FMA2(acc[1][1], a2.y, q1);
                FMA2(acc[2][0], a2.x, q2); FMA2(acc[2][1], a2.y, q2);
                FMA2(acc[3][0], a2.x, q3); FMA2(acc[3][1], a2.y, q3);
            }
        }
        __syncthreads();
    }
    float4 bv = *(const float4*)(b2 + nc + tn*4);
    #pragma unroll
    for (int p = 0; p < 2; p++) {
        float2 f0 = UPK(acc[0][p]), f1 = UPK(acc[1][p]), f2 = UPK(acc[2][p]), f3 = UPK(acc[3][p]);
        int mm = tm*4 + p*2;
        float* C0 = g_templates + ((size_t)(b*NSLOT) + mm)*DIM + nc + tn*4;
        float4 c0 = *(float4*)C0;
        c0.x += f0.x + bv.x; c0.y += f1.x + bv.y; c0.z += f2.x + bv.z; c0.w += f3.x + bv.w;
        *(float4*)C0 = c0;
        float* C1 = C0 + DIM;
        float4 c1 = *(float4*)C1;
        c1.x += f0.y + bv.x; c1.y += f1.y + bv.y; c1.z += f2.y + bv.z; c1.w += f3.y + bv.w;
        *(float4*)C1 = c1;
    }
}

// ---------------- outputs ----------------
// transposed copy of templates: coalesced both ways. grid 8 (b)
__global__ __launch_bounds__(256) void out_templates_kernel(float* __restrict__ out) {
    __shared__ float smt[64*65];
    int b = blockIdx.x, t = threadIdx.x;
    for (int dc = 0; dc < 4; dc++) {
        #pragma unroll
        for (int i = 0; i < 16; i++) {
            int n = i*4 + (t >> 6), dd = t & 63;
            smt[n*65 + dd] = g_templates[((size_t)(b*NSLOT) + n)*DIM + dc*64 + dd];
        }
        __syncthreads();
        #pragma unroll
        for (int i = 0; i < 16; i++) {
            int dd = i*4 + (t >> 6), n = t & 63;
            out[((size_t)(b*DIM) + dc*64 + dd)*NSLOT + n] = smt[n*65 + dd];
        }
        __syncthreads();
    }
}

// transposed copy: coalesced reads of g_attn + coalesced writes of out. grid (32, 8)
__global__ __launch_bounds__(256) void out_attn_kernel(float* __restrict__ out) {
    __shared__ float smt[128*65];
    __shared__ float inv_s[64];
    int lt = blockIdx.x, b = blockIdx.y, t = threadIdx.x;
    if (t < 64) inv_s[t] = 1.0f / g_colsum[b*NSLOT + t];
    #pragma unroll 4
    for (int i = 0; i < 32; i++) {
        int r = i*4 + (t >> 6);
        smt[r*65 + (t & 63)] = g_attn[((size_t)(b*4096) + lt*128 + r)*64 + (t & 63)];
    }
    __syncthreads();
    size_t ob = (size_t)BATCH*DIM*NSLOT + ((size_t)b*NSLOT)*LTOK + lt*128;
    for (int ng = 0; ng < 16; ng++) {
        int n = ng*4 + (t >> 6);
        float inv = inv_s[n];
        #pragma unroll
        for (int lc = 0; lc < 2; lc++) {
            int l = lc*64 + (t & 63);
            out[ob + (size_t)n*LTOK + l] = smt[l*65 + n] * inv;
        }
    }
}

// ---------------- launch ----------------
extern "C" void kernel_launch(void* const* d_in, const int* in_sizes, int n_in,
                              void* d_out, int out_size) {
    const float* x       = (const float*)d_in[0];
    const float* tinit   = (const float*)d_in[1];
    const float* conv_w  = (const float*)d_in[2];
    const float* conv_b  = (const float*)d_in[3];
    const float* Wq      = (const float*)d_in[4];
    const float* Wk      = (const float*)d_in[5];
    const float* Wv      = (const float*)d_in[6];
    const float* ln_in_g = (const float*)d_in[7];
    const float* ln_in_b = (const float*)d_in[8];
    const float* ln_t_g  = (const float*)d_in[9];
    const float* ln_t_b  = (const float*)d_in[10];
    const float* ln_m_g  = (const float*)d_in[11];
    const float* ln_m_b  = (const float*)d_in[12];
    const float* W1      = (const float*)d_in[13];
    const float* b1      = (const float*)d_in[14];
    const float* W2      = (const float*)d_in[15];
    const float* b2      = (const float*)d_in[16];
    float* out = (float*)d_out;

    cudaFuncSetAttribute(conv_mma_kernel, cudaFuncAttributeMaxDynamicSharedMemorySize, CMM_SMEM);
    cudaFuncSetAttribute(kv_mma_kernel, cudaFuncAttributeMaxDynamicSharedMemorySize, CMM_SMEM);
    cudaFuncSetAttribute(attn_gc_kernel, cudaFuncAttributeMaxDynamicSharedMemorySize, AGC_SMEM);
    cudaFuncSetAttribute(gemm_q_kernel, cudaFuncAttributeMaxDynamicSharedMemorySize, GEMMQ_SMEM);
    cudaFuncSetAttribute(gemm_h_kernel, cudaFuncAttributeMaxDynamicSharedMemorySize, GEMMH_SMEM);
    cudaFuncSetAttribute(gemm_o_kernel, cudaFuncAttributeMaxDynamicSharedMemorySize, GEMMO_SMEM);

    prep_kernel<<<3976, 256>>>(tinit, conv_w, Wk, Wv);
    xsplit_kernel<<<8*33*33, 256>>>(x);
    conv_mma_kernel<<<256, 512, CMM_SMEM>>>(conv_b, ln_in_g, ln_in_b);
    kv_mma_kernel<<<512, 512, CMM_SMEM>>>();

    for (int it = 0; it < 6; it++) {
        gemm_q_kernel<<<dim3(4, 8), 256, GEMMQ_SMEM>>>(Wq, ln_t_g, ln_t_b);
        attn_gc_kernel<<<dim3(32, 8), 256, AGC_SMEM>>>(it == 5 ? 1 : 0);
        finalize_kernel<<<dim3(8, 8), 256>>>(ln_m_g, ln_m_b);
        gemm_h_kernel<<<dim3(8, 8), 256, GEMMH_SMEM>>>(W1, b1);
        gemm_o_kernel<<<dim3(4, 8), 256, GEMMO_SMEM>>>(W2, b2);
    }

    out_templates_kernel<<<8, 256>>>(out);
    out_attn_kernel<<<dim3(32, 8), 256>>>(out);
}

// round 17
// speedup vs baseline: 1.8689x; 1.0100x over previous
#include <cuda_runtime.h>
#include <cuda_bf16.h>
#include <stdint.h>
#include <math.h>

#define BATCH 8
#define DIM   256
#define NSLOT 64
#define LTOK  4096

typedef unsigned long long u64;

__device__ __forceinline__ u64 PK1(float v) {
    u64 r; asm("mov.b64 %0, {%1,%1};" : "=l"(r) : "f"(v)); return r;
}
__device__ __forceinline__ void FMA2(u64& d, u64 a, u64 b) {
    asm("fma.rn.f32x2 %0, %1, %2, %0;" : "+l"(d) : "l"(a), "l"(b));
}
__device__ __forceinline__ float2 UPK(u64 v) {
    float2 f; asm("mov.b64 {%0,%1}, %2;" : "=f"(f.x), "=f"(f.y) : "l"(v)); return f;
}

// ---------------- scratch ----------------
__device__ float g_templates[BATCH*NSLOT*DIM];
__device__ float g_tbuf[BATCH*NSLOT*DIM];
__device__ float g_attn[BATCH*LTOK*NSLOT];
__device__ float g_colsum_part[BATCH*64*NSLOT];
__device__ float g_colsum[BATCH*NSLOT];
__device__ float g_accpart[32*BATCH*NSLOT*DIM];
__device__ float g_hidden[BATCH*NSLOT*512];
// bf16 split operands
__device__ __nv_bfloat16 g_xh[36799488];
__device__ __nv_bfloat16 g_xl[36799488];
__device__ __nv_bfloat16 g_cwh[27*32768];
__device__ __nv_bfloat16 g_cwl[27*32768];
__device__ __nv_bfloat16 g_kvh[256*512];
__device__ __nv_bfloat16 g_kvl[256*512];
__device__ __nv_bfloat16 g_toksh[32768*256];
__device__ __nv_bfloat16 g_toksl[32768*256];
__device__ __nv_bfloat16 g_kh[32768*256];
__device__ __nv_bfloat16 g_kl[32768*256];
__device__ __nv_bfloat16 g_vh[32768*256];
__device__ __nv_bfloat16 g_vl[32768*256];
__device__ __nv_bfloat16 g_qh[BATCH*NSLOT*DIM];
__device__ __nv_bfloat16 g_ql[BATCH*NSLOT*DIM];

__device__ __forceinline__ float gelu_exact(float v) {
    return 0.5f * v * (1.0f + erff(v * 0.70710678118654752f));
}

// ========== mma.sync helpers ==========
__device__ __forceinline__ uint32_t smem_u32(const void* p) {
    uint32_t a;
    asm("{ .reg .u64 t; cvta.to.shared.u64 t, %1; cvt.u32.u64 %0, t; }" : "=r"(a) : "l"(p));
    return a;
}
__device__ __forceinline__ void ldsm_x4(uint32_t* r, uint32_t addr) {
    asm volatile("ldmatrix.sync.aligned.m8n8.x4.shared.b16 {%0,%1,%2,%3}, [%4];"
        : "=r"(r[0]), "=r"(r[1]), "=r"(r[2]), "=r"(r[3]) : "r"(addr));
}
__device__ __forceinline__ void ldsm_x4_t(uint32_t* r, uint32_t addr) {
    asm volatile("ldmatrix.sync.aligned.m8n8.x4.trans.shared.b16 {%0,%1,%2,%3}, [%4];"
        : "=r"(r[0]), "=r"(r[1]), "=r"(r[2]), "=r"(r[3]) : "r"(addr));
}
__device__ __forceinline__ void mma_bf16(float* d, const uint32_t* a, const uint32_t* b) {
    asm volatile("mma.sync.aligned.m16n8k16.row.col.f32.bf16.bf16.f32 "
        "{%0,%1,%2,%3}, {%4,%5,%6,%7}, {%8,%9}, {%0,%1,%2,%3};"
        : "+f"(d[0]), "+f"(d[1]), "+f"(d[2]), "+f"(d[3])
        : "r"(a[0]), "r"(a[1]), "r"(a[2]), "r"(a[3]), "r"(b[0]), "r"(b[1]));
}
__device__ __forceinline__ void bsplit(float v0, float v1, __nv_bfloat162& hh, __nv_bfloat162& ll) {
    __nv_bfloat16 h0 = __float2bfloat16(v0), h1 = __float2bfloat16(v1);
    hh.x = h0; hh.y = h1;
    ll.x = __float2bfloat16(v0 - __bfloat162float(h0));
    ll.y = __float2bfloat16(v1 - __bfloat162float(h1));
}
__device__ __forceinline__ void cpa16(uint32_t dst, const void* src) {
    asm volatile("cp.async.cg.shared.global [%0], [%1], 16;" :: "r"(dst), "l"(src) : "memory");
}
#define CP_COMMIT asm volatile("cp.async.commit_group;" ::: "memory")
#define CP_WAIT0  asm volatile("cp.async.wait_group 0;" ::: "memory")
#define CP_WAIT1  asm volatile("cp.async.wait_group 1;" ::: "memory")

// 128x256 += A(128x128, pitch 272B) x B(128k x 256n, pitch 528B); 3-term bf16 split.
__device__ __forceinline__ void mma_chunk(
    uint32_t sAh, uint32_t sAl, uint32_t sBh, uint32_t sBl,
    float d[2][8][4], int wm, int wn, int lane)
{
    uint32_t aoff0 = (uint32_t)((wm*32 + (lane & 15))*272 + (lane >> 4)*16);
    uint32_t boff0 = (uint32_t)((lane & 15)*528 + (wn*64 + (lane >> 4)*8)*2);
    #pragma unroll
    for (int kk = 0; kk < 8; kk++) {
        uint32_t ah[8], al[8], bb[16];
        uint32_t ao = aoff0 + kk*32;
        ldsm_x4(ah,     sAh + ao);
        ldsm_x4(ah + 4, sAh + ao + 4352);
        ldsm_x4(al,     sAl + ao);
        ldsm_x4(al + 4, sAl + ao + 4352);
        uint32_t bo = boff0 + kk*8448;
        #pragma unroll
        for (int jj = 0; jj < 4; jj++) ldsm_x4_t(bb + jj*4, sBh + bo + jj*32);
        #pragma unroll
        for (int mi = 0; mi < 2; mi++) {
            #pragma unroll
            for (int j = 0; j < 8; j++) {
                const uint32_t* bf = bb + (j >> 1)*4 + (j & 1)*2;
                mma_bf16(d[mi][j], mi ? ah + 4 : ah, bf);
                mma_bf16(d[mi][j], mi ? al + 4 : al, bf);
            }
        }
        #pragma unroll
        for (int jj = 0; jj < 4; jj++) ldsm_x4_t(bb + jj*4, sBl + bo + jj*32);
        #pragma unroll
        for (int mi = 0; mi < 2; mi++) {
            #pragma unroll
            for (int j = 0; j < 8; j++) {
                const uint32_t* bf = bb + (j >> 1)*4 + (j & 1)*2;
                mma_bf16(d[mi][j], mi ? ah + 4 : ah, bf);
            }
        }
    }
}

// dual-term pass: d += Ah*B + Al*B
__device__ __forceinline__ void mma_dual(
    uint32_t sAh, uint32_t sAl, uint32_t sB,
    float d[2][8][4], int wm, int wn, int lane)
{
    uint32_t aoff0 = (uint32_t)((wm*32 + (lane & 15))*272 + (lane >> 4)*16);
    uint32_t boff0 = (uint32_t)((lane & 15)*528 + (wn*64 + (lane >> 4)*8)*2);
    #pragma unroll
    for (int kk = 0; kk < 8; kk++) {
        uint32_t ah[8], al[8], bb[16];
        uint32_t ao = aoff0 + kk*32;
        ldsm_x4(ah,     sAh + ao);
        ldsm_x4(ah + 4, sAh + ao + 4352);
        ldsm_x4(al,     sAl + ao);
        ldsm_x4(al + 4, sAl + ao + 4352);
        uint32_t bo = boff0 + kk*8448;
        #pragma unroll
        for (int jj = 0; jj < 4; jj++) ldsm_x4_t(bb + jj*4, sB + bo + jj*32);
        #pragma unroll
        for (int mi = 0; mi < 2; mi++) {
            #pragma unroll
            for (int j = 0; j < 8; j++) {
                const uint32_t* bf = bb + (j >> 1)*4 + (j & 1)*2;
                mma_bf16(d[mi][j], mi ? ah + 4 : ah, bf);
                mma_bf16(d[mi][j], mi ? al + 4 : al, bf);
            }
        }
    }
}

// single-term pass: d += Ah*B
__device__ __forceinline__ void mma_single(
    uint32_t sAh, uint32_t sB,
    float d[2][8][4], int wm, int wn, int lane)
{
    uint32_t aoff0 = (uint32_t)((wm*32 + (lane & 15))*272 + (lane >> 4)*16);
    uint32_t boff0 = (uint32_t)((lane & 15)*528 + (wn*64 + (lane >> 4)*8)*2);
    #pragma unroll
    for (int kk = 0; kk < 8; kk++) {
        uint32_t ah[8], bb[16];
        uint32_t ao = aoff0 + kk*32;
        ldsm_x4(ah,     sAh + ao);
        ldsm_x4(ah + 4, sAh + ao + 4352);
        uint32_t bo = boff0 + kk*8448;
        #pragma unroll
        for (int jj = 0; jj < 4; jj++) ldsm_x4_t(bb + jj*4, sB + bo + jj*32);
        #pragma unroll
        for (int mi = 0; mi < 2; mi++) {
            #pragma unroll
            for (int j = 0; j < 8; j++) {
                const uint32_t* bf = bb + (j >> 1)*4 + (j & 1)*2;
                mma_bf16(d[mi][j], mi ? ah + 4 : ah, bf);
            }
        }
    }
}

// ---------------- merged prep: cwsplit | kvsplit | templates_init ----------------
__global__ void prep_kernel(const float* __restrict__ tinit, const float* __restrict__ cw,
                            const float* __restrict__ Wk, const float* __restrict__ Wv) {
    int bid = blockIdx.x;
    if (bid < 3456) {
        int idx = bid*256 + threadIdx.x;
        int tap = idx >> 15, r = idx & 32767;
        int k = r >> 8, n = r & 255;
        float v = cw[(size_t)n*3456 + k*27 + tap];
        __nv_bfloat16 hi = __float2bfloat16(v);
        g_cwh[idx] = hi;
        g_cwl[idx] = __float2bfloat16(v - __bfloat162float(hi));
    } else if (bid < 3968) {
        int idx = (bid - 3456)*256 + threadIdx.x;
        int k = idx >> 9, c512 = idx & 511;
        int mat = c512 >> 8, col = c512 & 255;
        const float* W = mat ? Wv : Wk;
        float v = W[(size_t)k*256 + col];
        __nv_bfloat16 hi = __float2bfloat16(v);
        g_kvh[idx] = hi;
        g_kvl[idx] = __float2bfloat16(v - __bfloat162float(hi));
    } else {
        int b = bid - 3968, t = threadIdx.x;
        for (int n = 0; n < NSLOT; n++)
            g_templates[(b*NSLOT + n)*DIM + t] = tinit[n*DIM + t];
    }
}

__global__ __launch_bounds__(256) void xsplit_kernel(const float* __restrict__ x) {
    __shared__ float st[128*33];
    int bid = blockIdx.x; int b = bid / 1089; int rem = bid % 1089; int d = rem / 33, h = rem % 33;
    int t = threadIdx.x, warp = t >> 5, lane = t & 31;
    const float* xb = x + ((((size_t)b*128)*33 + d)*33 + h)*33;
    for (int c = warp; c < 128; c += 8) {
        const float* src = xb + (size_t)c*35937;
        st[c*33 + lane] = src[lane];
        if (lane == 0) st[c*33 + 32] = src[32];
    }
    __syncthreads();
    size_t ob = ((((size_t)b*33 + d)*33 + h)*33)*128;
    for (int i = t; i < 33*128; i += 256) {
        int w = i >> 7, c = i & 127;
        float v = st[c*33 + w];
        __nv_bfloat16 hi = __float2bfloat16(v);
        g_xh[ob + (size_t)w*128 + c] = hi;
        g_xl[ob + (size_t)w*128 + c] = __float2bfloat16(v - __bfloat162float(hi));
    }
}

// ---------------- conv (implicit GEMM, cp.async-pipelined A+B, L2 A-prefetch) ----------------
#define CMM_SMEM 204800
__global__ __launch_bounds__(512, 1) void conv_mma_kernel(
    const float* __restrict__ convb, const float* __restrict__ lng, const float* __restrict__ lnb)
{
    extern __shared__ char sm[];
    uint32_t sb = smem_u32(sm);
    const uint32_t oAh = 0, oAl = 34816, oB0 = 69632, oB1 = 137216;
    int t = threadIdx.x, lane = t & 31, wid = t >> 5;
    int wm = wid >> 2, wn = wid & 3;
    int bx = blockIdx.x; int b = bx >> 5, xd = (bx >> 1) & 15, half = bx & 1;

    float d[2][8][4];
    #pragma unroll
    for (int i = 0; i < 2; i++)
        #pragma unroll
        for (int j = 0; j < 8; j++)
            #pragma unroll
            for (int c = 0; c < 4; c++) d[i][j][c] = 0.f;

    int m = t >> 2, q = t & 3;
    int xhl = m >> 4, xw = m & 15;

    {
        const uint4* s1 = (const uint4*)(g_cwh);
        #pragma unroll
        for (int it = 0; it < 8; it++) {
            int i = t + it*512;
            cpa16(sb + oB0 + (uint32_t)((i >> 5)*528 + (i & 31)*16), s1 + i);
        }
        CP_COMMIT;
    }

    for (int tap = 0; tap < 27; tap++) {
        int kd = tap/9, r9 = tap%9, kh = r9/3, kw = r9%3;
        {   // A tiles via cp.async
            size_t xi = ((((size_t)(b*33) + 2*xd + kd)*33 + 2*(half*8 + xhl) + kh)*33 + 2*xw + kw)*128 + q*32;
            const uint4* shi = (const uint4*)(g_xh + xi);
            const uint4* slo = (const uint4*)(g_xl + xi);
            uint32_t dh = sb + oAh + (uint32_t)(m*272 + q*64);
            uint32_t dl = sb + oAl + (uint32_t)(m*272 + q*64);
            #pragma unroll
            for (int j = 0; j < 4; j++) {
                cpa16(dh + j*16, shi + j);
                cpa16(dl + j*16, slo + j);
            }
            CP_COMMIT;
        }
        // L2 prefetch of next tap's A rows (overlaps this tap's MMA)
        if (tap < 26) {
            int tn2 = tap + 1;
            int kd2 = tn2/9, r92 = tn2%9, kh2 = r92/3, kw2 = r92%3;
            size_t xi2 = ((((size_t)(b*33) + 2*xd + kd2)*33 + 2*(half*8 + xhl) + kh2)*33 + 2*xw + kw2)*128 + q*32;
            asm volatile("prefetch.global.L2 [%0];" :: "l"(g_xh + xi2));
            asm volatile("prefetch.global.L2 [%0];" :: "l"(g_xl + xi2));
        }
        CP_WAIT0;          // A(tap) + Bh(tap)
        __syncthreads();
        {
            const uint4* s2 = (const uint4*)(g_cwl + tap*32768);
            #pragma unroll
            for (int it = 0; it < 8; it++) {
                int i = t + it*512;
                cpa16(sb + oB1 + (uint32_t)((i >> 5)*528 + (i & 31)*16), s2 + i);
            }
            CP_COMMIT;
        }
        mma_dual(sb + oAh, sb + oAl, sb + oB0, d, wm, wn, lane);
        CP_WAIT0;          // Bl(tap)
        __syncthreads();
        if (tap < 26) {
            const uint4* s1 = (const uint4*)(g_cwh + (tap+1)*32768);
            #pragma unroll
            for (int it = 0; it < 8; it++) {
                int i = t + it*512;
                cpa16(sb + oB0 + (uint32_t)((i >> 5)*528 + (i & 31)*16), s1 + i);
            }
            CP_COMMIT;
        }
        mma_single(sb + oAh, sb + oB1, d, wm, wn, lane);
        __syncthreads();
    }

    float* stg = (float*)sm;
    {
        int r0 = wm*32 + (lane >> 2);
        int c0 = wn*64 + (lane & 3)*2;
        #pragma unroll
        for (int mi = 0; mi < 2; mi++)
            #pragma unroll
            for (int j = 0; j < 8; j++) {
                int rr = r0 + mi*16, cc = c0 + j*8;
                *(float2*)(stg + (size_t)rr*264 + cc)     = make_float2(d[mi][j][0], d[mi][j][1]);
                *(float2*)(stg + (size_t)(rr+8)*264 + cc) = make_float2(d[mi][j][2], d[mi][j][3]);
            }
    }
    __syncthreads();

    {
        int tok = t >> 2, q2 = t & 3;
        const float* src = stg + (size_t)tok*264 + q2*64;
        float z[64];
        float s = 0.f, sq = 0.f;
        #pragma unroll
        for (int i = 0; i < 64; i++) {
            float v = fmaxf(src[i] + convb[q2*64 + i], 0.f);
            z[i] = v; s += v; sq += v*v;
        }
        s  += __shfl_xor_sync(0xffffffffu, s, 1);  s  += __shfl_xor_sync(0xffffffffu, s, 2);
        sq += __shfl_xor_sync(0xffffffffu, sq, 1); sq += __shfl_xor_sync(0xffffffffu, sq, 2);
        float mu = s * (1.f/256.f);
        float rs = rsqrtf(sq * (1.f/256.f) - mu*mu + 1e-5f);
        int l = (xd*16 + half*8 + (tok >> 4))*16 + (tok & 15);
        size_t tg = ((size_t)b*4096 + l)*256 + q2*64;
        #pragma unroll
        for (int i = 0; i < 64; i += 2) {
            int ch = q2*64 + i;
            float v0 = (z[i]   - mu)*rs*lng[ch]   + lnb[ch];
            float v1 = (z[i+1] - mu)*rs*lng[ch+1] + lnb[ch+1];
            __nv_bfloat162 hh, ll;
            bsplit(v0, v1, hh, ll);
            *(__nv_bfloat162*)(g_toksh + tg + i) = hh;
            *(__nv_bfloat162*)(g_toksl + tg + i) = ll;
        }
    }
}

// ---------------- K/V projection via mma.sync (cp.async loads) ----------------
__global__ __launch_bounds__(512, 1) void kv_mma_kernel() {
    extern __shared__ char sm[];
    uint32_t sb = smem_u32(sm);
    const uint32_t oAh = 0, oAl = 34816, oBh = 69632, oBl = 137216;
    int t = threadIdx.x, lane = t & 31, wid = t >> 5;
    int wm = wid >> 2, wn = wid & 3;
    int nhalf = blockIdx.x & 1, chunk = blockIdx.x >> 1;

    float d[2][8][4];
    #pragma unroll
    for (int i = 0; i < 2; i++)
        #pragma unroll
        for (int j = 0; j < 8; j++)
            #pragma unroll
            for (int c = 0; c < 4; c++) d[i][j][c] = 0.f;

    int m = t >> 2, q = t & 3;
    for (int kc = 0; kc < 2; kc++) {
        {   // A tokens via cp.async
            size_t ti = ((size_t)(chunk*128 + m))*256 + kc*128 + q*32;
            const uint4* shi = (const uint4*)(g_toksh + ti);
            const uint4* slo = (const uint4*)(g_toksl + ti);
            uint32_t dh = sb + oAh + (uint32_t)(m*272 + q*64);
            uint32_t dl = sb + oAl + (uint32_t)(m*272 + q*64);
            #pragma unroll
            for (int j = 0; j < 4; j++) {
                cpa16(dh + j*16, shi + j);
                cpa16(dl + j*16, slo + j);
            }
        }
        {   // B weights via cp.async
            #pragma unroll
            for (int it = 0; it < 8; it++) {
                int i = t + it*512;
                int row = i >> 5, seg = i & 31;
                size_t off = (size_t)(kc*128 + row)*512 + nhalf*256 + seg*8;
                cpa16(sb + oBh + (uint32_t)(row*528 + seg*16), g_kvh + off);
                cpa16(sb + oBl + (uint32_t)(row*528 + seg*16), g_kvl + off);
            }
        }
        CP_COMMIT;
        CP_WAIT0;
        __syncthreads();
        mma_chunk(sb + oAh, sb + oAl, sb + oBh, sb + oBl, d, wm, wn, lane);
        __syncthreads();
    }

    __nv_bfloat16* dh = nhalf ? g_vh : g_kh;
    __nv_bfloat16* dl = nhalf ? g_vl : g_kl;
    int r0 = wm*32 + (lane >> 2);
    int c0 = wn*64 + (lane & 3)*2;
    #pragma unroll
    for (int mi = 0; mi < 2; mi++)
        #pragma unroll
        for (int j = 0; j < 8; j++) {
            int rr = r0 + mi*16, cc = c0 + j*8;
            size_t tok = (size_t)chunk*128 + rr;
            __nv_bfloat162 hh, ll;
            bsplit(d[mi][j][0], d[mi][j][1], hh, ll);
            *(__nv_bfloat162*)(dh + tok*256 + cc) = hh;
            *(__nv_bfloat162*)(dl + tok*256 + cc) = ll;
            bsplit(d[mi][j][2], d[mi][j][3], hh, ll);
            *(__nv_bfloat162*)(dh + (tok+8)*256 + cc) = hh;
            *(__nv_bfloat162*)(dl + (tok+8)*256 + cc) = ll;
        }
}

// ---------------- fused LN_t + q-GEMM (full B preload, sync-free compute) ----------------
#define GEMMQ_SMEM ((16384 + 16384)*4)
__global__ __launch_bounds__(256) void gemm_q_kernel(
    const float* __restrict__ Wq, const float* __restrict__ lng, const float* __restrict__ lnb)
{
    extern __shared__ float smf[];
    float* Af = smf; float* Bf = smf + 16384;
    int b = blockIdx.y; int nc = blockIdx.x * 64;
    int t = threadIdx.x;
    int kk0 = t >> 4, n4 = (t & 15)*4;
    #pragma unroll
    for (int k0 = 0; k0 < 256; k0 += 16)
        *(float4*)(Bf + (k0 + kk0)*64 + n4) = *(const float4*)(Wq + (size_t)(k0+kk0)*256 + nc + n4);
    {
        int r = t >> 2, part = t & 3;
        const float* row = g_templates + ((size_t)(b*NSLOT) + r)*DIM + part*64;
        float s = 0.f, sq = 0.f;
        #pragma unroll
        for (int i = 0; i < 64; i += 4) {
            float4 v = *(const float4*)(row + i);
            s += v.x+v.y+v.z+v.w;
            sq += v.x*v.x + v.y*v.y + v.z*v.z + v.w*v.w;
        }
        s  += __shfl_xor_sync(0xffffffffu, s, 1);  s  += __shfl_xor_sync(0xffffffffu, s, 2);
        sq += __shfl_xor_sync(0xffffffffu, sq, 1); sq += __shfl_xor_sync(0xffffffffu, sq, 2);
        float mu = s * (1.0f/256.0f);
        float rs = rsqrtf(sq * (1.0f/256.0f) - mu*mu + 1e-5f);
        #pragma unroll
        for (int i = 0; i < 64; i += 4) {
            float4 v = *(const float4*)(row + i);
            float4 gg = *(const float4*)(lng + part*64 + i);
            float4 bv = *(const float4*)(lnb + part*64 + i);
            Af[(part*64+i+0)*64 + r] = (v.x - mu)*rs*gg.x + bv.x;
            Af[(part*64+i+1)*64 + r] = (v.y - mu)*rs*gg.y + bv.y;
            Af[(part*64+i+2)*64 + r] = (v.z - mu)*rs*gg.z + bv.z;
            Af[(part*64+i+3)*64 + r] = (v.w - mu)*rs*gg.w + bv.w;
        }
    }
    __syncthreads();

    int tm = t >> 4, tn = t & 15;
    u64 acc[4][2] = {};
    for (int k0 = 0; k0 < 256; k0 += 16) {
        #pragma unroll
        for (int kk = 0; kk < 16; kk++) {
            ulonglong2 a2 = *(ulonglong2*)(Af + (k0+kk)*64 + tm*4);
            float4 bb = *(float4*)(Bf + (k0+kk)*64 + tn*4);
            u64 q0 = PK1(bb.x), q1 = PK1(bb.y), q2 = PK1(bb.z), q3 = PK1(bb.w);
            FMA2(acc[0][0], a2.x, q0); FMA2(acc[0][1], a2.y, q0);
            FMA2(acc[1][0], a2.x, q1); FMA2(acc[1][1], a2.y, q1);
            FMA2(acc[2][0], a2.x, q2); FMA2(acc[2][1], a2.y, q2);
            FMA2(acc[3][0], a2.x, q3); FMA2(acc[3][1], a2.y, q3);
        }
    }
    const float scale = 0.0625f;
    #pragma unroll
    for (int p = 0; p < 2; p++) {
        float2 f0 = UPK(acc[0][p]), f1 = UPK(acc[1][p]), f2 = UPK(acc[2][p]), f3 = UPK(acc[3][p]);
        int mm = tm*4 + p*2;
        size_t o0 = ((size_t)(b*NSLOT) + mm)*DIM + nc + tn*4;
        __nv_bfloat162 hh, ll;
        bsplit(f0.x*scale, f1.x*scale, hh, ll);
        *(__nv_bfloat162*)(g_qh + o0) = hh; *(__nv_bfloat162*)(g_ql + o0) = ll;
        bsplit(f2.x*scale, f3.x*scale, hh, ll);
        *(__nv_bfloat162*)(g_qh + o0 + 2) = hh; *(__nv_bfloat162*)(g_ql + o0 + 2) = ll;
        bsplit(f0.y*scale, f1.y*scale, hh, ll);
        *(__nv_bfloat162*)(g_qh + o0 + DIM) = hh; *(__nv_bfloat162*)(g_ql + o0 + DIM) = ll;
        bsplit(f2.y*scale, f3.y*scale, hh, ll);
        *(__nv_bfloat162*)(g_qh + o0 + DIM + 2) = hh; *(__nv_bfloat162*)(g_ql + o0 + DIM + 2) = ll;
    }
}

// ---------------- FUSED attn logits + softmax + colsum + attn^T@v ----------------
#define AGC_SMEM 208896
__global__ __launch_bounds__(256) void attn_gc_kernel(int write_attn) {
    extern __shared__ char sm[];
    uint32_t sb = smem_u32(sm);
    const uint32_t oK0h = 0, oK0l = 34816, oQ0h = 69632, oQ0l = 87040;
    const uint32_t oK1h = 104448, oK1l = 139264, oQ1h = 174080, oQ1l = 191488;
    const uint32_t oStg = 0, oAth = 34816, oAtl = 53248;
    const uint32_t oVh = 71680, oVl = 139264;
    int t = threadIdx.x, lane = t & 31, wid = t >> 5;
    int lb = blockIdx.x, b = blockIdx.y;

    int wm = wid >> 1, wn = wid & 1;
    float d[2][4][4];
    #pragma unroll
    for (int i = 0; i < 2; i++)
        #pragma unroll
        for (int j = 0; j < 4; j++)
            #pragma unroll
            for (int c = 0; c < 4; c++) d[i][j][c] = 0.f;

    #pragma unroll
    for (int kc = 0; kc < 2; kc++) {
        uint32_t bKh = kc ? oK1h : oK0h, bKl = kc ? oK1l : oK0l;
        uint32_t bQh = kc ? oQ1h : oQ0h, bQl = kc ? oQ1l : oQ0l;
        {
            int row = t >> 1, half = t & 1;
            size_t ti = ((size_t)(b*4096) + lb*128 + row)*256 + kc*128 + half*64;
            const uint4* shi = (const uint4*)(g_kh + ti);
            const uint4* slo = (const uint4*)(g_kl + ti);
            uint32_t dh = sb + bKh + (uint32_t)(row*272 + half*128);
            uint32_t dl = sb + bKl + (uint32_t)(row*272 + half*128);
            #pragma unroll
            for (int j = 0; j < 8; j++) {
                cpa16(dh + j*16, shi + j);
                cpa16(dl + j*16, slo + j);
            }
        }
        {
            int row = t >> 2, q4 = t & 3;
            size_t ti = ((size_t)(b*NSLOT) + row)*256 + kc*128 + q4*32;
            const uint4* shi = (const uint4*)(g_qh + ti);
            const uint4* slo = (const uint4*)(g_ql + ti);
            uint32_t dh = sb + bQh + (uint32_t)(row*272 + q4*64);
            uint32_t dl = sb + bQl + (uint32_t)(row*272 + q4*64);
            #pragma unroll
            for (int j = 0; j < 4; j++) {
                cpa16(dh + j*16, shi + j);
                cpa16(dl + j*16, slo + j);
            }
        }
        CP_COMMIT;
    }

    #pragma unroll
    for (int kc = 0; kc < 2; kc++) {
        if (kc == 0) { CP_WAIT1; } else { CP_WAIT0; }
        __syncthreads();
        uint32_t bKh = kc ? oK1h : oK0h, bKl = kc ? oK1l : oK0l;
        uint32_t bQh = kc ? oQ1h : oQ0h, bQl = kc ? oQ1l : oQ0l;
        uint32_t aoff0 = (uint32_t)((wm*32 + (lane & 15))*272 + (lane >> 4)*16);
        uint32_t qoff0 = (uint32_t)(((lane >> 4)*8 + (lane & 7) + wn*32)*272 + ((lane >> 3) & 1)*16);
        #pragma unroll
        for (int kk = 0; kk < 8; kk++) {
            uint32_t ah[8], al[8], qh8[8], ql8[8];
            uint32_t ao = aoff0 + kk*32;
            ldsm_x4(ah,     sb + bKh + ao);
            ldsm_x4(ah + 4, sb + bKh + ao + 16*272);
            ldsm_x4(al,     sb + bKl + ao);
            ldsm_x4(al + 4, sb + bKl + ao + 16*272);
            uint32_t qo = qoff0 + kk*32;
            ldsm_x4(qh8,     sb + bQh + qo);
            ldsm_x4(qh8 + 4, sb + bQh + qo + 16*272);
            ldsm_x4(ql8,     sb + bQl + qo);
            ldsm_x4(ql8 + 4, sb + bQl + qo + 16*272);
            #pragma unroll
            for (int mi = 0; mi < 2; mi++) {
                #pragma unroll
                for (int j = 0; j < 4; j++) {
                    const uint32_t* bh = qh8 + (j >> 1)*4 + (j & 1)*2;
                    const uint32_t* bl = ql8 + (j >> 1)*4 + (j & 1)*2;
                    const uint32_t* am = mi ? ah + 4 : ah;
                    const uint32_t* aml = mi ? al + 4 : al;
                    mma_bf16(d[mi][j], am, bh);
                    mma_bf16(d[mi][j], am, bl);
                    mma_bf16(d[mi][j], aml, bh);
                }
            }
        }
        __syncthreads();
    }

    // prefetch V (dest aliases dead Q0/K1/Q1 regions), overlapped with softmax/colsum
    {
        int row = t >> 1, half = t & 1;
        size_t ti = ((size_t)(b*4096) + lb*128 + row)*256 + half*128;
        const uint4* shi = (const uint4*)(g_vh + ti);
        const uint4* slo = (const uint4*)(g_vl + ti);
        uint32_t dsh = sb + oVh + (uint32_t)(row*528 + half*256);
        uint32_t dsl = sb + oVl + (uint32_t)(row*528 + half*256);
        #pragma unroll
        for (int j = 0; j < 16; j++) {
            cpa16(dsh + j*16, shi + j);
            cpa16(dsl + j*16, slo + j);
        }
        CP_COMMIT;
    }

    float* stg = (float*)(sm + oStg);
    {
        int r0 = wm*32 + (lane >> 2);
        int c0 = wn*32 + (lane & 3)*2;
        #pragma unroll
        for (int mi = 0; mi < 2; mi++)
            #pragma unroll
            for (int j = 0; j < 4; j++) {
                int rr = r0 + mi*16, cc = c0 + j*8;
                *(float2*)(stg + rr*68 + cc)     = make_float2(d[mi][j][0], d[mi][j][1]);
                *(float2*)(stg + (rr+8)*68 + cc) = make_float2(d[mi][j][2], d[mi][j][3]);
            }
    }
    __syncthreads();

    {
        int row = t >> 1, half = t & 1;
        float* sr = stg + row*68 + half*32;
        float a[32];
        float mx = -3.4e38f;
        #pragma unroll
        for (int i = 0; i < 32; i++) { a[i] = sr[i]; mx = fmaxf(mx, a[i]); }
        mx = fmaxf(mx, __shfl_xor_sync(0xffffffffu, mx, 1));
        float s = 0.f;
        #pragma unroll
        for (int i = 0; i < 32; i++) { a[i] = expf(a[i] - mx); s += a[i]; }
        s += __shfl_xor_sync(0xffffffffu, s, 1);
        float inv = 1.0f / s;
        #pragma unroll
        for (int i = 0; i < 32; i++) { a[i] = a[i]*inv + 1e-8f; sr[i] = a[i]; }
        if (write_attn) {
            size_t gi = ((size_t)(b*4096) + lb*128 + row)*64 + half*32;
            #pragma unroll
            for (int i = 0; i < 32; i += 4)
                *(float4*)(g_attn + gi + i) = make_float4(a[i], a[i+1], a[i+2], a[i+3]);
        }
        char* dst_h = sm + oAth + row*144 + half*64;
        char* dst_l = sm + oAtl + row*144 + half*64;
        #pragma unroll
        for (int i = 0; i < 32; i += 2) {
            __nv_bfloat162 hh, ll;
            bsplit(a[i], a[i+1], hh, ll);
            *(__nv_bfloat162*)(dst_h + i*2) = hh;
            *(__nv_bfloat162*)(dst_l + i*2) = ll;
        }
    }
    __syncthreads();
    // parallel colsum: 128 threads, two half-partials per (lb, n)
    if (t < 128) {
        int n = t & 63, h = t >> 6;
        float s = 0.f;
        for (int r = 0; r < 64; r++) s += stg[(h*64 + r)*68 + n];
        g_colsum_part[((size_t)b*64 + lb*2 + h)*NSLOT + n] = s;
    }

    CP_WAIT0;         // V landed
    __syncthreads();

    int wm2 = wid & 1, wn2 = wid >> 1;
    float d2[2][8][4];
    #pragma unroll
    for (int i = 0; i < 2; i++)
        #pragma unroll
        for (int j = 0; j < 8; j++)
            #pragma unroll
            for (int c = 0; c < 4; c++) d2[i][j][c] = 0.f;
    {
        uint32_t aoff0 = (uint32_t)((((lane >> 4)*8 + (lane & 7)))*144 + ((lane >> 3) & 1)*16 + wm2*64);
        uint32_t boff0 = (uint32_t)((lane & 15)*528 + (wn2*64 + (lane >> 4)*8)*2);
        #pragma unroll
        for (int kk = 0; kk < 8; kk++) {
            uint32_t ah[8], al[8], bh8[16], bl8[16];
            uint32_t ao = aoff0 + kk*16*144;
            ldsm_x4_t(ah,     sb + oAth + ao);
            ldsm_x4_t(ah + 4, sb + oAth + ao + 32);
            ldsm_x4_t(al,     sb + oAtl + ao);
            ldsm_x4_t(al + 4, sb + oAtl + ao + 32);
            uint32_t bo = boff0 + kk*8448;
            #pragma unroll
            for (int jj = 0; jj < 4; jj++) ldsm_x4_t(bh8 + jj*4, sb + oVh + bo + jj*32);
            #pragma unroll
            for (int jj = 0; jj < 4; jj++) ldsm_x4_t(bl8 + jj*4, sb + oVl + bo + jj*32);
            #pragma unroll
            for (int mi = 0; mi < 2; mi++) {
                #pragma unroll
                for (int j = 0; j < 8; j++) {
                    const uint32_t* bfh = bh8 + (j >> 1)*4 + (j & 1)*2;
                    const uint32_t* bfl = bl8 + (j >> 1)*4 + (j & 1)*2;
                    const uint32_t* am = mi ? ah + 4 : ah;
                    const uint32_t* aml = mi ? al + 4 : al;
                    mma_bf16(d2[mi][j], am, bfh);
                    mma_bf16(d2[mi][j], am, bfl);
                    mma_bf16(d2[mi][j], aml, bfh);
                }
            }
        }
    }

    int r0 = wm2*32 + (lane >> 2);
    int c0 = wn2*64 + (lane & 3)*2;
    float* C = g_accpart + ((size_t)((lb*BATCH + b)*NSLOT))*DIM;
    #pragma unroll
    for (int mi = 0; mi < 2; mi++)
        #pragma unroll
        for (int j = 0; j < 8; j++) {
            int slot = r0 + mi*16, cc = c0 + j*8;
            *(float2*)(C + (size_t)slot*DIM + cc)     = make_float2(d2[mi][j][0], d2[mi][j][1]);
            *(float2*)(C + (size_t)(slot+8)*DIM + cc) = make_float2(d2[mi][j][2], d2[mi][j][3]);
        }
}

// ---------------- colsum + template update + LN_m. grid (8 ng, 8 b) ----------------
__global__ __launch_bounds__(256) void finalize_kernel(const float* __restrict__ g,
                                                       const float* __restrict__ bb) {
    __shared__ float tv[8*256];
    __shared__ float csin_s[8];
    int ng = blockIdx.x, b = blockIdx.y, t = threadIdx.x;
    {
        int s = t >> 5, l = t & 31;
        int n = ng*8 + s;
        float v = g_colsum_part[((size_t)b*64 + 2*l)*NSLOT + n]
                + g_colsum_part[((size_t)b*64 + 2*l + 1)*NSLOT + n];
        #pragma unroll
        for (int m = 16; m; m >>= 1) v += __shfl_xor_sync(0xffffffffu, v, m);
        if (l == 0) { csin_s[s] = 1.0f / v; g_colsum[b*NSLOT + n] = v; }
    }
    __syncthreads();
    #pragma unroll
    for (int s = 0; s < 8; s++) {
        int n = ng*8 + s;
        float acc = 0.f;
        #pragma unroll 8
        for (int p = 0; p < 32; p++)
            acc += g_accpart[((size_t)(p*BATCH + b)*NSLOT + n)*DIM + t];
        size_t idx = ((size_t)(b*NSLOT) + n)*DIM + t;
        float val = g_templates[idx] + acc * csin_s[s];
        g_templates[idx] = val;
        tv[s*256 + t] = val;
    }
    __syncthreads();
    {
        int w = t >> 5, l = t & 31;
        const float* row = tv + w*256;
        float s1 = 0.f, s2 = 0.f;
        #pragma unroll
        for (int i = l; i < 256; i += 32) { float v = row[i]; s1 += v; s2 += v*v; }
        #pragma unroll
        for (int m = 16; m; m >>= 1) {
            s1 += __shfl_xor_sync(0xffffffffu, s1, m);
            s2 += __shfl_xor_sync(0xffffffffu, s2, m);
        }
        float mu = s1 * (1.f/256.f);
        float rs = rsqrtf(s2 * (1.f/256.f) - mu*mu + 1e-5f);
        int n = ng*8 + w;
        float* drow = g_tbuf + ((size_t)(b*NSLOT) + n)*DIM;
        #pragma unroll
        for (int i = l; i < 256; i += 32)
            drow[i] = (row[i] - mu)*rs*g[i] + bb[i];
    }
}

// ---------------- hidden = GELU(tbuf @ W1 + b1), full preload ----------------
#define GEMMH_SMEM ((16384 + 16384)*4)
__global__ __launch_bounds__(256) void gemm_h_kernel(const float* __restrict__ W1,
                                                     const float* __restrict__ b1)
{
    extern __shared__ float smf[];
    float* Af = smf; float* Bf = smf + 16384;
    int b = blockIdx.y; int nc = blockIdx.x * 64;
    int t = threadIdx.x;
    int kk0 = t >> 4, n4 = (t & 15)*4;
    #pragma unroll
    for (int k0 = 0; k0 < 256; k0 += 16)
        *(float4*)(Bf + (k0 + kk0)*64 + n4) = *(const float4*)(W1 + (size_t)(k0+kk0)*512 + nc + n4);
    {
        int r = t >> 2, part = t & 3;
        const float* row = g_tbuf + ((size_t)(b*NSLOT) + r)*DIM + part*64;
        #pragma unroll
        for (int i = 0; i < 64; i += 4) {
            float4 v = *(const float4*)(row + i);
            Af[(part*64+i+0)*64 + r] = v.x;
            Af[(part*64+i+1)*64 + r] = v.y;
            Af[(part*64+i+2)*64 + r] = v.z;
            Af[(part*64+i+3)*64 + r] = v.w;
        }
    }
    __syncthreads();
    int tm = t >> 4, tn = t & 15;
    u64 acc[4][2] = {};
    for (int k0 = 0; k0 < 256; k0 += 16) {
        #pragma unroll
        for (int kk = 0; kk < 16; kk++) {
            ulonglong2 a2 = *(ulonglong2*)(Af + (k0+kk)*64 + tm*4);
            float4 bb = *(float4*)(Bf + (k0+kk)*64 + tn*4);
            u64 q0 = PK1(bb.x), q1 = PK1(bb.y), q2 = PK1(bb.z), q3 = PK1(bb.w);
            FMA2(acc[0][0], a2.x, q0); FMA2(acc[0][1], a2.y, q0);
            FMA2(acc[1][0], a2.x, q1); FMA2(acc[1][1], a2.y, q1);
            FMA2(acc[2][0], a2.x, q2); FMA2(acc[2][1], a2.y, q2);
            FMA2(acc[3][0], a2.x, q3); FMA2(acc[3][1], a2.y, q3);
        }
    }
    float4 bv = *(const float4*)(b1 + nc + tn*4);
    #pragma unroll
    for (int p = 0; p < 2; p++) {
        float2 f0 = UPK(acc[0][p]), f1 = UPK(acc[1][p]), f2 = UPK(acc[2][p]), f3 = UPK(acc[3][p]);
        float4 r0 = {gelu_exact(f0.x+bv.x), gelu_exact(f1.x+bv.y), gelu_exact(f2.x+bv.z), gelu_exact(f3.x+bv.w)};
        float4 r1 = {gelu_exact(f0.y+bv.x), gelu_exact(f1.y+bv.y), gelu_exact(f2.y+bv.z), gelu_exact(f3.y+bv.w)};
        int mm = tm*4 + p*2;
        *(float4*)(g_hidden + ((size_t)(b*NSLOT) + mm  )*512 + nc + tn*4) = r0;
        *(float4*)(g_hidden + ((size_t)(b*NSLOT) + mm+1)*512 + nc + tn*4) = r1;
    }
}

// ---------------- templates += hidden @ W2 + b2, 2-phase preload ----------------
#define GEMMO_SMEM ((16384 + 16384)*4)
__global__ __launch_bounds__(256) void gemm_o_kernel(const float* __restrict__ W2,
                                                     const float* __restrict__ b2)
{
    extern __shared__ float smf[];
    float* Af = smf; float* Bf = smf + 16384;
    int b = blockIdx.y; int nc = blockIdx.x * 64;
    int t = threadIdx.x;
    int kk0 = t >> 4, n4 = (t & 15)*4;
    int tm = t >> 4, tn = t & 15;
    u64 acc[4][2] = {};
    for (int hc = 0; hc < 2; hc++) {
        #pragma unroll
        for (int k0 = 0; k0 < 256; k0 += 16)
            *(float4*)(Bf + (k0 + kk0)*64 + n4) =
                *(const float4*)(W2 + (size_t)(hc*256 + k0 + kk0)*256 + nc + n4);
        {
            int r = t >> 2, part = t & 3;
            const float* row = g_hidden + ((size_t)(b*NSLOT) + r)*512 + hc*256 + part*64;
            #pragma unroll
            for (int i = 0; i < 64; i += 4) {
                float4 v = *(const float4*)(row + i);
                Af[(part*64+i+0)*64 + r] = v.x;
                Af[(part*64+i+1)*64 + r] = v.y;
                Af[(part*64+i+2)*64 + r] = v.z;
                Af[(part*64+i+3)*64 + r] = v.w;
            }
        }
        __syncthreads();
        for (int k0 = 0; k0 < 256; k0 += 16) {
            #pragma unroll
            for (int kk = 0; kk < 16; kk++) {
                ulonglong2 a2 = *(ulonglong2*)(Af + (k0+kk)*64 + tm*4);
                float4 bb = *(float4*)(Bf + (k0+kk)*64 + tn*4);
                u64 q0 = PK1(bb.x), q1 = PK1(bb.y), q2 = PK1(bb.z), q3 = PK1(bb.w);
                FMA2(acc[0][0], a2.x, q0); FMA2(acc[0][1], a2.y, q0);
                FMA2(acc[1][0], a2.x, q1); FMA2(acc[1][1], a2.y, q1);
                FMA2(acc[2][0], a2.x, q2); FMA2(acc[2][1], a2.y, q2);
                FMA2(acc[3][0], a2.x, q3); FMA2(acc[3][1], a2.y, q3);
            }
        }
        __syncthreads();
    }
    float4 bv = *(const float4*)(b2 + nc + tn*4);
    #pragma unroll
    for (int p = 0; p < 2; p++) {
        float2 f0 = UPK(acc[0][p]), f1 = UPK(acc[1][p]), f2 = UPK(acc[2][p]), f3 = UPK(acc[3][p]);
        int mm = tm*4 + p*2;
        float* C0 = g_templates + ((size_t)(b*NSLOT) + mm)*DIM + nc + tn*4;
        float4 c0 = *(float4*)C0;
        c0.x += f0.x + bv.x; c0.y += f1.x + bv.y; c0.z += f2.x + bv.z; c0.w += f3.x + bv.w;
        *(float4*)C0 = c0;
        float* C1 = C0 + DIM;
        float4 c1 = *(float4*)C1;
        c1.x += f0.y + bv.x; c1.y += f1.y + bv.y; c1.z += f2.y + bv.z; c1.w += f3.y + bv.w;
        *(float4*)C1 = c1;
    }
}

// ---------------- outputs ----------------
__global__ __launch_bounds__(256) void out_templates_kernel(float* __restrict__ out) {
    __shared__ float smt[64*65];
    int b = blockIdx.x, t = threadIdx.x;
    for (int dc = 0; dc < 4; dc++) {
        #pragma unroll
        for (int i = 0; i < 16; i++) {
            int n = i*4 + (t >> 6), dd = t & 63;
            smt[n*65 + dd] = g_templates[((size_t)(b*NSLOT) + n)*DIM + dc*64 + dd];
        }
        __syncthreads();
        #pragma unroll
        for (int i = 0; i < 16; i++) {
            int dd = i*4 + (t >> 6), n = t & 63;
            out[((size_t)(b*DIM) + dc*64 + dd)*NSLOT + n] = smt[n*65 + dd];
        }
        __syncthreads();
    }
}

__global__ __launch_bounds__(256) void out_attn_kernel(float* __restrict__ out) {
    __shared__ float smt[128*65];
    __shared__ float inv_s[64];
    int lt = blockIdx.x, b = blockIdx.y, t = threadIdx.x;
    if (t < 64) inv_s[t] = 1.0f / g_colsum[b*NSLOT + t];
    #pragma unroll 4
    for (int i = 0; i < 32; i++) {
        int r = i*4 + (t >> 6);
        smt[r*65 + (t & 63)] = g_attn[((size_t)(b*4096) + lt*128 + r)*64 + (t & 63)];
    }
    __syncthreads();
    size_t ob = (size_t)BATCH*DIM*NSLOT + ((size_t)b*NSLOT)*LTOK + lt*128;
    for (int ng = 0; ng < 16; ng++) {
        int n = ng*4 + (t >> 6);
        float inv = inv_s[n];
        #pragma unroll
        for (int lc = 0; lc < 2; lc++) {
            int l = lc*64 + (t & 63);
            out[ob + (size_t)n*LTOK + l] = smt[l*65 + n] * inv;
        }
    }
}

// ---------------- launch ----------------
extern "C" void kernel_launch(void* const* d_in, const int* in_sizes, int n_in,
                              void* d_out, int out_size) {
    const float* x       = (const float*)d_in[0];
    const float* tinit   = (const float*)d_in[1];
    const float* conv_w  = (const float*)d_in[2];
    const float* conv_b  = (const float*)d_in[3];
    const float* Wq      = (const float*)d_in[4];
    const float* Wk      = (const float*)d_in[5];
    const float* Wv      = (const float*)d_in[6];
    const float* ln_in_g = (const float*)d_in[7];
    const float* ln_in_b = (const float*)d_in[8];
    const float* ln_t_g  = (const float*)d_in[9];
    const float* ln_t_b  = (const float*)d_in[10];
    const float* ln_m_g  = (const float*)d_in[11];
    const float* ln_m_b  = (const float*)d_in[12];
    const float* W1      = (const float*)d_in[13];
    const float* b1      = (const float*)d_in[14];
    const float* W2      = (const float*)d_in[15];
    const float* b2      = (const float*)d_in[16];
    float* out = (float*)d_out;

    cudaFuncSetAttribute(conv_mma_kernel, cudaFuncAttributeMaxDynamicSharedMemorySize, CMM_SMEM);
    cudaFuncSetAttribute(kv_mma_kernel, cudaFuncAttributeMaxDynamicSharedMemorySize, CMM_SMEM);
    cudaFuncSetAttribute(attn_gc_kernel, cudaFuncAttributeMaxDynamicSharedMemorySize, AGC_SMEM);
    cudaFuncSetAttribute(gemm_q_kernel, cudaFuncAttributeMaxDynamicSharedMemorySize, GEMMQ_SMEM);
    cudaFuncSetAttribute(gemm_h_kernel, cudaFuncAttributeMaxDynamicSharedMemorySize, GEMMH_SMEM);
    cudaFuncSetAttribute(gemm_o_kernel, cudaFuncAttributeMaxDynamicSharedMemorySize, GEMMO_SMEM);

    prep_kernel<<<3976, 256>>>(tinit, conv_w, Wk, Wv);
    xsplit_kernel<<<8*33*33, 256>>>(x);
    conv_mma_kernel<<<256, 512, CMM_SMEM>>>(conv_b, ln_in_g, ln_in_b);
    kv_mma_kernel<<<512, 512, CMM_SMEM>>>();

    for (int it = 0; it < 6; it++) {
        gemm_q_kernel<<<dim3(4, 8), 256, GEMMQ_SMEM>>>(Wq, ln_t_g, ln_t_b);
        attn_gc_kernel<<<dim3(32, 8), 256, AGC_SMEM>>>(it == 5 ? 1 : 0);
        finalize_kernel<<<dim3(8, 8), 256>>>(ln_m_g, ln_m_b);
        gemm_h_kernel<<<dim3(8, 8), 256, GEMMH_SMEM>>>(W1, b1);
        gemm_o_kernel<<<dim3(4, 8), 256, GEMMO_SMEM>>>(W2, b2);
    }

    out_templates_kernel<<<8, 256>>>(out);
    out_attn_kernel<<<dim3(32, 8), 256>>>(out);
}